// round 10
// baseline (speedup 1.0000x reference)
#include <cuda_runtime.h>
#include <math.h>

#define BATCH 2
#define HWd   192
#define HW2   (HWd*HWd)      // 36864
#define HGd   48
#define Ntok  (HGd*HGd)      // 2304
#define D2    256
#define VDdim 2048
#define NFtot 3
#define LISTCAP 128
#define MAXU   224

typedef unsigned long long u64;

// ---------------- scratch (device globals; no allocs allowed) ----------------
__device__ float g_buf1[(size_t)BATCH*384*HW2];
__device__ float g_buf2[(size_t)BATCH*384*HW2];
__device__ float g_buf3[(size_t)BATCH*512*HW2];
__device__ float g_buf4[(size_t)BATCH*512*Ntok];
__device__ float g_qtok[(size_t)BATCH*Ntok*D2];
__device__ float g_attn[(size_t)BATCH*NFtot*Ntok*Ntok];
__device__ float g_otok[(size_t)BATCH*NFtot*Ntok*VDdim];

// ---------------- packed fp32x2 primitives (Blackwell FFMA2) -----------------
__device__ __forceinline__ u64 dup2(float x) {
    u64 r;
    asm("mov.b64 %0, {%1, %1};" : "=l"(r) : "r"(__float_as_uint(x)));
    return r;
}
__device__ __forceinline__ void fma2(u64 &d, u64 a, u64 b) {
    asm("fma.rn.f32x2 %0, %1, %2, %3;" : "=l"(d) : "l"(a), "l"(b), "l"(d));
}
__device__ __forceinline__ float2 unpk(u64 v) {
    float lo, hi;
    asm("mov.b64 {%0, %1}, %2;" : "=f"(lo), "=f"(hi) : "l"(v));
    return make_float2(lo, hi);
}

// one k-step of the 8x8 fragment: 32 fma.f32x2
__device__ __forceinline__ void fma_step(
    const float* __restrict__ As_k, const float* __restrict__ Bs_k,
    int tx, int ty, u64 acc[8][4])
{
    float4 av0 = *(const float4*)(As_k + ty*4);
    float4 av1 = *(const float4*)(As_k + 64 + ty*4);
    ulonglong2 bv0 = *(const ulonglong2*)(Bs_k + tx*4);
    ulonglong2 bv1 = *(const ulonglong2*)(Bs_k + 64 + tx*4);
    u64 aa[8] = {dup2(av0.x), dup2(av0.y), dup2(av0.z), dup2(av0.w),
                 dup2(av1.x), dup2(av1.y), dup2(av1.z), dup2(av1.w)};
    u64 bb[4] = {bv0.x, bv0.y, bv1.x, bv1.y};
    #pragma unroll
    for (int i = 0; i < 8; i++) {
        fma2(acc[i][0], aa[i], bb[0]);
        fma2(acc[i][1], aa[i], bb[1]);
        fma2(acc[i][2], aa[i], bb[2]);
        fma2(acc[i][3], aa[i], bb[3]);
    }
}

// =============================================================================
// double-buffered conv GEMM body
// =============================================================================
__device__ __forceinline__ void gemm_db_conv2(
    const float* __restrict__ A, const float* __restrict__ Bbase, int K,
    float (* __restrict__ As)[16][132], float (* __restrict__ Bs)[16][128],
    int t, u64 acc[8][4])
{
    int arow = t >> 1, akq = (t & 1) * 8;
    int bk = t >> 4, bn = (t & 15) * 4;
    int tx = t & 15, ty = t >> 4;
    const float* Ap = A + (long)arow * K + akq;

    float4 a0 = *(const float4*)(Ap);
    float4 a1 = *(const float4*)(Ap + 4);
    const float* bs0 = Bbase + (long)bk * HW2;
    float4 b0 = *(const float4*)(bs0 + bn);
    float4 b1 = *(const float4*)(bs0 + bn + 64);
    As[0][akq+0][arow]=a0.x; As[0][akq+1][arow]=a0.y; As[0][akq+2][arow]=a0.z; As[0][akq+3][arow]=a0.w;
    As[0][akq+4][arow]=a1.x; As[0][akq+5][arow]=a1.y; As[0][akq+6][arow]=a1.z; As[0][akq+7][arow]=a1.w;
    *(float4*)&Bs[0][bk][bn]    = b0;
    *(float4*)&Bs[0][bk][bn+64] = b1;
    __syncthreads();
    int buf = 0;
    for (int k0 = 16; k0 <= K; k0 += 16) {
        if (k0 < K) {
            a0 = *(const float4*)(Ap + k0);
            a1 = *(const float4*)(Ap + k0 + 4);
            const float* bs2 = Bbase + (long)(k0 + bk) * HW2;
            b0 = *(const float4*)(bs2 + bn);
            b1 = *(const float4*)(bs2 + bn + 64);
        }
        #pragma unroll
        for (int kk = 0; kk < 16; kk++)
            fma_step(&As[buf][kk][0], &Bs[buf][kk][0], tx, ty, acc);
        if (k0 < K) {
            int nb = buf ^ 1;
            As[nb][akq+0][arow]=a0.x; As[nb][akq+1][arow]=a0.y; As[nb][akq+2][arow]=a0.z; As[nb][akq+3][arow]=a0.w;
            As[nb][akq+4][arow]=a1.x; As[nb][akq+5][arow]=a1.y; As[nb][akq+6][arow]=a1.z; As[nb][akq+7][arow]=a1.w;
            *(float4*)&Bs[nb][bk][bn]    = b0;
            *(float4*)&Bs[nb][bk][bn+64] = b1;
            __syncthreads();
            buf = nb;
        }
    }
}

// =============================================================================
// double-buffered TT GEMM body
// =============================================================================
__device__ __forceinline__ void gemm_db_tt2(
    const float* __restrict__ Abase, const float* __restrict__ Bbase, int K,
    float (* __restrict__ As)[16][132], float (* __restrict__ Bs)[16][132],
    int t, u64 acc[8][4])
{
    int row = t >> 1, kq = (t & 1) * 8;
    int tx = t & 15, ty = t >> 4;
    const float* Ap = Abase + (long)row * K + kq;
    const float* Bp = Bbase + (long)row * K + kq;

    float4 a0 = *(const float4*)(Ap);
    float4 a1 = *(const float4*)(Ap + 4);
    float4 b0 = *(const float4*)(Bp);
    float4 b1 = *(const float4*)(Bp + 4);
    As[0][kq+0][row]=a0.x; As[0][kq+1][row]=a0.y; As[0][kq+2][row]=a0.z; As[0][kq+3][row]=a0.w;
    As[0][kq+4][row]=a1.x; As[0][kq+5][row]=a1.y; As[0][kq+6][row]=a1.z; As[0][kq+7][row]=a1.w;
    Bs[0][kq+0][row]=b0.x; Bs[0][kq+1][row]=b0.y; Bs[0][kq+2][row]=b0.z; Bs[0][kq+3][row]=b0.w;
    Bs[0][kq+4][row]=b1.x; Bs[0][kq+5][row]=b1.y; Bs[0][kq+6][row]=b1.z; Bs[0][kq+7][row]=b1.w;
    __syncthreads();
    int buf = 0;
    for (int k0 = 16; k0 <= K; k0 += 16) {
        if (k0 < K) {
            a0 = *(const float4*)(Ap + k0);
            a1 = *(const float4*)(Ap + k0 + 4);
            b0 = *(const float4*)(Bp + k0);
            b1 = *(const float4*)(Bp + k0 + 4);
        }
        #pragma unroll
        for (int kk = 0; kk < 16; kk++)
            fma_step(&As[buf][kk][0], &Bs[buf][kk][0], tx, ty, acc);
        if (k0 < K) {
            int nb = buf ^ 1;
            As[nb][kq+0][row]=a0.x; As[nb][kq+1][row]=a0.y; As[nb][kq+2][row]=a0.z; As[nb][kq+3][row]=a0.w;
            As[nb][kq+4][row]=a1.x; As[nb][kq+5][row]=a1.y; As[nb][kq+6][row]=a1.z; As[nb][kq+7][row]=a1.w;
            Bs[nb][kq+0][row]=b0.x; Bs[nb][kq+1][row]=b0.y; Bs[nb][kq+2][row]=b0.z; Bs[nb][kq+3][row]=b0.w;
            Bs[nb][kq+4][row]=b1.x; Bs[nb][kq+5][row]=b1.y; Bs[nb][kq+6][row]=b1.z; Bs[nb][kq+7][row]=b1.w;
            __syncthreads();
            buf = nb;
        }
    }
}

__device__ __forceinline__ void gemm128_store2(
    float* __restrict__ Crow, const float* __restrict__ bias,
    int t, u64 acc[8][4], long ldc)
{
    int tx = t & 15, ty = t >> 4;
    #pragma unroll
    for (int i = 0; i < 8; i++) {
        int m = (i < 4) ? (ty*4 + i) : (64 + ty*4 + i - 4);
        float bv = bias ? bias[m] : 0.f;
        float2 p0 = unpk(acc[i][0]), p1 = unpk(acc[i][1]);
        float2 p2 = unpk(acc[i][2]), p3 = unpk(acc[i][3]);
        float4 o0 = {p0.x+bv, p0.y+bv, p1.x+bv, p1.y+bv};
        float4 o1 = {p2.x+bv, p2.y+bv, p3.x+bv, p3.y+bv};
        *(float4*)&Crow[(long)m*ldc + tx*4]      = o0;
        *(float4*)&Crow[(long)m*ldc + 64 + tx*4] = o1;
    }
}

// stage A
__global__ void __launch_bounds__(256,2) gemm_stageA(
    const float* __restrict__ x,
    const float* __restrict__ qk_w, const float* __restrict__ qk_b,
    const float* __restrict__ v_w,  const float* __restrict__ v_b)
{
    int n0 = blockIdx.x * 128, y = blockIdx.y, b = blockIdx.z;
    int t = threadIdx.x;
    __shared__ float As[2][16][132];
    __shared__ float Bs[2][16][128];
    u64 acc[8][4] = {};
    const float* A   = (y < 2) ? (qk_w + (long)y*128*128) : v_w;
    const float* bia = (y < 2) ? (qk_b + y*128)           : v_b;
    int cch          = (y < 2) ? (y*128)                  : 256;
    gemm_db_conv2(A, x + (long)b*128*HW2 + n0, 128, As, Bs, t, acc);
    gemm128_store2(g_buf1 + ((long)b*384 + cch) * HW2 + n0, bia, t, acc, HW2);
}

// stage C
__global__ void __launch_bounds__(256,2) gemm_stageC(
    const float* __restrict__ q2_w, const float* __restrict__ q2_b,
    const float* __restrict__ k2_w, const float* __restrict__ k2_b)
{
    int n0 = blockIdx.x * 128, y = blockIdx.y, b = blockIdx.z;
    int t = threadIdx.x;
    __shared__ float As[2][16][132];
    __shared__ float Bs[2][16][128];
    u64 acc[8][4] = {};
    const float* A   = (y < 2) ? (q2_w + (long)y*128*128) : (k2_w + (long)(y-2)*128*128);
    const float* bia = (y < 2) ? (q2_b + y*128)           : (k2_b + (y-2)*128);
    const float* Bbase = g_buf2 + ((long)b*384 + ((y < 2) ? 0 : 128)) * HW2 + n0;
    gemm_db_conv2(A, Bbase, 128, As, Bs, t, acc);
    gemm128_store2(g_buf3 + ((long)b*512 + y*128) * HW2 + n0, bia, t, acc, HW2);
}

// attention GEMM
__global__ void __launch_bounds__(256,2) attn_gemm2(
    const float* __restrict__ kc, const float* __restrict__ knew)
{
    int z = blockIdx.z; int b = z / NFtot, f = z % NFtot;
    const float* Qp = g_qtok + (long)b * Ntok * D2;
    const float* Kp = (f < 2) ? (kc   + ((long)(b*2 + f)) * Ntok * D2)
                              : (knew + ((long)(b*2 + 1)) * Ntok * D2);
    int m0 = blockIdx.y * 128, n0 = blockIdx.x * 128;
    int t = threadIdx.x;
    int tx = t & 15, ty = t >> 4;
    __shared__ float As[2][16][132];
    __shared__ float Bs[2][16][132];
    u64 acc[8][4] = {};
    gemm_db_tt2(Qp + (long)m0 * D2, Kp + (long)n0 * D2, D2, As, Bs, t, acc);
    float* Cp = g_attn + (long)z * Ntok * Ntok;
    #pragma unroll
    for (int i = 0; i < 8; i++) {
        int m = (i < 4) ? (ty*4 + i) : (64 + ty*4 + i - 4);
        float2 p0 = unpk(acc[i][0]), p1 = unpk(acc[i][1]);
        float2 p2 = unpk(acc[i][2]), p3 = unpk(acc[i][3]);
        float4 o0 = {p0.x, p0.y, p1.x, p1.y};
        float4 o1 = {p2.x, p2.y, p3.x, p3.y};
        *(float4*)&Cp[(long)(m0+m)*Ntok + n0 + tx*4]      = o0;
        *(float4*)&Cp[(long)(m0+m)*Ntok + n0 + 64 + tx*4] = o1;
    }
}

// proj 1x1 GEMM with fused window de-permute gather
__global__ void __launch_bounds__(256,2) proj_gemm2(
    const float* __restrict__ W, const float* __restrict__ bias,
    float* __restrict__ Out)
{
    int z  = blockIdx.z;
    int n0 = blockIdx.x * 128;
    int t = threadIdx.x;
    int tx = t & 15, ty = t >> 4;
    __shared__ float As[2][16][132];
    __shared__ float Bs[2][16][132];
    u64 acc[8][4] = {};
    int row = t >> 1;
    int p = n0 + row;
    int h = p / HWd, w = p % HWd;
    int token = (h % HGd) * HGd + (w % HGd);
    int vbase = ((h / HGd) * 4 + (w / HGd)) * 128;
    {
        int kq = (t & 1) * 8;
        const float* Ap = W + (long)row * 128 + kq;
        const float* Bp = g_otok + ((long)z * Ntok + token) * VDdim + vbase + kq;
        float4 a0 = *(const float4*)(Ap);
        float4 a1 = *(const float4*)(Ap + 4);
        float4 b0 = *(const float4*)(Bp);
        float4 b1 = *(const float4*)(Bp + 4);
        As[0][kq+0][row]=a0.x; As[0][kq+1][row]=a0.y; As[0][kq+2][row]=a0.z; As[0][kq+3][row]=a0.w;
        As[0][kq+4][row]=a1.x; As[0][kq+5][row]=a1.y; As[0][kq+6][row]=a1.z; As[0][kq+7][row]=a1.w;
        Bs[0][kq+0][row]=b0.x; Bs[0][kq+1][row]=b0.y; Bs[0][kq+2][row]=b0.z; Bs[0][kq+3][row]=b0.w;
        Bs[0][kq+4][row]=b1.x; Bs[0][kq+5][row]=b1.y; Bs[0][kq+6][row]=b1.z; Bs[0][kq+7][row]=b1.w;
        __syncthreads();
        int buf = 0;
        for (int k0 = 16; k0 <= 128; k0 += 16) {
            if (k0 < 128) {
                a0 = *(const float4*)(Ap + k0);
                a1 = *(const float4*)(Ap + k0 + 4);
                b0 = *(const float4*)(Bp + k0);
                b1 = *(const float4*)(Bp + k0 + 4);
            }
            #pragma unroll
            for (int kk = 0; kk < 16; kk++)
                fma_step(&As[buf][kk][0], &Bs[buf][kk][0], tx, ty, acc);
            if (k0 < 128) {
                int nb = buf ^ 1;
                As[nb][kq+0][row]=a0.x; As[nb][kq+1][row]=a0.y; As[nb][kq+2][row]=a0.z; As[nb][kq+3][row]=a0.w;
                As[nb][kq+4][row]=a1.x; As[nb][kq+5][row]=a1.y; As[nb][kq+6][row]=a1.z; As[nb][kq+7][row]=a1.w;
                Bs[nb][kq+0][row]=b0.x; Bs[nb][kq+1][row]=b0.y; Bs[nb][kq+2][row]=b0.z; Bs[nb][kq+3][row]=b0.w;
                Bs[nb][kq+4][row]=b1.x; Bs[nb][kq+5][row]=b1.y; Bs[nb][kq+6][row]=b1.z; Bs[nb][kq+7][row]=b1.w;
                __syncthreads();
                buf = nb;
            }
        }
    }
    #pragma unroll
    for (int i = 0; i < 8; i++) {
        int m = (i < 4) ? (ty*4 + i) : (64 + ty*4 + i - 4);
        float bv = bias[m];
        float2 p0 = unpk(acc[i][0]), p1 = unpk(acc[i][1]);
        float2 p2 = unpk(acc[i][2]), p3 = unpk(acc[i][3]);
        float4 o0 = {p0.x+bv, p0.y+bv, p1.x+bv, p1.y+bv};
        float4 o1 = {p2.x+bv, p2.y+bv, p3.x+bv, p3.y+bv};
        *(float4*)&Out[((long)z*128 + m)*HW2 + n0 + tx*4]      = o0;
        *(float4*)&Out[((long)z*128 + m)*HW2 + n0 + 64 + tx*4] = o1;
    }
}

// ---------------- depthwise 3x3 pad1 ------------------------------------------
__global__ void dw3x3(const float* __restrict__ qk_dw_w, const float* __restrict__ qk_dw_b,
                      const float* __restrict__ v_dw_w,  const float* __restrict__ v_dw_b)
{
    int idx = blockIdx.x * 256 + threadIdx.x;
    if (idx >= BATCH*384*HW2) return;
    int p  = idx % HW2;
    int ch = (idx / HW2) % 384;
    int b  = idx / (384*HW2);
    int h = p / HWd, w = p % HWd;
    const float* wgt; float bv;
    if (ch < 256) { wgt = qk_dw_w + ch*9;        bv = qk_dw_b[ch]; }
    else          { wgt = v_dw_w  + (ch-256)*9;  bv = v_dw_b[ch-256]; }
    const float* in = g_buf1 + ((long)(b*384 + ch)) * HW2;
    float s = bv;
    #pragma unroll
    for (int ky = 0; ky < 3; ky++) {
        int y = h + ky - 1;
        if ((unsigned)y >= (unsigned)HWd) continue;
        #pragma unroll
        for (int kx = 0; kx < 3; kx++) {
            int x = w + kx - 1;
            if ((unsigned)x >= (unsigned)HWd) continue;
            s += wgt[ky*3+kx] * in[y*HWd + x];
        }
    }
    g_buf2[idx] = s;
}

// ---------------- depthwise 4x4 stride4 pad1 ----------------------------------
__global__ void dw4x4(const float* __restrict__ q2_dw_w, const float* __restrict__ q2_dw_b,
                      const float* __restrict__ k2_dw_w, const float* __restrict__ k2_dw_b)
{
    int idx = blockIdx.x * 256 + threadIdx.x;
    if (idx >= BATCH*512*Ntok) return;
    int t  = idx % Ntok;
    int ch = (idx / Ntok) % 512;
    int b  = idx / (512*Ntok);
    int oy = t / HGd, ox = t % HGd;
    const float* wgt; float bv;
    if (ch < 256) { wgt = q2_dw_w + ch*16;       bv = q2_dw_b[ch]; }
    else          { wgt = k2_dw_w + (ch-256)*16; bv = k2_dw_b[ch-256]; }
    const float* in = g_buf3 + ((long)(b*512 + ch)) * HW2;
    float s = bv;
    #pragma unroll
    for (int ky = 0; ky < 4; ky++) {
        int y = oy*4 - 1 + ky;
        if ((unsigned)y >= (unsigned)HWd) continue;
        #pragma unroll
        for (int kx = 0; kx < 4; kx++) {
            int x = ox*4 - 1 + kx;
            if ((unsigned)x >= (unsigned)HWd) continue;
            s += wgt[ky*4+kx] * in[y*HWd + x];
        }
    }
    g_buf4[idx] = s;
}

// ---------------- l2 normalize + token-major q/k ------------------------------
__global__ void __launch_bounds__(256) norm_qk(float* __restrict__ kout,
                                               const float* __restrict__ temp)
{
    int token = blockIdx.x, b = blockIdx.y, d = threadIdx.x;
    float qv = g_buf4[((long)b*512 + d)       * Ntok + token];
    float kv = g_buf4[((long)b*512 + 256 + d) * Ntok + token];
    __shared__ float red[256];
    __shared__ float qinv_s, kinv_s;
    red[d] = qv*qv; __syncthreads();
    for (int s = 128; s > 0; s >>= 1) { if (d < s) red[d] += red[d+s]; __syncthreads(); }
    if (d == 0) qinv_s = (*temp) / fmaxf(sqrtf(red[0]), 1e-12f);
    __syncthreads();
    red[d] = kv*kv; __syncthreads();
    for (int s = 128; s > 0; s >>= 1) { if (d < s) red[d] += red[d+s]; __syncthreads(); }
    if (d == 0) kinv_s = 1.f / fmaxf(sqrtf(red[0]), 1e-12f);
    __syncthreads();
    g_qtok[((long)b*Ntok + token) * D2 + d] = qv * qinv_s;
    kout  [((long)(b*2 + 1)*Ntok + token) * D2 + d] = kv * kinv_s;
}

// ---------------- build v_new -------------------------------------------------
__global__ void build_vnew(float* __restrict__ vout)
{
    int idx = blockIdx.x * 256 + threadIdx.x;
    if (idx >= BATCH*Ntok*VDdim) return;
    int vd    = idx % VDdim;
    int token = (idx / VDdim) % Ntok;
    int b     = idx / (Ntok*VDdim);
    int c  = vd & 127;
    int p2 = (vd >> 7) & 3;
    int p1 = vd >> 9;
    int hi = token / HGd, wi = token % HGd;
    float val = g_buf2[((long)(b*384 + 256 + c)) * HW2 + (p1*HGd + hi) * HWd + (p2*HGd + wi)];
    vout[((long)(b*2 + 1)*Ntok + token) * VDdim + vd] = val;
}

// =============================================================================
// sparse_attn_av16: one block = 4x4 query tile (16 queries), 512 threads,
// 4 dims/thread. Per-query select identical math; union gather list with
// rank-indexed weight table Wt[e][16]; AV loop loads each union row chunk
// once (float4 -> 2x f32x2) and fma2's into 16 accumulator pairs.
// grid: (144 tiles, 6 zf)
// =============================================================================
__global__ void __launch_bounds__(512) sparse_attn_av16(
    const float* __restrict__ v_cached, const float* __restrict__ vout)
{
    int tile = blockIdx.x;               // 0..143
    int z    = blockIdx.y;               // b*3+f
    int b = z / NFtot, f = z % NFtot;
    int qy0 = (tile / 12) * 4, qx0 = (tile % 12) * 4;
    int tid = threadIdx.x;

    extern __shared__ float sm[];
    float* rowbuf = sm;                          // 2304
    float* cand   = rowbuf + Ntok;               // 512*5 = 2560
    int*   sidx   = (int*)(cand + 2560);         // 16*128
    float* sval   = (float*)(sidx + 16*LISTCAP); // 16*128
    float* Wt     = sval + 16*LISTCAP;           // MAXU*16
    int*   uidx   = (int*)(Wt + MAXU*16);        // MAXU

    __shared__ int   scnt[16];
    __shared__ unsigned umask[72];
    __shared__ int   ubase[73];
    __shared__ int   nnz;
    __shared__ float bcast;

    if (tid < 72) umask[tid] = 0;

    for (int q = 0; q < 16; q++) {
        int ny = qy0 + (q >> 2), nx = qx0 + (q & 3);
        int n = ny * HGd + nx;
        const float* arow = g_attn + ((long)z * Ntok + n) * Ntok;
        __syncthreads();
        for (int m = tid*4; m < Ntok; m += 2048)
            *(float4*)&rowbuf[m] = *(const float4*)&arow[m];
        if (tid == 0) nnz = 0;
        __syncthreads();

        // per-thread top-5
        float t5[5] = {-INFINITY,-INFINITY,-INFINITY,-INFINITY,-INFINITY};
        for (int m = tid; m < Ntok; m += 512) {
            float v = rowbuf[m];
            if (v > t5[4]) {
                t5[4] = v;
                #pragma unroll
                for (int i = 4; i > 0; i--)
                    if (t5[i] > t5[i-1]) { float tmp = t5[i-1]; t5[i-1] = t5[i]; t5[i] = tmp; }
            }
        }
        #pragma unroll
        for (int i = 0; i < 5; i++) cand[tid*5 + i] = t5[i];
        __syncthreads();

        // warp 0 merges 2560 candidates -> kth largest (strict-< exclusion)
        if (tid < 32) {
            float l5[5] = {-INFINITY,-INFINITY,-INFINITY,-INFINITY,-INFINITY};
            const float* cp = cand + tid*80;
            #pragma unroll
            for (int i = 0; i < 80; i++) {
                float v = cp[i];
                if (v > l5[4]) {
                    l5[4] = v;
                    #pragma unroll
                    for (int j = 4; j > 0; j--)
                        if (l5[j] > l5[j-1]) { float tmp = l5[j-1]; l5[j-1] = l5[j]; l5[j] = tmp; }
                }
            }
            float thr = INFINITY;
            #pragma unroll
            for (int r = 0; r < 5; r++) {
                float lm = -INFINITY;
                #pragma unroll
                for (int i = 0; i < 5; i++) {
                    float v = l5[i];
                    if (v < thr && v > lm) lm = v;
                }
                #pragma unroll
                for (int o = 16; o > 0; o >>= 1)
                    lm = fmaxf(lm, __shfl_xor_sync(0xffffffffu, lm, o));
                thr = lm;
            }
            if (tid == 0) bcast = thr;
        }
        __syncthreads();
        float kth = bcast;

        // collect nonzero entries; OR into union bitmap
        for (int m = tid; m < Ntok; m += 512) {
            float a = rowbuf[m];
            float coef = (a >= kth) ? 1.f : 0.f;
            int my = m / HGd, mx = m % HGd;
            if (abs(ny - my) + abs(nx - mx) <= 4) coef += 1.f;
            float v = a * coef;
            if (v != 0.f) {
                int pos = atomicAdd(&nnz, 1);
                if (pos < LISTCAP) { sidx[q*LISTCAP + pos] = m; sval[q*LISTCAP + pos] = v; }
                atomicOr(&umask[m >> 5], 1u << (m & 31));
            }
        }
        __syncthreads();
        int cnt = min(nnz, LISTCAP);

        // softmax: warp-0 max, block exp, warp-0 sum, block divide
        if (tid < 32) {
            float mx = -INFINITY;
            for (int e = tid; e < cnt; e += 32) mx = fmaxf(mx, sval[q*LISTCAP + e]);
            #pragma unroll
            for (int o = 16; o > 0; o >>= 1)
                mx = fmaxf(mx, __shfl_xor_sync(0xffffffffu, mx, o));
            if (tid == 0) bcast = mx;
        }
        __syncthreads();
        float mxv = bcast;
        if (tid < cnt) sval[q*LISTCAP + tid] = expf(sval[q*LISTCAP + tid] - mxv);
        __syncthreads();
        if (tid < 32) {
            float s = 0.f;
            for (int e = tid; e < cnt; e += 32) s += sval[q*LISTCAP + e];
            #pragma unroll
            for (int o = 16; o > 0; o >>= 1)
                s += __shfl_xor_sync(0xffffffffu, s, o);
            if (tid == 0) { bcast = s; scnt[q] = cnt; }
        }
        __syncthreads();
        if (tid < cnt) sval[q*LISTCAP + tid] = sval[q*LISTCAP + tid] / bcast;
    }
    __syncthreads();

    // union prefix ranks
    if (tid == 0) {
        int s = 0;
        for (int w = 0; w < 72; w++) { ubase[w] = s; s += __popc(umask[w]); }
        ubase[72] = s;
    }
    __syncthreads();
    int U = min(ubase[72], MAXU);

    // zero weight table, build union index list
    for (int i = tid; i < MAXU*16; i += 512) Wt[i] = 0.f;
    __syncthreads();
    if (tid < 72) {
        unsigned bits = umask[tid];
        int pos = ubase[tid];
        while (bits) {
            int bit = __ffs(bits) - 1; bits &= bits - 1;
            if (pos < MAXU) uidx[pos] = tid*32 + bit;
            pos++;
        }
    }
    __syncthreads();
    // scatter per-query weights by union rank: Wt[rank][q]
    for (int i = tid; i < 16*LISTCAP; i += 512) {
        int q = i >> 7, e = i & (LISTCAP-1);
        if (e < scnt[q]) {
            int m = sidx[q*LISTCAP + e];
            int w32 = m >> 5, bit = m & 31;
            int rank = ubase[w32] + __popc(umask[w32] & ((1u << bit) - 1u));
            if (rank < MAXU) Wt[rank*16 + q] = sval[q*LISTCAP + e];
        }
    }
    __syncthreads();

    // AV over union list: one float4 load per row, 16 fma2-pair accumulators
    const float* vbase = (f < 2) ? (v_cached + ((long)(b*2 + f)) * Ntok * VDdim)
                                 : (vout     + ((long)(b*2 + 1)) * Ntok * VDdim);
    int d0 = tid * 4;
    u64 acc[16][2] = {};
    for (int e = 0; e < U; e++) {
        int m = uidx[e];
        ulonglong2 vv = *(const ulonglong2*)(vbase + (long)m * VDdim + d0);
        float4 wA = *(const float4*)&Wt[e*16 + 0];
        float4 wB = *(const float4*)&Wt[e*16 + 4];
        float4 wC = *(const float4*)&Wt[e*16 + 8];
        float4 wD = *(const float4*)&Wt[e*16 + 12];
        float ws[16] = {wA.x,wA.y,wA.z,wA.w, wB.x,wB.y,wB.z,wB.w,
                        wC.x,wC.y,wC.z,wC.w, wD.x,wD.y,wD.z,wD.w};
        #pragma unroll
        for (int q = 0; q < 16; q++) {
            u64 wq = dup2(ws[q]);
            fma2(acc[q][0], wq, vv.x);
            fma2(acc[q][1], wq, vv.y);
        }
    }
    #pragma unroll
    for (int q = 0; q < 16; q++) {
        int ny = qy0 + (q >> 2), nx = qx0 + (q & 3);
        float2 p0 = unpk(acc[q][0]), p1 = unpk(acc[q][1]);
        float* orow = g_otok + ((long)z * Ntok + ny*HGd + nx) * VDdim + d0;
        *(float4*)orow = make_float4(p0.x, p0.y, p1.x, p1.y);
    }
}

// ---------------------------------- launch -----------------------------------
extern "C" void kernel_launch(void* const* d_in, const int* in_sizes, int n_in,
                              void* d_out, int out_size)
{
    (void)in_sizes; (void)n_in; (void)out_size;
    const float* x         = (const float*)d_in[0];
    const float* k_cached  = (const float*)d_in[1];
    const float* v_cached  = (const float*)d_in[2];
    const float* temperature = (const float*)d_in[3];
    const float* qk_w  = (const float*)d_in[4],  *qk_b  = (const float*)d_in[5];
    const float* qk_dw_w = (const float*)d_in[6], *qk_dw_b = (const float*)d_in[7];
    const float* v_w   = (const float*)d_in[8],  *v_b   = (const float*)d_in[9];
    const float* v_dw_w = (const float*)d_in[10], *v_dw_b = (const float*)d_in[11];
    const float* k2_w  = (const float*)d_in[12], *k2_b  = (const float*)d_in[13];
    const float* k2_dw_w = (const float*)d_in[14], *k2_dw_b = (const float*)d_in[15];
    const float* q2_w  = (const float*)d_in[16], *q2_b  = (const float*)d_in[17];
    const float* q2_dw_w = (const float*)d_in[18], *q2_dw_b = (const float*)d_in[19];
    const float* proj_w = (const float*)d_in[20], *proj_b = (const float*)d_in[21];

    float* out = (float*)d_out;
    const long OUT_K = (long)BATCH * NFtot * 128 * HW2;
    const long OUT_V = OUT_K + (long)BATCH * 2 * Ntok * D2;
    float* kout = out + OUT_K;
    float* vout = out + OUT_V;

    dim3 blk(256);

    // dynamic smem for sparse_attn_av16
    const int AV_SMEM = (Ntok + 2560 + 16*LISTCAP*2 + MAXU*16 + MAXU) * 4;
    static int smem_set = 0;
    if (!smem_set) {
        cudaFuncSetAttribute(sparse_attn_av16,
                             cudaFuncAttributeMaxDynamicSharedMemorySize, AV_SMEM);
        smem_set = 1;
    }

    gemm_stageA<<<dim3(288,3,BATCH), blk>>>(x, qk_w, qk_b, v_w, v_b);
    dw3x3<<<(BATCH*384*HW2 + 255)/256, blk>>>(qk_dw_w, qk_dw_b, v_dw_w, v_dw_b);
    gemm_stageC<<<dim3(288,4,BATCH), blk>>>(q2_w, q2_b, k2_w, k2_b);
    dw4x4<<<(BATCH*512*Ntok + 255)/256, blk>>>(q2_dw_w, q2_dw_b, k2_dw_w, k2_dw_b);
    norm_qk<<<dim3(Ntok, BATCH), blk>>>(kout, temperature);
    build_vnew<<<(BATCH*Ntok*VDdim + 255)/256, blk>>>(vout);
    for (int b = 0; b < BATCH; b++) {
        cudaMemcpyAsync(kout + (long)(b*2)*Ntok*D2,
                        k_cached + (long)(b*2+1)*Ntok*D2,
                        (size_t)Ntok*D2*sizeof(float), cudaMemcpyDeviceToDevice, 0);
        cudaMemcpyAsync(vout + (long)(b*2)*Ntok*VDdim,
                        v_cached + (long)(b*2+1)*Ntok*VDdim,
                        (size_t)Ntok*VDdim*sizeof(float), cudaMemcpyDeviceToDevice, 0);
    }
    attn_gemm2<<<dim3(18,18,BATCH*NFtot), blk>>>(k_cached, kout);
    sparse_attn_av16<<<dim3(144, BATCH*NFtot), 512, AV_SMEM>>>(v_cached, vout);
    proj_gemm2<<<dim3(288,1,BATCH*NFtot), blk>>>(proj_w, proj_b, out);
}

// round 11
// speedup vs baseline: 1.3848x; 1.3848x over previous
#include <cuda_runtime.h>
#include <math.h>

#define BATCH 2
#define HWd   192
#define HW2   (HWd*HWd)      // 36864
#define HGd   48
#define Ntok  (HGd*HGd)      // 2304
#define D2    256
#define VDdim 2048
#define NFtot 3
#define LISTCAP 128
#define MAXU   256

typedef unsigned long long u64;

// ---------------- scratch (device globals; no allocs allowed) ----------------
__device__ float g_buf1[(size_t)BATCH*384*HW2];
__device__ float g_buf2[(size_t)BATCH*384*HW2];
__device__ float g_buf3[(size_t)BATCH*512*HW2];
__device__ float g_buf4[(size_t)BATCH*512*Ntok];
__device__ float g_qtok[(size_t)BATCH*Ntok*D2];
__device__ float g_attn[(size_t)BATCH*NFtot*Ntok*Ntok];
__device__ float g_otok[(size_t)BATCH*NFtot*Ntok*VDdim];

// ---------------- packed fp32x2 primitives (Blackwell FFMA2) -----------------
__device__ __forceinline__ u64 dup2(float x) {
    u64 r;
    asm("mov.b64 %0, {%1, %1};" : "=l"(r) : "r"(__float_as_uint(x)));
    return r;
}
__device__ __forceinline__ void fma2(u64 &d, u64 a, u64 b) {
    asm("fma.rn.f32x2 %0, %1, %2, %3;" : "=l"(d) : "l"(a), "l"(b), "l"(d));
}
__device__ __forceinline__ float2 unpk(u64 v) {
    float lo, hi;
    asm("mov.b64 {%0, %1}, %2;" : "=f"(lo), "=f"(hi) : "l"(v));
    return make_float2(lo, hi);
}

// one k-step of the 8x8 fragment: 32 fma.f32x2
__device__ __forceinline__ void fma_step(
    const float* __restrict__ As_k, const float* __restrict__ Bs_k,
    int tx, int ty, u64 acc[8][4])
{
    float4 av0 = *(const float4*)(As_k + ty*4);
    float4 av1 = *(const float4*)(As_k + 64 + ty*4);
    ulonglong2 bv0 = *(const ulonglong2*)(Bs_k + tx*4);
    ulonglong2 bv1 = *(const ulonglong2*)(Bs_k + 64 + tx*4);
    u64 aa[8] = {dup2(av0.x), dup2(av0.y), dup2(av0.z), dup2(av0.w),
                 dup2(av1.x), dup2(av1.y), dup2(av1.z), dup2(av1.w)};
    u64 bb[4] = {bv0.x, bv0.y, bv1.x, bv1.y};
    #pragma unroll
    for (int i = 0; i < 8; i++) {
        fma2(acc[i][0], aa[i], bb[0]);
        fma2(acc[i][1], aa[i], bb[1]);
        fma2(acc[i][2], aa[i], bb[2]);
        fma2(acc[i][3], aa[i], bb[3]);
    }
}

// =============================================================================
// double-buffered conv GEMM body
// =============================================================================
__device__ __forceinline__ void gemm_db_conv2(
    const float* __restrict__ A, const float* __restrict__ Bbase, int K,
    float (* __restrict__ As)[16][132], float (* __restrict__ Bs)[16][128],
    int t, u64 acc[8][4])
{
    int arow = t >> 1, akq = (t & 1) * 8;
    int bk = t >> 4, bn = (t & 15) * 4;
    int tx = t & 15, ty = t >> 4;
    const float* Ap = A + (long)arow * K + akq;

    float4 a0 = *(const float4*)(Ap);
    float4 a1 = *(const float4*)(Ap + 4);
    const float* bs0 = Bbase + (long)bk * HW2;
    float4 b0 = *(const float4*)(bs0 + bn);
    float4 b1 = *(const float4*)(bs0 + bn + 64);
    As[0][akq+0][arow]=a0.x; As[0][akq+1][arow]=a0.y; As[0][akq+2][arow]=a0.z; As[0][akq+3][arow]=a0.w;
    As[0][akq+4][arow]=a1.x; As[0][akq+5][arow]=a1.y; As[0][akq+6][arow]=a1.z; As[0][akq+7][arow]=a1.w;
    *(float4*)&Bs[0][bk][bn]    = b0;
    *(float4*)&Bs[0][bk][bn+64] = b1;
    __syncthreads();
    int buf = 0;
    for (int k0 = 16; k0 <= K; k0 += 16) {
        if (k0 < K) {
            a0 = *(const float4*)(Ap + k0);
            a1 = *(const float4*)(Ap + k0 + 4);
            const float* bs2 = Bbase + (long)(k0 + bk) * HW2;
            b0 = *(const float4*)(bs2 + bn);
            b1 = *(const float4*)(bs2 + bn + 64);
        }
        #pragma unroll
        for (int kk = 0; kk < 16; kk++)
            fma_step(&As[buf][kk][0], &Bs[buf][kk][0], tx, ty, acc);
        if (k0 < K) {
            int nb = buf ^ 1;
            As[nb][akq+0][arow]=a0.x; As[nb][akq+1][arow]=a0.y; As[nb][akq+2][arow]=a0.z; As[nb][akq+3][arow]=a0.w;
            As[nb][akq+4][arow]=a1.x; As[nb][akq+5][arow]=a1.y; As[nb][akq+6][arow]=a1.z; As[nb][akq+7][arow]=a1.w;
            *(float4*)&Bs[nb][bk][bn]    = b0;
            *(float4*)&Bs[nb][bk][bn+64] = b1;
            __syncthreads();
            buf = nb;
        }
    }
}

// =============================================================================
// double-buffered TT GEMM body
// =============================================================================
__device__ __forceinline__ void gemm_db_tt2(
    const float* __restrict__ Abase, const float* __restrict__ Bbase, int K,
    float (* __restrict__ As)[16][132], float (* __restrict__ Bs)[16][132],
    int t, u64 acc[8][4])
{
    int row = t >> 1, kq = (t & 1) * 8;
    int tx = t & 15, ty = t >> 4;
    const float* Ap = Abase + (long)row * K + kq;
    const float* Bp = Bbase + (long)row * K + kq;

    float4 a0 = *(const float4*)(Ap);
    float4 a1 = *(const float4*)(Ap + 4);
    float4 b0 = *(const float4*)(Bp);
    float4 b1 = *(const float4*)(Bp + 4);
    As[0][kq+0][row]=a0.x; As[0][kq+1][row]=a0.y; As[0][kq+2][row]=a0.z; As[0][kq+3][row]=a0.w;
    As[0][kq+4][row]=a1.x; As[0][kq+5][row]=a1.y; As[0][kq+6][row]=a1.z; As[0][kq+7][row]=a1.w;
    Bs[0][kq+0][row]=b0.x; Bs[0][kq+1][row]=b0.y; Bs[0][kq+2][row]=b0.z; Bs[0][kq+3][row]=b0.w;
    Bs[0][kq+4][row]=b1.x; Bs[0][kq+5][row]=b1.y; Bs[0][kq+6][row]=b1.z; Bs[0][kq+7][row]=b1.w;
    __syncthreads();
    int buf = 0;
    for (int k0 = 16; k0 <= K; k0 += 16) {
        if (k0 < K) {
            a0 = *(const float4*)(Ap + k0);
            a1 = *(const float4*)(Ap + k0 + 4);
            b0 = *(const float4*)(Bp + k0);
            b1 = *(const float4*)(Bp + k0 + 4);
        }
        #pragma unroll
        for (int kk = 0; kk < 16; kk++)
            fma_step(&As[buf][kk][0], &Bs[buf][kk][0], tx, ty, acc);
        if (k0 < K) {
            int nb = buf ^ 1;
            As[nb][kq+0][row]=a0.x; As[nb][kq+1][row]=a0.y; As[nb][kq+2][row]=a0.z; As[nb][kq+3][row]=a0.w;
            As[nb][kq+4][row]=a1.x; As[nb][kq+5][row]=a1.y; As[nb][kq+6][row]=a1.z; As[nb][kq+7][row]=a1.w;
            Bs[nb][kq+0][row]=b0.x; Bs[nb][kq+1][row]=b0.y; Bs[nb][kq+2][row]=b0.z; Bs[nb][kq+3][row]=b0.w;
            Bs[nb][kq+4][row]=b1.x; Bs[nb][kq+5][row]=b1.y; Bs[nb][kq+6][row]=b1.z; Bs[nb][kq+7][row]=b1.w;
            __syncthreads();
            buf = nb;
        }
    }
}

__device__ __forceinline__ void gemm128_store2(
    float* __restrict__ Crow, const float* __restrict__ bias,
    int t, u64 acc[8][4], long ldc)
{
    int tx = t & 15, ty = t >> 4;
    #pragma unroll
    for (int i = 0; i < 8; i++) {
        int m = (i < 4) ? (ty*4 + i) : (64 + ty*4 + i - 4);
        float bv = bias ? bias[m] : 0.f;
        float2 p0 = unpk(acc[i][0]), p1 = unpk(acc[i][1]);
        float2 p2 = unpk(acc[i][2]), p3 = unpk(acc[i][3]);
        float4 o0 = {p0.x+bv, p0.y+bv, p1.x+bv, p1.y+bv};
        float4 o1 = {p2.x+bv, p2.y+bv, p3.x+bv, p3.y+bv};
        *(float4*)&Crow[(long)m*ldc + tx*4]      = o0;
        *(float4*)&Crow[(long)m*ldc + 64 + tx*4] = o1;
    }
}

// stage A
__global__ void __launch_bounds__(256,2) gemm_stageA(
    const float* __restrict__ x,
    const float* __restrict__ qk_w, const float* __restrict__ qk_b,
    const float* __restrict__ v_w,  const float* __restrict__ v_b)
{
    int n0 = blockIdx.x * 128, y = blockIdx.y, b = blockIdx.z;
    int t = threadIdx.x;
    __shared__ float As[2][16][132];
    __shared__ float Bs[2][16][128];
    u64 acc[8][4] = {};
    const float* A   = (y < 2) ? (qk_w + (long)y*128*128) : v_w;
    const float* bia = (y < 2) ? (qk_b + y*128)           : v_b;
    int cch          = (y < 2) ? (y*128)                  : 256;
    gemm_db_conv2(A, x + (long)b*128*HW2 + n0, 128, As, Bs, t, acc);
    gemm128_store2(g_buf1 + ((long)b*384 + cch) * HW2 + n0, bia, t, acc, HW2);
}

// stage C
__global__ void __launch_bounds__(256,2) gemm_stageC(
    const float* __restrict__ q2_w, const float* __restrict__ q2_b,
    const float* __restrict__ k2_w, const float* __restrict__ k2_b)
{
    int n0 = blockIdx.x * 128, y = blockIdx.y, b = blockIdx.z;
    int t = threadIdx.x;
    __shared__ float As[2][16][132];
    __shared__ float Bs[2][16][128];
    u64 acc[8][4] = {};
    const float* A   = (y < 2) ? (q2_w + (long)y*128*128) : (k2_w + (long)(y-2)*128*128);
    const float* bia = (y < 2) ? (q2_b + y*128)           : (k2_b + (y-2)*128);
    const float* Bbase = g_buf2 + ((long)b*384 + ((y < 2) ? 0 : 128)) * HW2 + n0;
    gemm_db_conv2(A, Bbase, 128, As, Bs, t, acc);
    gemm128_store2(g_buf3 + ((long)b*512 + y*128) * HW2 + n0, bia, t, acc, HW2);
}

// attention GEMM
__global__ void __launch_bounds__(256,2) attn_gemm2(
    const float* __restrict__ kc, const float* __restrict__ knew)
{
    int z = blockIdx.z; int b = z / NFtot, f = z % NFtot;
    const float* Qp = g_qtok + (long)b * Ntok * D2;
    const float* Kp = (f < 2) ? (kc   + ((long)(b*2 + f)) * Ntok * D2)
                              : (knew + ((long)(b*2 + 1)) * Ntok * D2);
    int m0 = blockIdx.y * 128, n0 = blockIdx.x * 128;
    int t = threadIdx.x;
    int tx = t & 15, ty = t >> 4;
    __shared__ float As[2][16][132];
    __shared__ float Bs[2][16][132];
    u64 acc[8][4] = {};
    gemm_db_tt2(Qp + (long)m0 * D2, Kp + (long)n0 * D2, D2, As, Bs, t, acc);
    float* Cp = g_attn + (long)z * Ntok * Ntok;
    #pragma unroll
    for (int i = 0; i < 8; i++) {
        int m = (i < 4) ? (ty*4 + i) : (64 + ty*4 + i - 4);
        float2 p0 = unpk(acc[i][0]), p1 = unpk(acc[i][1]);
        float2 p2 = unpk(acc[i][2]), p3 = unpk(acc[i][3]);
        float4 o0 = {p0.x, p0.y, p1.x, p1.y};
        float4 o1 = {p2.x, p2.y, p3.x, p3.y};
        *(float4*)&Cp[(long)(m0+m)*Ntok + n0 + tx*4]      = o0;
        *(float4*)&Cp[(long)(m0+m)*Ntok + n0 + 64 + tx*4] = o1;
    }
}

// proj 1x1 GEMM with fused window de-permute gather
__global__ void __launch_bounds__(256,2) proj_gemm2(
    const float* __restrict__ W, const float* __restrict__ bias,
    float* __restrict__ Out)
{
    int z  = blockIdx.z;
    int n0 = blockIdx.x * 128;
    int t = threadIdx.x;
    int tx = t & 15, ty = t >> 4;
    __shared__ float As[2][16][132];
    __shared__ float Bs[2][16][132];
    u64 acc[8][4] = {};
    int row = t >> 1;
    int p = n0 + row;
    int h = p / HWd, w = p % HWd;
    int token = (h % HGd) * HGd + (w % HGd);
    int vbase = ((h / HGd) * 4 + (w / HGd)) * 128;
    {
        int kq = (t & 1) * 8;
        const float* Ap = W + (long)row * 128 + kq;
        const float* Bp = g_otok + ((long)z * Ntok + token) * VDdim + vbase + kq;
        float4 a0 = *(const float4*)(Ap);
        float4 a1 = *(const float4*)(Ap + 4);
        float4 b0 = *(const float4*)(Bp);
        float4 b1 = *(const float4*)(Bp + 4);
        As[0][kq+0][row]=a0.x; As[0][kq+1][row]=a0.y; As[0][kq+2][row]=a0.z; As[0][kq+3][row]=a0.w;
        As[0][kq+4][row]=a1.x; As[0][kq+5][row]=a1.y; As[0][kq+6][row]=a1.z; As[0][kq+7][row]=a1.w;
        Bs[0][kq+0][row]=b0.x; Bs[0][kq+1][row]=b0.y; Bs[0][kq+2][row]=b0.z; Bs[0][kq+3][row]=b0.w;
        Bs[0][kq+4][row]=b1.x; Bs[0][kq+5][row]=b1.y; Bs[0][kq+6][row]=b1.z; Bs[0][kq+7][row]=b1.w;
        __syncthreads();
        int buf = 0;
        for (int k0 = 16; k0 <= 128; k0 += 16) {
            if (k0 < 128) {
                a0 = *(const float4*)(Ap + k0);
                a1 = *(const float4*)(Ap + k0 + 4);
                b0 = *(const float4*)(Bp + k0);
                b1 = *(const float4*)(Bp + k0 + 4);
            }
            #pragma unroll
            for (int kk = 0; kk < 16; kk++)
                fma_step(&As[buf][kk][0], &Bs[buf][kk][0], tx, ty, acc);
            if (k0 < 128) {
                int nb = buf ^ 1;
                As[nb][kq+0][row]=a0.x; As[nb][kq+1][row]=a0.y; As[nb][kq+2][row]=a0.z; As[nb][kq+3][row]=a0.w;
                As[nb][kq+4][row]=a1.x; As[nb][kq+5][row]=a1.y; As[nb][kq+6][row]=a1.z; As[nb][kq+7][row]=a1.w;
                Bs[nb][kq+0][row]=b0.x; Bs[nb][kq+1][row]=b0.y; Bs[nb][kq+2][row]=b0.z; Bs[nb][kq+3][row]=b0.w;
                Bs[nb][kq+4][row]=b1.x; Bs[nb][kq+5][row]=b1.y; Bs[nb][kq+6][row]=b1.z; Bs[nb][kq+7][row]=b1.w;
                __syncthreads();
                buf = nb;
            }
        }
    }
    #pragma unroll
    for (int i = 0; i < 8; i++) {
        int m = (i < 4) ? (ty*4 + i) : (64 + ty*4 + i - 4);
        float bv = bias[m];
        float2 p0 = unpk(acc[i][0]), p1 = unpk(acc[i][1]);
        float2 p2 = unpk(acc[i][2]), p3 = unpk(acc[i][3]);
        float4 o0 = {p0.x+bv, p0.y+bv, p1.x+bv, p1.y+bv};
        float4 o1 = {p2.x+bv, p2.y+bv, p3.x+bv, p3.y+bv};
        *(float4*)&Out[((long)z*128 + m)*HW2 + n0 + tx*4]      = o0;
        *(float4*)&Out[((long)z*128 + m)*HW2 + n0 + 64 + tx*4] = o1;
    }
}

// ---------------- depthwise 3x3 pad1 ------------------------------------------
__global__ void dw3x3(const float* __restrict__ qk_dw_w, const float* __restrict__ qk_dw_b,
                      const float* __restrict__ v_dw_w,  const float* __restrict__ v_dw_b)
{
    int idx = blockIdx.x * 256 + threadIdx.x;
    if (idx >= BATCH*384*HW2) return;
    int p  = idx % HW2;
    int ch = (idx / HW2) % 384;
    int b  = idx / (384*HW2);
    int h = p / HWd, w = p % HWd;
    const float* wgt; float bv;
    if (ch < 256) { wgt = qk_dw_w + ch*9;        bv = qk_dw_b[ch]; }
    else          { wgt = v_dw_w  + (ch-256)*9;  bv = v_dw_b[ch-256]; }
    const float* in = g_buf1 + ((long)(b*384 + ch)) * HW2;
    float s = bv;
    #pragma unroll
    for (int ky = 0; ky < 3; ky++) {
        int y = h + ky - 1;
        if ((unsigned)y >= (unsigned)HWd) continue;
        #pragma unroll
        for (int kx = 0; kx < 3; kx++) {
            int x = w + kx - 1;
            if ((unsigned)x >= (unsigned)HWd) continue;
            s += wgt[ky*3+kx] * in[y*HWd + x];
        }
    }
    g_buf2[idx] = s;
}

// ---------------- depthwise 4x4 stride4 pad1 ----------------------------------
__global__ void dw4x4(const float* __restrict__ q2_dw_w, const float* __restrict__ q2_dw_b,
                      const float* __restrict__ k2_dw_w, const float* __restrict__ k2_dw_b)
{
    int idx = blockIdx.x * 256 + threadIdx.x;
    if (idx >= BATCH*512*Ntok) return;
    int t  = idx % Ntok;
    int ch = (idx / Ntok) % 512;
    int b  = idx / (512*Ntok);
    int oy = t / HGd, ox = t % HGd;
    const float* wgt; float bv;
    if (ch < 256) { wgt = q2_dw_w + ch*16;       bv = q2_dw_b[ch]; }
    else          { wgt = k2_dw_w + (ch-256)*16; bv = k2_dw_b[ch-256]; }
    const float* in = g_buf3 + ((long)(b*512 + ch)) * HW2;
    float s = bv;
    #pragma unroll
    for (int ky = 0; ky < 4; ky++) {
        int y = oy*4 - 1 + ky;
        if ((unsigned)y >= (unsigned)HWd) continue;
        #pragma unroll
        for (int kx = 0; kx < 4; kx++) {
            int x = ox*4 - 1 + kx;
            if ((unsigned)x >= (unsigned)HWd) continue;
            s += wgt[ky*4+kx] * in[y*HWd + x];
        }
    }
    g_buf4[idx] = s;
}

// ---------------- l2 normalize + token-major q/k ------------------------------
__global__ void __launch_bounds__(256) norm_qk(float* __restrict__ kout,
                                               const float* __restrict__ temp)
{
    int token = blockIdx.x, b = blockIdx.y, d = threadIdx.x;
    float qv = g_buf4[((long)b*512 + d)       * Ntok + token];
    float kv = g_buf4[((long)b*512 + 256 + d) * Ntok + token];
    __shared__ float red[256];
    __shared__ float qinv_s, kinv_s;
    red[d] = qv*qv; __syncthreads();
    for (int s = 128; s > 0; s >>= 1) { if (d < s) red[d] += red[d+s]; __syncthreads(); }
    if (d == 0) qinv_s = (*temp) / fmaxf(sqrtf(red[0]), 1e-12f);
    __syncthreads();
    red[d] = kv*kv; __syncthreads();
    for (int s = 128; s > 0; s >>= 1) { if (d < s) red[d] += red[d+s]; __syncthreads(); }
    if (d == 0) kinv_s = 1.f / fmaxf(sqrtf(red[0]), 1e-12f);
    __syncthreads();
    g_qtok[((long)b*Ntok + token) * D2 + d] = qv * qinv_s;
    kout  [((long)(b*2 + 1)*Ntok + token) * D2 + d] = kv * kinv_s;
}

// ---------------- build v_new -------------------------------------------------
__global__ void build_vnew(float* __restrict__ vout)
{
    int idx = blockIdx.x * 256 + threadIdx.x;
    if (idx >= BATCH*Ntok*VDdim) return;
    int vd    = idx % VDdim;
    int token = (idx / VDdim) % Ntok;
    int b     = idx / (Ntok*VDdim);
    int c  = vd & 127;
    int p2 = (vd >> 7) & 3;
    int p1 = vd >> 9;
    int hi = token / HGd, wi = token % HGd;
    float val = g_buf2[((long)(b*384 + 256 + c)) * HW2 + (p1*HGd + hi) * HWd + (p2*HGd + wi)];
    vout[((long)(b*2 + 1)*Ntok + token) * VDdim + vd] = val;
}

// =============================================================================
// sparse_attn_av4: one block = 2x2 query tile, union-list AV with register
// reuse (round-9 winner), AV inner loop now in packed fma.rn.f32x2.
// =============================================================================
__global__ void __launch_bounds__(256) sparse_attn_av4(
    const float* __restrict__ v_cached, const float* __restrict__ vout)
{
    int tile = blockIdx.x;               // 0..575
    int z    = blockIdx.y;               // b*3+f
    int b = z / NFtot, f = z % NFtot;
    int qy0 = (tile / 24) * 2, qx0 = (tile % 24) * 2;
    int tid = threadIdx.x;

    __shared__ float rowbuf[Ntok];
    __shared__ float cand[256*5];
    __shared__ float bcast;
    __shared__ int   sidx[4][LISTCAP];
    __shared__ float sval[4][LISTCAP];
    __shared__ int   scnt[4];
    __shared__ unsigned umask[72];
    __shared__ int   ubase[73];
    __shared__ int   nnz;
    __shared__ int   uidx[MAXU];
    __shared__ float Wt[4][MAXU];

    if (tid < 72) umask[tid] = 0;

    for (int q = 0; q < 4; q++) {
        int ny = qy0 + (q >> 1), nx = qx0 + (q & 1);
        int n = ny * HGd + nx;
        const float* arow = g_attn + ((long)z * Ntok + n) * Ntok;
        __syncthreads();
        for (int m = tid*4; m < Ntok; m += 1024)
            *(float4*)&rowbuf[m] = *(const float4*)&arow[m];
        if (tid == 0) nnz = 0;
        __syncthreads();

        // per-thread top-5
        float t5[5] = {-INFINITY,-INFINITY,-INFINITY,-INFINITY,-INFINITY};
        for (int m = tid; m < Ntok; m += 256) {
            float v = rowbuf[m];
            if (v > t5[4]) {
                t5[4] = v;
                #pragma unroll
                for (int i = 4; i > 0; i--)
                    if (t5[i] > t5[i-1]) { float tmp = t5[i-1]; t5[i-1] = t5[i]; t5[i] = tmp; }
            }
        }
        #pragma unroll
        for (int i = 0; i < 5; i++) cand[tid*5 + i] = t5[i];
        __syncthreads();

        // warp 0 merges 1280 candidates -> kth largest (strict-< exclusion)
        if (tid < 32) {
            float l5[5] = {-INFINITY,-INFINITY,-INFINITY,-INFINITY,-INFINITY};
            const float* cp = cand + tid*40;
            #pragma unroll
            for (int i = 0; i < 40; i++) {
                float v = cp[i];
                if (v > l5[4]) {
                    l5[4] = v;
                    #pragma unroll
                    for (int j = 4; j > 0; j--)
                        if (l5[j] > l5[j-1]) { float tmp = l5[j-1]; l5[j-1] = l5[j]; l5[j] = tmp; }
                }
            }
            float thr = INFINITY;
            #pragma unroll
            for (int r = 0; r < 5; r++) {
                float lm = -INFINITY;
                #pragma unroll
                for (int i = 0; i < 5; i++) {
                    float v = l5[i];
                    if (v < thr && v > lm) lm = v;
                }
                #pragma unroll
                for (int o = 16; o > 0; o >>= 1)
                    lm = fmaxf(lm, __shfl_xor_sync(0xffffffffu, lm, o));
                thr = lm;
            }
            if (tid == 0) bcast = thr;
        }
        __syncthreads();
        float kth = bcast;

        // collect nonzero entries; OR into union bitmap
        for (int m = tid; m < Ntok; m += 256) {
            float a = rowbuf[m];
            float coef = (a >= kth) ? 1.f : 0.f;
            int my = m / HGd, mx = m % HGd;
            if (abs(ny - my) + abs(nx - mx) <= 4) coef += 1.f;
            float v = a * coef;
            if (v != 0.f) {
                int pos = atomicAdd(&nnz, 1);
                if (pos < LISTCAP) { sidx[q][pos] = m; sval[q][pos] = v; }
                atomicOr(&umask[m >> 5], 1u << (m & 31));
            }
        }
        __syncthreads();
        int cnt = min(nnz, LISTCAP);

        // softmax: warp-0 max, block exp, warp-0 sum, block divide
        if (tid < 32) {
            float mx = -INFINITY;
            for (int e = tid; e < cnt; e += 32) mx = fmaxf(mx, sval[q][e]);
            #pragma unroll
            for (int o = 16; o > 0; o >>= 1)
                mx = fmaxf(mx, __shfl_xor_sync(0xffffffffu, mx, o));
            if (tid == 0) bcast = mx;
        }
        __syncthreads();
        float mxv = bcast;
        if (tid < cnt) sval[q][tid] = expf(sval[q][tid] - mxv);
        __syncthreads();
        if (tid < 32) {
            float s = 0.f;
            for (int e = tid; e < cnt; e += 32) s += sval[q][e];
            #pragma unroll
            for (int o = 16; o > 0; o >>= 1)
                s += __shfl_xor_sync(0xffffffffu, s, o);
            if (tid == 0) { bcast = s; scnt[q] = cnt; }
        }
        __syncthreads();
        if (tid < cnt) sval[q][tid] = sval[q][tid] / bcast;
    }
    __syncthreads();

    // union prefix ranks
    if (tid == 0) {
        int s = 0;
        for (int w = 0; w < 72; w++) { ubase[w] = s; s += __popc(umask[w]); }
        ubase[72] = s;
    }
    __syncthreads();
    int U = min(ubase[72], MAXU);

    // zero weight table, build union index list
    for (int i = tid; i < 4*MAXU; i += 256) ((float*)Wt)[i] = 0.f;
    __syncthreads();
    if (tid < 72) {
        unsigned bits = umask[tid];
        int pos = ubase[tid];
        while (bits) {
            int bit = __ffs(bits) - 1; bits &= bits - 1;
            if (pos < MAXU) uidx[pos] = tid*32 + bit;
            pos++;
        }
    }
    __syncthreads();
    // scatter per-query weights by union rank
    for (int i = tid; i < 4*LISTCAP; i += 256) {
        int q = i >> 7, e = i & (LISTCAP-1);
        if (e < scnt[q]) {
            int m = sidx[q][e];
            int w32 = m >> 5, bit = m & 31;
            int rank = ubase[w32] + __popc(umask[w32] & ((1u << bit) - 1u));
            if (rank < MAXU) Wt[q][rank] = sval[q][e];
        }
    }
    __syncthreads();

    // AV over union list: one load, 4 accumulator sets, packed f32x2 FMA
    const float* vbase = (f < 2) ? (v_cached + ((long)(b*2 + f)) * Ntok * VDdim)
                                 : (vout     + ((long)(b*2 + 1)) * Ntok * VDdim);
    int d0 = tid * 8;
    u64 acc[4][4] = {};
    for (int e = 0; e < U; e++) {
        int m = uidx[e];
        const float* vr = vbase + (long)m * VDdim + d0;
        ulonglong2 v0 = *(const ulonglong2*)vr;
        ulonglong2 v1 = *(const ulonglong2*)(vr + 4);
        u64 w0 = dup2(Wt[0][e]);
        u64 w1 = dup2(Wt[1][e]);
        u64 w2 = dup2(Wt[2][e]);
        u64 w3 = dup2(Wt[3][e]);
        fma2(acc[0][0], w0, v0.x); fma2(acc[0][1], w0, v0.y);
        fma2(acc[0][2], w0, v1.x); fma2(acc[0][3], w0, v1.y);
        fma2(acc[1][0], w1, v0.x); fma2(acc[1][1], w1, v0.y);
        fma2(acc[1][2], w1, v1.x); fma2(acc[1][3], w1, v1.y);
        fma2(acc[2][0], w2, v0.x); fma2(acc[2][1], w2, v0.y);
        fma2(acc[2][2], w2, v1.x); fma2(acc[2][3], w2, v1.y);
        fma2(acc[3][0], w3, v0.x); fma2(acc[3][1], w3, v0.y);
        fma2(acc[3][2], w3, v1.x); fma2(acc[3][3], w3, v1.y);
    }
    #pragma unroll
    for (int q = 0; q < 4; q++) {
        int ny = qy0 + (q >> 1), nx = qx0 + (q & 1);
        float2 p0 = unpk(acc[q][0]), p1 = unpk(acc[q][1]);
        float2 p2 = unpk(acc[q][2]), p3 = unpk(acc[q][3]);
        float* orow = g_otok + ((long)z * Ntok + ny*HGd + nx) * VDdim + d0;
        *(float4*)orow       = make_float4(p0.x, p0.y, p1.x, p1.y);
        *(float4*)(orow + 4) = make_float4(p2.x, p2.y, p3.x, p3.y);
    }
}

// ---------------------------------- launch -----------------------------------
extern "C" void kernel_launch(void* const* d_in, const int* in_sizes, int n_in,
                              void* d_out, int out_size)
{
    (void)in_sizes; (void)n_in; (void)out_size;
    const float* x         = (const float*)d_in[0];
    const float* k_cached  = (const float*)d_in[1];
    const float* v_cached  = (const float*)d_in[2];
    const float* temperature = (const float*)d_in[3];
    const float* qk_w  = (const float*)d_in[4],  *qk_b  = (const float*)d_in[5];
    const float* qk_dw_w = (const float*)d_in[6], *qk_dw_b = (const float*)d_in[7];
    const float* v_w   = (const float*)d_in[8],  *v_b   = (const float*)d_in[9];
    const float* v_dw_w = (const float*)d_in[10], *v_dw_b = (const float*)d_in[11];
    const float* k2_w  = (const float*)d_in[12], *k2_b  = (const float*)d_in[13];
    const float* k2_dw_w = (const float*)d_in[14], *k2_dw_b = (const float*)d_in[15];
    const float* q2_w  = (const float*)d_in[16], *q2_b  = (const float*)d_in[17];
    const float* q2_dw_w = (const float*)d_in[18], *q2_dw_b = (const float*)d_in[19];
    const float* proj_w = (const float*)d_in[20], *proj_b = (const float*)d_in[21];

    float* out = (float*)d_out;
    const long OUT_K = (long)BATCH * NFtot * 128 * HW2;
    const long OUT_V = OUT_K + (long)BATCH * 2 * Ntok * D2;
    float* kout = out + OUT_K;
    float* vout = out + OUT_V;

    dim3 blk(256);

    gemm_stageA<<<dim3(288,3,BATCH), blk>>>(x, qk_w, qk_b, v_w, v_b);
    dw3x3<<<(BATCH*384*HW2 + 255)/256, blk>>>(qk_dw_w, qk_dw_b, v_dw_w, v_dw_b);
    gemm_stageC<<<dim3(288,4,BATCH), blk>>>(q2_w, q2_b, k2_w, k2_b);
    dw4x4<<<(BATCH*512*Ntok + 255)/256, blk>>>(q2_dw_w, q2_dw_b, k2_dw_w, k2_dw_b);
    norm_qk<<<dim3(Ntok, BATCH), blk>>>(kout, temperature);
    build_vnew<<<(BATCH*Ntok*VDdim + 255)/256, blk>>>(vout);
    for (int b = 0; b < BATCH; b++) {
        cudaMemcpyAsync(kout + (long)(b*2)*Ntok*D2,
                        k_cached + (long)(b*2+1)*Ntok*D2,
                        (size_t)Ntok*D2*sizeof(float), cudaMemcpyDeviceToDevice, 0);
        cudaMemcpyAsync(vout + (long)(b*2)*Ntok*VDdim,
                        v_cached + (long)(b*2+1)*Ntok*VDdim,
                        (size_t)Ntok*VDdim*sizeof(float), cudaMemcpyDeviceToDevice, 0);
    }
    attn_gemm2<<<dim3(18,18,BATCH*NFtot), blk>>>(k_cached, kout);
    sparse_attn_av4<<<dim3(576, BATCH*NFtot), blk>>>(v_cached, vout);
    proj_gemm2<<<dim3(288,1,BATCH*NFtot), blk>>>(proj_w, proj_b, out);
}

// round 12
// speedup vs baseline: 1.4912x; 1.0768x over previous
#include <cuda_runtime.h>
#include <math.h>

#define BATCH 2
#define HWd   192
#define HW2   (HWd*HWd)      // 36864
#define HGd   48
#define Ntok  (HGd*HGd)      // 2304
#define D2    256
#define VDdim 2048
#define NFtot 3
#define LISTCAP 128
#define MAXU   256

typedef unsigned long long u64;

// ---------------- scratch (device globals; no allocs allowed) ----------------
__device__ float g_buf1[(size_t)BATCH*384*HW2];
__device__ float g_buf2[(size_t)BATCH*384*HW2];
__device__ float g_buf3[(size_t)BATCH*512*HW2];
__device__ float g_buf4[(size_t)BATCH*512*Ntok];
__device__ float g_qtok[(size_t)BATCH*Ntok*D2];
__device__ float g_attn[(size_t)BATCH*NFtot*Ntok*Ntok];
__device__ float g_otok[(size_t)BATCH*NFtot*Ntok*VDdim];

// ---------------- packed fp32x2 primitives (Blackwell FFMA2) -----------------
__device__ __forceinline__ u64 dup2(float x) {
    u64 r;
    asm("mov.b64 %0, {%1, %1};" : "=l"(r) : "r"(__float_as_uint(x)));
    return r;
}
__device__ __forceinline__ void fma2(u64 &d, u64 a, u64 b) {
    asm("fma.rn.f32x2 %0, %1, %2, %3;" : "=l"(d) : "l"(a), "l"(b), "l"(d));
}
__device__ __forceinline__ float2 unpk(u64 v) {
    float lo, hi;
    asm("mov.b64 {%0, %1}, %2;" : "=f"(lo), "=f"(hi) : "l"(v));
    return make_float2(lo, hi);
}

// one k-step of the 8x8 fragment: 32 fma.f32x2
__device__ __forceinline__ void fma_step(
    const float* __restrict__ As_k, const float* __restrict__ Bs_k,
    int tx, int ty, u64 acc[8][4])
{
    float4 av0 = *(const float4*)(As_k + ty*4);
    float4 av1 = *(const float4*)(As_k + 64 + ty*4);
    ulonglong2 bv0 = *(const ulonglong2*)(Bs_k + tx*4);
    ulonglong2 bv1 = *(const ulonglong2*)(Bs_k + 64 + tx*4);
    u64 aa[8] = {dup2(av0.x), dup2(av0.y), dup2(av0.z), dup2(av0.w),
                 dup2(av1.x), dup2(av1.y), dup2(av1.z), dup2(av1.w)};
    u64 bb[4] = {bv0.x, bv0.y, bv1.x, bv1.y};
    #pragma unroll
    for (int i = 0; i < 8; i++) {
        fma2(acc[i][0], aa[i], bb[0]);
        fma2(acc[i][1], aa[i], bb[1]);
        fma2(acc[i][2], aa[i], bb[2]);
        fma2(acc[i][3], aa[i], bb[3]);
    }
}

// =============================================================================
// double-buffered conv GEMM body
// =============================================================================
__device__ __forceinline__ void gemm_db_conv2(
    const float* __restrict__ A, const float* __restrict__ Bbase, int K,
    float (* __restrict__ As)[16][132], float (* __restrict__ Bs)[16][128],
    int t, u64 acc[8][4])
{
    int arow = t >> 1, akq = (t & 1) * 8;
    int bk = t >> 4, bn = (t & 15) * 4;
    int tx = t & 15, ty = t >> 4;
    const float* Ap = A + (long)arow * K + akq;

    float4 a0 = *(const float4*)(Ap);
    float4 a1 = *(const float4*)(Ap + 4);
    const float* bs0 = Bbase + (long)bk * HW2;
    float4 b0 = *(const float4*)(bs0 + bn);
    float4 b1 = *(const float4*)(bs0 + bn + 64);
    As[0][akq+0][arow]=a0.x; As[0][akq+1][arow]=a0.y; As[0][akq+2][arow]=a0.z; As[0][akq+3][arow]=a0.w;
    As[0][akq+4][arow]=a1.x; As[0][akq+5][arow]=a1.y; As[0][akq+6][arow]=a1.z; As[0][akq+7][arow]=a1.w;
    *(float4*)&Bs[0][bk][bn]    = b0;
    *(float4*)&Bs[0][bk][bn+64] = b1;
    __syncthreads();
    int buf = 0;
    for (int k0 = 16; k0 <= K; k0 += 16) {
        if (k0 < K) {
            a0 = *(const float4*)(Ap + k0);
            a1 = *(const float4*)(Ap + k0 + 4);
            const float* bs2 = Bbase + (long)(k0 + bk) * HW2;
            b0 = *(const float4*)(bs2 + bn);
            b1 = *(const float4*)(bs2 + bn + 64);
        }
        #pragma unroll
        for (int kk = 0; kk < 16; kk++)
            fma_step(&As[buf][kk][0], &Bs[buf][kk][0], tx, ty, acc);
        if (k0 < K) {
            int nb = buf ^ 1;
            As[nb][akq+0][arow]=a0.x; As[nb][akq+1][arow]=a0.y; As[nb][akq+2][arow]=a0.z; As[nb][akq+3][arow]=a0.w;
            As[nb][akq+4][arow]=a1.x; As[nb][akq+5][arow]=a1.y; As[nb][akq+6][arow]=a1.z; As[nb][akq+7][arow]=a1.w;
            *(float4*)&Bs[nb][bk][bn]    = b0;
            *(float4*)&Bs[nb][bk][bn+64] = b1;
            __syncthreads();
            buf = nb;
        }
    }
}

// =============================================================================
// double-buffered TT GEMM body
// =============================================================================
__device__ __forceinline__ void gemm_db_tt2(
    const float* __restrict__ Abase, const float* __restrict__ Bbase, int K,
    float (* __restrict__ As)[16][132], float (* __restrict__ Bs)[16][132],
    int t, u64 acc[8][4])
{
    int row = t >> 1, kq = (t & 1) * 8;
    int tx = t & 15, ty = t >> 4;
    const float* Ap = Abase + (long)row * K + kq;
    const float* Bp = Bbase + (long)row * K + kq;

    float4 a0 = *(const float4*)(Ap);
    float4 a1 = *(const float4*)(Ap + 4);
    float4 b0 = *(const float4*)(Bp);
    float4 b1 = *(const float4*)(Bp + 4);
    As[0][kq+0][row]=a0.x; As[0][kq+1][row]=a0.y; As[0][kq+2][row]=a0.z; As[0][kq+3][row]=a0.w;
    As[0][kq+4][row]=a1.x; As[0][kq+5][row]=a1.y; As[0][kq+6][row]=a1.z; As[0][kq+7][row]=a1.w;
    Bs[0][kq+0][row]=b0.x; Bs[0][kq+1][row]=b0.y; Bs[0][kq+2][row]=b0.z; Bs[0][kq+3][row]=b0.w;
    Bs[0][kq+4][row]=b1.x; Bs[0][kq+5][row]=b1.y; Bs[0][kq+6][row]=b1.z; Bs[0][kq+7][row]=b1.w;
    __syncthreads();
    int buf = 0;
    for (int k0 = 16; k0 <= K; k0 += 16) {
        if (k0 < K) {
            a0 = *(const float4*)(Ap + k0);
            a1 = *(const float4*)(Ap + k0 + 4);
            b0 = *(const float4*)(Bp + k0);
            b1 = *(const float4*)(Bp + k0 + 4);
        }
        #pragma unroll
        for (int kk = 0; kk < 16; kk++)
            fma_step(&As[buf][kk][0], &Bs[buf][kk][0], tx, ty, acc);
        if (k0 < K) {
            int nb = buf ^ 1;
            As[nb][kq+0][row]=a0.x; As[nb][kq+1][row]=a0.y; As[nb][kq+2][row]=a0.z; As[nb][kq+3][row]=a0.w;
            As[nb][kq+4][row]=a1.x; As[nb][kq+5][row]=a1.y; As[nb][kq+6][row]=a1.z; As[nb][kq+7][row]=a1.w;
            Bs[nb][kq+0][row]=b0.x; Bs[nb][kq+1][row]=b0.y; Bs[nb][kq+2][row]=b0.z; Bs[nb][kq+3][row]=b0.w;
            Bs[nb][kq+4][row]=b1.x; Bs[nb][kq+5][row]=b1.y; Bs[nb][kq+6][row]=b1.z; Bs[nb][kq+7][row]=b1.w;
            __syncthreads();
            buf = nb;
        }
    }
}

__device__ __forceinline__ void gemm128_store2(
    float* __restrict__ Crow, const float* __restrict__ bias,
    int t, u64 acc[8][4], long ldc)
{
    int tx = t & 15, ty = t >> 4;
    #pragma unroll
    for (int i = 0; i < 8; i++) {
        int m = (i < 4) ? (ty*4 + i) : (64 + ty*4 + i - 4);
        float bv = bias ? bias[m] : 0.f;
        float2 p0 = unpk(acc[i][0]), p1 = unpk(acc[i][1]);
        float2 p2 = unpk(acc[i][2]), p3 = unpk(acc[i][3]);
        float4 o0 = {p0.x+bv, p0.y+bv, p1.x+bv, p1.y+bv};
        float4 o1 = {p2.x+bv, p2.y+bv, p3.x+bv, p3.y+bv};
        *(float4*)&Crow[(long)m*ldc + tx*4]      = o0;
        *(float4*)&Crow[(long)m*ldc + 64 + tx*4] = o1;
    }
}

// stage A
__global__ void __launch_bounds__(256,2) gemm_stageA(
    const float* __restrict__ x,
    const float* __restrict__ qk_w, const float* __restrict__ qk_b,
    const float* __restrict__ v_w,  const float* __restrict__ v_b)
{
    int n0 = blockIdx.x * 128, y = blockIdx.y, b = blockIdx.z;
    int t = threadIdx.x;
    __shared__ float As[2][16][132];
    __shared__ float Bs[2][16][128];
    u64 acc[8][4] = {};
    const float* A   = (y < 2) ? (qk_w + (long)y*128*128) : v_w;
    const float* bia = (y < 2) ? (qk_b + y*128)           : v_b;
    int cch          = (y < 2) ? (y*128)                  : 256;
    gemm_db_conv2(A, x + (long)b*128*HW2 + n0, 128, As, Bs, t, acc);
    gemm128_store2(g_buf1 + ((long)b*384 + cch) * HW2 + n0, bia, t, acc, HW2);
}

// stage C
__global__ void __launch_bounds__(256,2) gemm_stageC(
    const float* __restrict__ q2_w, const float* __restrict__ q2_b,
    const float* __restrict__ k2_w, const float* __restrict__ k2_b)
{
    int n0 = blockIdx.x * 128, y = blockIdx.y, b = blockIdx.z;
    int t = threadIdx.x;
    __shared__ float As[2][16][132];
    __shared__ float Bs[2][16][128];
    u64 acc[8][4] = {};
    const float* A   = (y < 2) ? (q2_w + (long)y*128*128) : (k2_w + (long)(y-2)*128*128);
    const float* bia = (y < 2) ? (q2_b + y*128)           : (k2_b + (y-2)*128);
    const float* Bbase = g_buf2 + ((long)b*384 + ((y < 2) ? 0 : 128)) * HW2 + n0;
    gemm_db_conv2(A, Bbase, 128, As, Bs, t, acc);
    gemm128_store2(g_buf3 + ((long)b*512 + y*128) * HW2 + n0, bia, t, acc, HW2);
}

// attention GEMM
__global__ void __launch_bounds__(256,2) attn_gemm2(
    const float* __restrict__ kc, const float* __restrict__ knew)
{
    int z = blockIdx.z; int b = z / NFtot, f = z % NFtot;
    const float* Qp = g_qtok + (long)b * Ntok * D2;
    const float* Kp = (f < 2) ? (kc   + ((long)(b*2 + f)) * Ntok * D2)
                              : (knew + ((long)(b*2 + 1)) * Ntok * D2);
    int m0 = blockIdx.y * 128, n0 = blockIdx.x * 128;
    int t = threadIdx.x;
    int tx = t & 15, ty = t >> 4;
    __shared__ float As[2][16][132];
    __shared__ float Bs[2][16][132];
    u64 acc[8][4] = {};
    gemm_db_tt2(Qp + (long)m0 * D2, Kp + (long)n0 * D2, D2, As, Bs, t, acc);
    float* Cp = g_attn + (long)z * Ntok * Ntok;
    #pragma unroll
    for (int i = 0; i < 8; i++) {
        int m = (i < 4) ? (ty*4 + i) : (64 + ty*4 + i - 4);
        float2 p0 = unpk(acc[i][0]), p1 = unpk(acc[i][1]);
        float2 p2 = unpk(acc[i][2]), p3 = unpk(acc[i][3]);
        float4 o0 = {p0.x, p0.y, p1.x, p1.y};
        float4 o1 = {p2.x, p2.y, p3.x, p3.y};
        *(float4*)&Cp[(long)(m0+m)*Ntok + n0 + tx*4]      = o0;
        *(float4*)&Cp[(long)(m0+m)*Ntok + n0 + 64 + tx*4] = o1;
    }
}

// proj 1x1 GEMM with fused window de-permute gather
__global__ void __launch_bounds__(256,2) proj_gemm2(
    const float* __restrict__ W, const float* __restrict__ bias,
    float* __restrict__ Out)
{
    int z  = blockIdx.z;
    int n0 = blockIdx.x * 128;
    int t = threadIdx.x;
    int tx = t & 15, ty = t >> 4;
    __shared__ float As[2][16][132];
    __shared__ float Bs[2][16][132];
    u64 acc[8][4] = {};
    int row = t >> 1;
    int p = n0 + row;
    int h = p / HWd, w = p % HWd;
    int token = (h % HGd) * HGd + (w % HGd);
    int vbase = ((h / HGd) * 4 + (w / HGd)) * 128;
    {
        int kq = (t & 1) * 8;
        const float* Ap = W + (long)row * 128 + kq;
        const float* Bp = g_otok + ((long)z * Ntok + token) * VDdim + vbase + kq;
        float4 a0 = *(const float4*)(Ap);
        float4 a1 = *(const float4*)(Ap + 4);
        float4 b0 = *(const float4*)(Bp);
        float4 b1 = *(const float4*)(Bp + 4);
        As[0][kq+0][row]=a0.x; As[0][kq+1][row]=a0.y; As[0][kq+2][row]=a0.z; As[0][kq+3][row]=a0.w;
        As[0][kq+4][row]=a1.x; As[0][kq+5][row]=a1.y; As[0][kq+6][row]=a1.z; As[0][kq+7][row]=a1.w;
        Bs[0][kq+0][row]=b0.x; Bs[0][kq+1][row]=b0.y; Bs[0][kq+2][row]=b0.z; Bs[0][kq+3][row]=b0.w;
        Bs[0][kq+4][row]=b1.x; Bs[0][kq+5][row]=b1.y; Bs[0][kq+6][row]=b1.z; Bs[0][kq+7][row]=b1.w;
        __syncthreads();
        int buf = 0;
        for (int k0 = 16; k0 <= 128; k0 += 16) {
            if (k0 < 128) {
                a0 = *(const float4*)(Ap + k0);
                a1 = *(const float4*)(Ap + k0 + 4);
                b0 = *(const float4*)(Bp + k0);
                b1 = *(const float4*)(Bp + k0 + 4);
            }
            #pragma unroll
            for (int kk = 0; kk < 16; kk++)
                fma_step(&As[buf][kk][0], &Bs[buf][kk][0], tx, ty, acc);
            if (k0 < 128) {
                int nb = buf ^ 1;
                As[nb][kq+0][row]=a0.x; As[nb][kq+1][row]=a0.y; As[nb][kq+2][row]=a0.z; As[nb][kq+3][row]=a0.w;
                As[nb][kq+4][row]=a1.x; As[nb][kq+5][row]=a1.y; As[nb][kq+6][row]=a1.z; As[nb][kq+7][row]=a1.w;
                Bs[nb][kq+0][row]=b0.x; Bs[nb][kq+1][row]=b0.y; Bs[nb][kq+2][row]=b0.z; Bs[nb][kq+3][row]=b0.w;
                Bs[nb][kq+4][row]=b1.x; Bs[nb][kq+5][row]=b1.y; Bs[nb][kq+6][row]=b1.z; Bs[nb][kq+7][row]=b1.w;
                __syncthreads();
                buf = nb;
            }
        }
    }
    #pragma unroll
    for (int i = 0; i < 8; i++) {
        int m = (i < 4) ? (ty*4 + i) : (64 + ty*4 + i - 4);
        float bv = bias[m];
        float2 p0 = unpk(acc[i][0]), p1 = unpk(acc[i][1]);
        float2 p2 = unpk(acc[i][2]), p3 = unpk(acc[i][3]);
        float4 o0 = {p0.x+bv, p0.y+bv, p1.x+bv, p1.y+bv};
        float4 o1 = {p2.x+bv, p2.y+bv, p3.x+bv, p3.y+bv};
        *(float4*)&Out[((long)z*128 + m)*HW2 + n0 + tx*4]      = o0;
        *(float4*)&Out[((long)z*128 + m)*HW2 + n0 + 64 + tx*4] = o1;
    }
}

// ---------------- depthwise 3x3 pad1, 4 pixels/thread -------------------------
// one thread -> outputs [w0, w0+3] of one row; 3x6 input patch in registers
__global__ void __launch_bounds__(256) dw3x3v(
    const float* __restrict__ qk_dw_w, const float* __restrict__ qk_dw_b,
    const float* __restrict__ v_dw_w,  const float* __restrict__ v_dw_b)
{
    int idx = blockIdx.x * 256 + threadIdx.x;            // quad index
    const int NQ = BATCH*384*HW2/4;
    if (idx >= NQ) return;
    int qw = idx % (HWd/4);
    int h  = (idx / (HWd/4)) % HWd;
    int ch = (idx / (HW2/4)) % 384;
    int b  = idx / (384*HW2/4);
    int w0 = qw * 4;

    const float* wgt; float bv;
    if (ch < 256) { wgt = qk_dw_w + ch*9;        bv = qk_dw_b[ch]; }
    else          { wgt = v_dw_w  + (ch-256)*9;  bv = v_dw_b[ch-256]; }
    float k0=wgt[0],k1=wgt[1],k2=wgt[2],k3=wgt[3],k4=wgt[4],k5=wgt[5],k6=wgt[6],k7=wgt[7],k8=wgt[8];

    const float* in = g_buf1 + ((long)(b*384 + ch)) * HW2;
    // load 3 rows x 6 cols (w0-1 .. w0+4); zero at borders
    float r[3][6];
    #pragma unroll
    for (int ky = 0; ky < 3; ky++) {
        int y = h + ky - 1;
        if ((unsigned)y >= (unsigned)HWd) {
            #pragma unroll
            for (int j = 0; j < 6; j++) r[ky][j] = 0.f;
        } else {
            const float* rp = in + (long)y * HWd + w0;
            float4 c = *(const float4*)rp;                 // w0..w0+3 (16B aligned)
            r[ky][1] = c.x; r[ky][2] = c.y; r[ky][3] = c.z; r[ky][4] = c.w;
            r[ky][0] = (w0 > 0)        ? rp[-1] : 0.f;
            r[ky][5] = (w0 + 4 < HWd)  ? rp[4]  : 0.f;
        }
    }
    float4 o;
    float* op = (float*)&o;
    #pragma unroll
    for (int j = 0; j < 4; j++) {
        op[j] = bv
              + k0*r[0][j] + k1*r[0][j+1] + k2*r[0][j+2]
              + k3*r[1][j] + k4*r[1][j+1] + k5*r[1][j+2]
              + k6*r[2][j] + k7*r[2][j+1] + k8*r[2][j+2];
    }
    *(float4*)&g_buf2[(long)idx*4] = o;
}

// ---------------- depthwise 4x4 stride4 pad1 ----------------------------------
__global__ void dw4x4(const float* __restrict__ q2_dw_w, const float* __restrict__ q2_dw_b,
                      const float* __restrict__ k2_dw_w, const float* __restrict__ k2_dw_b)
{
    int idx = blockIdx.x * 256 + threadIdx.x;
    if (idx >= BATCH*512*Ntok) return;
    int t  = idx % Ntok;
    int ch = (idx / Ntok) % 512;
    int b  = idx / (512*Ntok);
    int oy = t / HGd, ox = t % HGd;
    const float* wgt; float bv;
    if (ch < 256) { wgt = q2_dw_w + ch*16;       bv = q2_dw_b[ch]; }
    else          { wgt = k2_dw_w + (ch-256)*16; bv = k2_dw_b[ch-256]; }
    const float* in = g_buf3 + ((long)(b*512 + ch)) * HW2;
    float s = bv;
    #pragma unroll
    for (int ky = 0; ky < 4; ky++) {
        int y = oy*4 - 1 + ky;
        if ((unsigned)y >= (unsigned)HWd) continue;
        #pragma unroll
        for (int kx = 0; kx < 4; kx++) {
            int x = ox*4 - 1 + kx;
            if ((unsigned)x >= (unsigned)HWd) continue;
            s += wgt[ky*4+kx] * in[y*HWd + x];
        }
    }
    g_buf4[idx] = s;
}

// ---------------- l2 normalize + token-major q/k (shfl reductions) ------------
__global__ void __launch_bounds__(256) norm_qk(float* __restrict__ kout,
                                               const float* __restrict__ temp)
{
    int token = blockIdx.x, b = blockIdx.y, d = threadIdx.x;
    int lane = d & 31, wid = d >> 5;
    float qv = g_buf4[((long)b*512 + d)       * Ntok + token];
    float kv = g_buf4[((long)b*512 + 256 + d) * Ntok + token];
    __shared__ float wsumq[8], wsumk[8];
    __shared__ float qinv_s, kinv_s;
    float sq = qv*qv, sk = kv*kv;
    #pragma unroll
    for (int o = 16; o > 0; o >>= 1) {
        sq += __shfl_xor_sync(0xffffffffu, sq, o);
        sk += __shfl_xor_sync(0xffffffffu, sk, o);
    }
    if (lane == 0) { wsumq[wid] = sq; wsumk[wid] = sk; }
    __syncthreads();
    if (d < 32) {
        float tq = (lane < 8) ? wsumq[lane] : 0.f;
        float tk = (lane < 8) ? wsumk[lane] : 0.f;
        #pragma unroll
        for (int o = 4; o > 0; o >>= 1) {
            tq += __shfl_xor_sync(0xffffffffu, tq, o);
            tk += __shfl_xor_sync(0xffffffffu, tk, o);
        }
        if (lane == 0) {
            qinv_s = (*temp) / fmaxf(sqrtf(tq), 1e-12f);
            kinv_s = 1.f / fmaxf(sqrtf(tk), 1e-12f);
        }
    }
    __syncthreads();
    g_qtok[((long)b*Ntok + token) * D2 + d] = qv * qinv_s;
    kout  [((long)(b*2 + 1)*Ntok + token) * D2 + d] = kv * kinv_s;
}

// ---------------- build v_new -------------------------------------------------
__global__ void build_vnew(float* __restrict__ vout)
{
    int idx = blockIdx.x * 256 + threadIdx.x;
    if (idx >= BATCH*Ntok*VDdim) return;
    int vd    = idx % VDdim;
    int token = (idx / VDdim) % Ntok;
    int b     = idx / (Ntok*VDdim);
    int c  = vd & 127;
    int p2 = (vd >> 7) & 3;
    int p1 = vd >> 9;
    int hi = token / HGd, wi = token % HGd;
    float val = g_buf2[((long)(b*384 + 256 + c)) * HW2 + (p1*HGd + hi) * HWd + (p2*HGd + wi)];
    vout[((long)(b*2 + 1)*Ntok + token) * VDdim + vd] = val;
}

// =============================================================================
// sparse_attn_av4: 2x2 query tile, union-list AV (round-11 winner, unchanged)
// =============================================================================
__global__ void __launch_bounds__(256) sparse_attn_av4(
    const float* __restrict__ v_cached, const float* __restrict__ vout)
{
    int tile = blockIdx.x;               // 0..575
    int z    = blockIdx.y;               // b*3+f
    int b = z / NFtot, f = z % NFtot;
    int qy0 = (tile / 24) * 2, qx0 = (tile % 24) * 2;
    int tid = threadIdx.x;

    __shared__ float rowbuf[Ntok];
    __shared__ float cand[256*5];
    __shared__ float bcast;
    __shared__ int   sidx[4][LISTCAP];
    __shared__ float sval[4][LISTCAP];
    __shared__ int   scnt[4];
    __shared__ unsigned umask[72];
    __shared__ int   ubase[73];
    __shared__ int   nnz;
    __shared__ int   uidx[MAXU];
    __shared__ float Wt[4][MAXU];

    if (tid < 72) umask[tid] = 0;

    for (int q = 0; q < 4; q++) {
        int ny = qy0 + (q >> 1), nx = qx0 + (q & 1);
        int n = ny * HGd + nx;
        const float* arow = g_attn + ((long)z * Ntok + n) * Ntok;
        __syncthreads();
        for (int m = tid*4; m < Ntok; m += 1024)
            *(float4*)&rowbuf[m] = *(const float4*)&arow[m];
        if (tid == 0) nnz = 0;
        __syncthreads();

        float t5[5] = {-INFINITY,-INFINITY,-INFINITY,-INFINITY,-INFINITY};
        for (int m = tid; m < Ntok; m += 256) {
            float v = rowbuf[m];
            if (v > t5[4]) {
                t5[4] = v;
                #pragma unroll
                for (int i = 4; i > 0; i--)
                    if (t5[i] > t5[i-1]) { float tmp = t5[i-1]; t5[i-1] = t5[i]; t5[i] = tmp; }
            }
        }
        #pragma unroll
        for (int i = 0; i < 5; i++) cand[tid*5 + i] = t5[i];
        __syncthreads();

        if (tid < 32) {
            float l5[5] = {-INFINITY,-INFINITY,-INFINITY,-INFINITY,-INFINITY};
            const float* cp = cand + tid*40;
            #pragma unroll
            for (int i = 0; i < 40; i++) {
                float v = cp[i];
                if (v > l5[4]) {
                    l5[4] = v;
                    #pragma unroll
                    for (int j = 4; j > 0; j--)
                        if (l5[j] > l5[j-1]) { float tmp = l5[j-1]; l5[j-1] = l5[j]; l5[j] = tmp; }
                }
            }
            float thr = INFINITY;
            #pragma unroll
            for (int r = 0; r < 5; r++) {
                float lm = -INFINITY;
                #pragma unroll
                for (int i = 0; i < 5; i++) {
                    float v = l5[i];
                    if (v < thr && v > lm) lm = v;
                }
                #pragma unroll
                for (int o = 16; o > 0; o >>= 1)
                    lm = fmaxf(lm, __shfl_xor_sync(0xffffffffu, lm, o));
                thr = lm;
            }
            if (tid == 0) bcast = thr;
        }
        __syncthreads();
        float kth = bcast;

        for (int m = tid; m < Ntok; m += 256) {
            float a = rowbuf[m];
            float coef = (a >= kth) ? 1.f : 0.f;
            int my = m / HGd, mx = m % HGd;
            if (abs(ny - my) + abs(nx - mx) <= 4) coef += 1.f;
            float v = a * coef;
            if (v != 0.f) {
                int pos = atomicAdd(&nnz, 1);
                if (pos < LISTCAP) { sidx[q][pos] = m; sval[q][pos] = v; }
                atomicOr(&umask[m >> 5], 1u << (m & 31));
            }
        }
        __syncthreads();
        int cnt = min(nnz, LISTCAP);

        if (tid < 32) {
            float mx = -INFINITY;
            for (int e = tid; e < cnt; e += 32) mx = fmaxf(mx, sval[q][e]);
            #pragma unroll
            for (int o = 16; o > 0; o >>= 1)
                mx = fmaxf(mx, __shfl_xor_sync(0xffffffffu, mx, o));
            if (tid == 0) bcast = mx;
        }
        __syncthreads();
        float mxv = bcast;
        if (tid < cnt) sval[q][tid] = expf(sval[q][tid] - mxv);
        __syncthreads();
        if (tid < 32) {
            float s = 0.f;
            for (int e = tid; e < cnt; e += 32) s += sval[q][e];
            #pragma unroll
            for (int o = 16; o > 0; o >>= 1)
                s += __shfl_xor_sync(0xffffffffu, s, o);
            if (tid == 0) { bcast = s; scnt[q] = cnt; }
        }
        __syncthreads();
        if (tid < cnt) sval[q][tid] = sval[q][tid] / bcast;
    }
    __syncthreads();

    if (tid == 0) {
        int s = 0;
        for (int w = 0; w < 72; w++) { ubase[w] = s; s += __popc(umask[w]); }
        ubase[72] = s;
    }
    __syncthreads();
    int U = min(ubase[72], MAXU);

    for (int i = tid; i < 4*MAXU; i += 256) ((float*)Wt)[i] = 0.f;
    __syncthreads();
    if (tid < 72) {
        unsigned bits = umask[tid];
        int pos = ubase[tid];
        while (bits) {
            int bit = __ffs(bits) - 1; bits &= bits - 1;
            if (pos < MAXU) uidx[pos] = tid*32 + bit;
            pos++;
        }
    }
    __syncthreads();
    for (int i = tid; i < 4*LISTCAP; i += 256) {
        int q = i >> 7, e = i & (LISTCAP-1);
        if (e < scnt[q]) {
            int m = sidx[q][e];
            int w32 = m >> 5, bit = m & 31;
            int rank = ubase[w32] + __popc(umask[w32] & ((1u << bit) - 1u));
            if (rank < MAXU) Wt[q][rank] = sval[q][e];
        }
    }
    __syncthreads();

    const float* vbase = (f < 2) ? (v_cached + ((long)(b*2 + f)) * Ntok * VDdim)
                                 : (vout     + ((long)(b*2 + 1)) * Ntok * VDdim);
    int d0 = tid * 8;
    u64 acc[4][4] = {};
    for (int e = 0; e < U; e++) {
        int m = uidx[e];
        const float* vr = vbase + (long)m * VDdim + d0;
        ulonglong2 v0 = *(const ulonglong2*)vr;
        ulonglong2 v1 = *(const ulonglong2*)(vr + 4);
        u64 w0 = dup2(Wt[0][e]);
        u64 w1 = dup2(Wt[1][e]);
        u64 w2 = dup2(Wt[2][e]);
        u64 w3 = dup2(Wt[3][e]);
        fma2(acc[0][0], w0, v0.x); fma2(acc[0][1], w0, v0.y);
        fma2(acc[0][2], w0, v1.x); fma2(acc[0][3], w0, v1.y);
        fma2(acc[1][0], w1, v0.x); fma2(acc[1][1], w1, v0.y);
        fma2(acc[1][2], w1, v1.x); fma2(acc[1][3], w1, v1.y);
        fma2(acc[2][0], w2, v0.x); fma2(acc[2][1], w2, v0.y);
        fma2(acc[2][2], w2, v1.x); fma2(acc[2][3], w2, v1.y);
        fma2(acc[3][0], w3, v0.x); fma2(acc[3][1], w3, v0.y);
        fma2(acc[3][2], w3, v1.x); fma2(acc[3][3], w3, v1.y);
    }
    #pragma unroll
    for (int q = 0; q < 4; q++) {
        int ny = qy0 + (q >> 1), nx = qx0 + (q & 1);
        float2 p0 = unpk(acc[q][0]), p1 = unpk(acc[q][1]);
        float2 p2 = unpk(acc[q][2]), p3 = unpk(acc[q][3]);
        float* orow = g_otok + ((long)z * Ntok + ny*HGd + nx) * VDdim + d0;
        *(float4*)orow       = make_float4(p0.x, p0.y, p1.x, p1.y);
        *(float4*)(orow + 4) = make_float4(p2.x, p2.y, p3.x, p3.y);
    }
}

// ---------------------------------- launch -----------------------------------
extern "C" void kernel_launch(void* const* d_in, const int* in_sizes, int n_in,
                              void* d_out, int out_size)
{
    (void)in_sizes; (void)n_in; (void)out_size;
    const float* x         = (const float*)d_in[0];
    const float* k_cached  = (const float*)d_in[1];
    const float* v_cached  = (const float*)d_in[2];
    const float* temperature = (const float*)d_in[3];
    const float* qk_w  = (const float*)d_in[4],  *qk_b  = (const float*)d_in[5];
    const float* qk_dw_w = (const float*)d_in[6], *qk_dw_b = (const float*)d_in[7];
    const float* v_w   = (const float*)d_in[8],  *v_b   = (const float*)d_in[9];
    const float* v_dw_w = (const float*)d_in[10], *v_dw_b = (const float*)d_in[11];
    const float* k2_w  = (const float*)d_in[12], *k2_b  = (const float*)d_in[13];
    const float* k2_dw_w = (const float*)d_in[14], *k2_dw_b = (const float*)d_in[15];
    const float* q2_w  = (const float*)d_in[16], *q2_b  = (const float*)d_in[17];
    const float* q2_dw_w = (const float*)d_in[18], *q2_dw_b = (const float*)d_in[19];
    const float* proj_w = (const float*)d_in[20], *proj_b = (const float*)d_in[21];

    float* out = (float*)d_out;
    const long OUT_K = (long)BATCH * NFtot * 128 * HW2;
    const long OUT_V = OUT_K + (long)BATCH * 2 * Ntok * D2;
    float* kout = out + OUT_K;
    float* vout = out + OUT_V;

    dim3 blk(256);

    gemm_stageA<<<dim3(288,3,BATCH), blk>>>(x, qk_w, qk_b, v_w, v_b);
    dw3x3v<<<(BATCH*384*HW2/4 + 255)/256, blk>>>(qk_dw_w, qk_dw_b, v_dw_w, v_dw_b);
    gemm_stageC<<<dim3(288,4,BATCH), blk>>>(q2_w, q2_b, k2_w, k2_b);
    dw4x4<<<(BATCH*512*Ntok + 255)/256, blk>>>(q2_dw_w, q2_dw_b, k2_dw_w, k2_dw_b);
    norm_qk<<<dim3(Ntok, BATCH), blk>>>(kout, temperature);
    build_vnew<<<(BATCH*Ntok*VDdim + 255)/256, blk>>>(vout);
    for (int b = 0; b < BATCH; b++) {
        cudaMemcpyAsync(kout + (long)(b*2)*Ntok*D2,
                        k_cached + (long)(b*2+1)*Ntok*D2,
                        (size_t)Ntok*D2*sizeof(float), cudaMemcpyDeviceToDevice, 0);
        cudaMemcpyAsync(vout + (long)(b*2)*Ntok*VDdim,
                        v_cached + (long)(b*2+1)*Ntok*VDdim,
                        (size_t)Ntok*VDdim*sizeof(float), cudaMemcpyDeviceToDevice, 0);
    }
    attn_gemm2<<<dim3(18,18,BATCH*NFtot), blk>>>(k_cached, kout);
    sparse_attn_av4<<<dim3(576, BATCH*NFtot), blk>>>(v_cached, vout);
    proj_gemm2<<<dim3(288,1,BATCH*NFtot), blk>>>(proj_w, proj_b, out);
}

// round 13
// speedup vs baseline: 1.5210x; 1.0200x over previous
#include <cuda_runtime.h>
#include <math.h>

#define BATCH 2
#define HWd   192
#define HW2   (HWd*HWd)      // 36864
#define HGd   48
#define Ntok  (HGd*HGd)      // 2304
#define D2    256
#define VDdim 2048
#define NFtot 3
#define SELCAP 64
#define MAXU   128
#define NROWS (BATCH*NFtot*Ntok)

typedef unsigned long long u64;

// ---------------- scratch (device globals; no allocs allowed) ----------------
__device__ float g_buf1[(size_t)BATCH*384*HW2];
__device__ float g_buf2[(size_t)BATCH*384*HW2];
__device__ float g_buf3[(size_t)BATCH*512*HW2];
__device__ float g_buf4[(size_t)BATCH*512*Ntok];
__device__ float g_qtok[(size_t)BATCH*Ntok*D2];
__device__ float g_attn[(size_t)BATCH*NFtot*Ntok*Ntok];
__device__ float g_otok[(size_t)BATCH*NFtot*Ntok*VDdim];
__device__ int   g_selidx[(size_t)NROWS*SELCAP];
__device__ float g_selw  [(size_t)NROWS*SELCAP];
__device__ int   g_selcnt[NROWS];

// ---------------- packed fp32x2 primitives (Blackwell FFMA2) -----------------
__device__ __forceinline__ u64 dup2(float x) {
    u64 r;
    asm("mov.b64 %0, {%1, %1};" : "=l"(r) : "r"(__float_as_uint(x)));
    return r;
}
__device__ __forceinline__ void fma2(u64 &d, u64 a, u64 b) {
    asm("fma.rn.f32x2 %0, %1, %2, %3;" : "=l"(d) : "l"(a), "l"(b), "l"(d));
}
__device__ __forceinline__ float2 unpk(u64 v) {
    float lo, hi;
    asm("mov.b64 {%0, %1}, %2;" : "=f"(lo), "=f"(hi) : "l"(v));
    return make_float2(lo, hi);
}

// one k-step of the 8x8 fragment: 32 fma.f32x2
__device__ __forceinline__ void fma_step(
    const float* __restrict__ As_k, const float* __restrict__ Bs_k,
    int tx, int ty, u64 acc[8][4])
{
    float4 av0 = *(const float4*)(As_k + ty*4);
    float4 av1 = *(const float4*)(As_k + 64 + ty*4);
    ulonglong2 bv0 = *(const ulonglong2*)(Bs_k + tx*4);
    ulonglong2 bv1 = *(const ulonglong2*)(Bs_k + 64 + tx*4);
    u64 aa[8] = {dup2(av0.x), dup2(av0.y), dup2(av0.z), dup2(av0.w),
                 dup2(av1.x), dup2(av1.y), dup2(av1.z), dup2(av1.w)};
    u64 bb[4] = {bv0.x, bv0.y, bv1.x, bv1.y};
    #pragma unroll
    for (int i = 0; i < 8; i++) {
        fma2(acc[i][0], aa[i], bb[0]);
        fma2(acc[i][1], aa[i], bb[1]);
        fma2(acc[i][2], aa[i], bb[2]);
        fma2(acc[i][3], aa[i], bb[3]);
    }
}

// =============================================================================
// double-buffered conv GEMM body
// =============================================================================
__device__ __forceinline__ void gemm_db_conv2(
    const float* __restrict__ A, const float* __restrict__ Bbase, int K,
    float (* __restrict__ As)[16][132], float (* __restrict__ Bs)[16][128],
    int t, u64 acc[8][4])
{
    int arow = t >> 1, akq = (t & 1) * 8;
    int bk = t >> 4, bn = (t & 15) * 4;
    int tx = t & 15, ty = t >> 4;
    const float* Ap = A + (long)arow * K + akq;

    float4 a0 = *(const float4*)(Ap);
    float4 a1 = *(const float4*)(Ap + 4);
    const float* bs0 = Bbase + (long)bk * HW2;
    float4 b0 = *(const float4*)(bs0 + bn);
    float4 b1 = *(const float4*)(bs0 + bn + 64);
    As[0][akq+0][arow]=a0.x; As[0][akq+1][arow]=a0.y; As[0][akq+2][arow]=a0.z; As[0][akq+3][arow]=a0.w;
    As[0][akq+4][arow]=a1.x; As[0][akq+5][arow]=a1.y; As[0][akq+6][arow]=a1.z; As[0][akq+7][arow]=a1.w;
    *(float4*)&Bs[0][bk][bn]    = b0;
    *(float4*)&Bs[0][bk][bn+64] = b1;
    __syncthreads();
    int buf = 0;
    for (int k0 = 16; k0 <= K; k0 += 16) {
        if (k0 < K) {
            a0 = *(const float4*)(Ap + k0);
            a1 = *(const float4*)(Ap + k0 + 4);
            const float* bs2 = Bbase + (long)(k0 + bk) * HW2;
            b0 = *(const float4*)(bs2 + bn);
            b1 = *(const float4*)(bs2 + bn + 64);
        }
        #pragma unroll
        for (int kk = 0; kk < 16; kk++)
            fma_step(&As[buf][kk][0], &Bs[buf][kk][0], tx, ty, acc);
        if (k0 < K) {
            int nb = buf ^ 1;
            As[nb][akq+0][arow]=a0.x; As[nb][akq+1][arow]=a0.y; As[nb][akq+2][arow]=a0.z; As[nb][akq+3][arow]=a0.w;
            As[nb][akq+4][arow]=a1.x; As[nb][akq+5][arow]=a1.y; As[nb][akq+6][arow]=a1.z; As[nb][akq+7][arow]=a1.w;
            *(float4*)&Bs[nb][bk][bn]    = b0;
            *(float4*)&Bs[nb][bk][bn+64] = b1;
            __syncthreads();
            buf = nb;
        }
    }
}

// =============================================================================
// double-buffered TT GEMM body
// =============================================================================
__device__ __forceinline__ void gemm_db_tt2(
    const float* __restrict__ Abase, const float* __restrict__ Bbase, int K,
    float (* __restrict__ As)[16][132], float (* __restrict__ Bs)[16][132],
    int t, u64 acc[8][4])
{
    int row = t >> 1, kq = (t & 1) * 8;
    int tx = t & 15, ty = t >> 4;
    const float* Ap = Abase + (long)row * K + kq;
    const float* Bp = Bbase + (long)row * K + kq;

    float4 a0 = *(const float4*)(Ap);
    float4 a1 = *(const float4*)(Ap + 4);
    float4 b0 = *(const float4*)(Bp);
    float4 b1 = *(const float4*)(Bp + 4);
    As[0][kq+0][row]=a0.x; As[0][kq+1][row]=a0.y; As[0][kq+2][row]=a0.z; As[0][kq+3][row]=a0.w;
    As[0][kq+4][row]=a1.x; As[0][kq+5][row]=a1.y; As[0][kq+6][row]=a1.z; As[0][kq+7][row]=a1.w;
    Bs[0][kq+0][row]=b0.x; Bs[0][kq+1][row]=b0.y; Bs[0][kq+2][row]=b0.z; Bs[0][kq+3][row]=b0.w;
    Bs[0][kq+4][row]=b1.x; Bs[0][kq+5][row]=b1.y; Bs[0][kq+6][row]=b1.z; Bs[0][kq+7][row]=b1.w;
    __syncthreads();
    int buf = 0;
    for (int k0 = 16; k0 <= K; k0 += 16) {
        if (k0 < K) {
            a0 = *(const float4*)(Ap + k0);
            a1 = *(const float4*)(Ap + k0 + 4);
            b0 = *(const float4*)(Bp + k0);
            b1 = *(const float4*)(Bp + k0 + 4);
        }
        #pragma unroll
        for (int kk = 0; kk < 16; kk++)
            fma_step(&As[buf][kk][0], &Bs[buf][kk][0], tx, ty, acc);
        if (k0 < K) {
            int nb = buf ^ 1;
            As[nb][kq+0][row]=a0.x; As[nb][kq+1][row]=a0.y; As[nb][kq+2][row]=a0.z; As[nb][kq+3][row]=a0.w;
            As[nb][kq+4][row]=a1.x; As[nb][kq+5][row]=a1.y; As[nb][kq+6][row]=a1.z; As[nb][kq+7][row]=a1.w;
            Bs[nb][kq+0][row]=b0.x; Bs[nb][kq+1][row]=b0.y; Bs[nb][kq+2][row]=b0.z; Bs[nb][kq+3][row]=b0.w;
            Bs[nb][kq+4][row]=b1.x; Bs[nb][kq+5][row]=b1.y; Bs[nb][kq+6][row]=b1.z; Bs[nb][kq+7][row]=b1.w;
            __syncthreads();
            buf = nb;
        }
    }
}

__device__ __forceinline__ void gemm128_store2(
    float* __restrict__ Crow, const float* __restrict__ bias,
    int t, u64 acc[8][4], long ldc)
{
    int tx = t & 15, ty = t >> 4;
    #pragma unroll
    for (int i = 0; i < 8; i++) {
        int m = (i < 4) ? (ty*4 + i) : (64 + ty*4 + i - 4);
        float bv = bias ? bias[m] : 0.f;
        float2 p0 = unpk(acc[i][0]), p1 = unpk(acc[i][1]);
        float2 p2 = unpk(acc[i][2]), p3 = unpk(acc[i][3]);
        float4 o0 = {p0.x+bv, p0.y+bv, p1.x+bv, p1.y+bv};
        float4 o1 = {p2.x+bv, p2.y+bv, p3.x+bv, p3.y+bv};
        *(float4*)&Crow[(long)m*ldc + tx*4]      = o0;
        *(float4*)&Crow[(long)m*ldc + 64 + tx*4] = o1;
    }
}

// stage A
__global__ void __launch_bounds__(256,2) gemm_stageA(
    const float* __restrict__ x,
    const float* __restrict__ qk_w, const float* __restrict__ qk_b,
    const float* __restrict__ v_w,  const float* __restrict__ v_b)
{
    int n0 = blockIdx.x * 128, y = blockIdx.y, b = blockIdx.z;
    int t = threadIdx.x;
    __shared__ float As[2][16][132];
    __shared__ float Bs[2][16][128];
    u64 acc[8][4] = {};
    const float* A   = (y < 2) ? (qk_w + (long)y*128*128) : v_w;
    const float* bia = (y < 2) ? (qk_b + y*128)           : v_b;
    int cch          = (y < 2) ? (y*128)                  : 256;
    gemm_db_conv2(A, x + (long)b*128*HW2 + n0, 128, As, Bs, t, acc);
    gemm128_store2(g_buf1 + ((long)b*384 + cch) * HW2 + n0, bia, t, acc, HW2);
}

// stage C
__global__ void __launch_bounds__(256,2) gemm_stageC(
    const float* __restrict__ q2_w, const float* __restrict__ q2_b,
    const float* __restrict__ k2_w, const float* __restrict__ k2_b)
{
    int n0 = blockIdx.x * 128, y = blockIdx.y, b = blockIdx.z;
    int t = threadIdx.x;
    __shared__ float As[2][16][132];
    __shared__ float Bs[2][16][128];
    u64 acc[8][4] = {};
    const float* A   = (y < 2) ? (q2_w + (long)y*128*128) : (k2_w + (long)(y-2)*128*128);
    const float* bia = (y < 2) ? (q2_b + y*128)           : (k2_b + (y-2)*128);
    const float* Bbase = g_buf2 + ((long)b*384 + ((y < 2) ? 0 : 128)) * HW2 + n0;
    gemm_db_conv2(A, Bbase, 128, As, Bs, t, acc);
    gemm128_store2(g_buf3 + ((long)b*512 + y*128) * HW2 + n0, bia, t, acc, HW2);
}

// attention GEMM
__global__ void __launch_bounds__(256,2) attn_gemm2(
    const float* __restrict__ kc, const float* __restrict__ knew)
{
    int z = blockIdx.z; int b = z / NFtot, f = z % NFtot;
    const float* Qp = g_qtok + (long)b * Ntok * D2;
    const float* Kp = (f < 2) ? (kc   + ((long)(b*2 + f)) * Ntok * D2)
                              : (knew + ((long)(b*2 + 1)) * Ntok * D2);
    int m0 = blockIdx.y * 128, n0 = blockIdx.x * 128;
    int t = threadIdx.x;
    int tx = t & 15, ty = t >> 4;
    __shared__ float As[2][16][132];
    __shared__ float Bs[2][16][132];
    u64 acc[8][4] = {};
    gemm_db_tt2(Qp + (long)m0 * D2, Kp + (long)n0 * D2, D2, As, Bs, t, acc);
    float* Cp = g_attn + (long)z * Ntok * Ntok;
    #pragma unroll
    for (int i = 0; i < 8; i++) {
        int m = (i < 4) ? (ty*4 + i) : (64 + ty*4 + i - 4);
        float2 p0 = unpk(acc[i][0]), p1 = unpk(acc[i][1]);
        float2 p2 = unpk(acc[i][2]), p3 = unpk(acc[i][3]);
        float4 o0 = {p0.x, p0.y, p1.x, p1.y};
        float4 o1 = {p2.x, p2.y, p3.x, p3.y};
        *(float4*)&Cp[(long)(m0+m)*Ntok + n0 + tx*4]      = o0;
        *(float4*)&Cp[(long)(m0+m)*Ntok + n0 + 64 + tx*4] = o1;
    }
}

// proj 1x1 GEMM with fused window de-permute gather
__global__ void __launch_bounds__(256,2) proj_gemm2(
    const float* __restrict__ W, const float* __restrict__ bias,
    float* __restrict__ Out)
{
    int z  = blockIdx.z;
    int n0 = blockIdx.x * 128;
    int t = threadIdx.x;
    int tx = t & 15, ty = t >> 4;
    __shared__ float As[2][16][132];
    __shared__ float Bs[2][16][132];
    u64 acc[8][4] = {};
    int row = t >> 1;
    int p = n0 + row;
    int h = p / HWd, w = p % HWd;
    int token = (h % HGd) * HGd + (w % HGd);
    int vbase = ((h / HGd) * 4 + (w / HGd)) * 128;
    {
        int kq = (t & 1) * 8;
        const float* Ap = W + (long)row * 128 + kq;
        const float* Bp = g_otok + ((long)z * Ntok + token) * VDdim + vbase + kq;
        float4 a0 = *(const float4*)(Ap);
        float4 a1 = *(const float4*)(Ap + 4);
        float4 b0 = *(const float4*)(Bp);
        float4 b1 = *(const float4*)(Bp + 4);
        As[0][kq+0][row]=a0.x; As[0][kq+1][row]=a0.y; As[0][kq+2][row]=a0.z; As[0][kq+3][row]=a0.w;
        As[0][kq+4][row]=a1.x; As[0][kq+5][row]=a1.y; As[0][kq+6][row]=a1.z; As[0][kq+7][row]=a1.w;
        Bs[0][kq+0][row]=b0.x; Bs[0][kq+1][row]=b0.y; Bs[0][kq+2][row]=b0.z; Bs[0][kq+3][row]=b0.w;
        Bs[0][kq+4][row]=b1.x; Bs[0][kq+5][row]=b1.y; Bs[0][kq+6][row]=b1.z; Bs[0][kq+7][row]=b1.w;
        __syncthreads();
        int buf = 0;
        for (int k0 = 16; k0 <= 128; k0 += 16) {
            if (k0 < 128) {
                a0 = *(const float4*)(Ap + k0);
                a1 = *(const float4*)(Ap + k0 + 4);
                b0 = *(const float4*)(Bp + k0);
                b1 = *(const float4*)(Bp + k0 + 4);
            }
            #pragma unroll
            for (int kk = 0; kk < 16; kk++)
                fma_step(&As[buf][kk][0], &Bs[buf][kk][0], tx, ty, acc);
            if (k0 < 128) {
                int nb = buf ^ 1;
                As[nb][kq+0][row]=a0.x; As[nb][kq+1][row]=a0.y; As[nb][kq+2][row]=a0.z; As[nb][kq+3][row]=a0.w;
                As[nb][kq+4][row]=a1.x; As[nb][kq+5][row]=a1.y; As[nb][kq+6][row]=a1.z; As[nb][kq+7][row]=a1.w;
                Bs[nb][kq+0][row]=b0.x; Bs[nb][kq+1][row]=b0.y; Bs[nb][kq+2][row]=b0.z; Bs[nb][kq+3][row]=b0.w;
                Bs[nb][kq+4][row]=b1.x; Bs[nb][kq+5][row]=b1.y; Bs[nb][kq+6][row]=b1.z; Bs[nb][kq+7][row]=b1.w;
                __syncthreads();
                buf = nb;
            }
        }
    }
    #pragma unroll
    for (int i = 0; i < 8; i++) {
        int m = (i < 4) ? (ty*4 + i) : (64 + ty*4 + i - 4);
        float bv = bias[m];
        float2 p0 = unpk(acc[i][0]), p1 = unpk(acc[i][1]);
        float2 p2 = unpk(acc[i][2]), p3 = unpk(acc[i][3]);
        float4 o0 = {p0.x+bv, p0.y+bv, p1.x+bv, p1.y+bv};
        float4 o1 = {p2.x+bv, p2.y+bv, p3.x+bv, p3.y+bv};
        *(float4*)&Out[((long)z*128 + m)*HW2 + n0 + tx*4]      = o0;
        *(float4*)&Out[((long)z*128 + m)*HW2 + n0 + 64 + tx*4] = o1;
    }
}

// ---------------- depthwise 3x3 pad1, 4 pixels/thread -------------------------
__global__ void __launch_bounds__(256) dw3x3v(
    const float* __restrict__ qk_dw_w, const float* __restrict__ qk_dw_b,
    const float* __restrict__ v_dw_w,  const float* __restrict__ v_dw_b)
{
    int idx = blockIdx.x * 256 + threadIdx.x;
    const int NQ = BATCH*384*HW2/4;
    if (idx >= NQ) return;
    int qw = idx % (HWd/4);
    int h  = (idx / (HWd/4)) % HWd;
    int ch = (idx / (HW2/4)) % 384;
    int b  = idx / (384*HW2/4);
    int w0 = qw * 4;

    const float* wgt; float bv;
    if (ch < 256) { wgt = qk_dw_w + ch*9;        bv = qk_dw_b[ch]; }
    else          { wgt = v_dw_w  + (ch-256)*9;  bv = v_dw_b[ch-256]; }
    float k0=wgt[0],k1=wgt[1],k2=wgt[2],k3=wgt[3],k4=wgt[4],k5=wgt[5],k6=wgt[6],k7=wgt[7],k8=wgt[8];

    const float* in = g_buf1 + ((long)(b*384 + ch)) * HW2;
    float r[3][6];
    #pragma unroll
    for (int ky = 0; ky < 3; ky++) {
        int y = h + ky - 1;
        if ((unsigned)y >= (unsigned)HWd) {
            #pragma unroll
            for (int j = 0; j < 6; j++) r[ky][j] = 0.f;
        } else {
            const float* rp = in + (long)y * HWd + w0;
            float4 c = *(const float4*)rp;
            r[ky][1] = c.x; r[ky][2] = c.y; r[ky][3] = c.z; r[ky][4] = c.w;
            r[ky][0] = (w0 > 0)        ? rp[-1] : 0.f;
            r[ky][5] = (w0 + 4 < HWd)  ? rp[4]  : 0.f;
        }
    }
    float4 o;
    float* op = (float*)&o;
    #pragma unroll
    for (int j = 0; j < 4; j++) {
        op[j] = bv
              + k0*r[0][j] + k1*r[0][j+1] + k2*r[0][j+2]
              + k3*r[1][j] + k4*r[1][j+1] + k5*r[1][j+2]
              + k6*r[2][j] + k7*r[2][j+1] + k8*r[2][j+2];
    }
    *(float4*)&g_buf2[(long)idx*4] = o;
}

// ---------------- depthwise 4x4 stride4 pad1 ----------------------------------
__global__ void dw4x4(const float* __restrict__ q2_dw_w, const float* __restrict__ q2_dw_b,
                      const float* __restrict__ k2_dw_w, const float* __restrict__ k2_dw_b)
{
    int idx = blockIdx.x * 256 + threadIdx.x;
    if (idx >= BATCH*512*Ntok) return;
    int t  = idx % Ntok;
    int ch = (idx / Ntok) % 512;
    int b  = idx / (512*Ntok);
    int oy = t / HGd, ox = t % HGd;
    const float* wgt; float bv;
    if (ch < 256) { wgt = q2_dw_w + ch*16;       bv = q2_dw_b[ch]; }
    else          { wgt = k2_dw_w + (ch-256)*16; bv = k2_dw_b[ch-256]; }
    const float* in = g_buf3 + ((long)(b*512 + ch)) * HW2;
    float s = bv;
    #pragma unroll
    for (int ky = 0; ky < 4; ky++) {
        int y = oy*4 - 1 + ky;
        if ((unsigned)y >= (unsigned)HWd) continue;
        #pragma unroll
        for (int kx = 0; kx < 4; kx++) {
            int x = ox*4 - 1 + kx;
            if ((unsigned)x >= (unsigned)HWd) continue;
            s += wgt[ky*4+kx] * in[y*HWd + x];
        }
    }
    g_buf4[idx] = s;
}

// ---------------- l2 normalize + token-major q/k (shfl reductions) ------------
__global__ void __launch_bounds__(256) norm_qk(float* __restrict__ kout,
                                               const float* __restrict__ temp)
{
    int token = blockIdx.x, b = blockIdx.y, d = threadIdx.x;
    int lane = d & 31, wid = d >> 5;
    float qv = g_buf4[((long)b*512 + d)       * Ntok + token];
    float kv = g_buf4[((long)b*512 + 256 + d) * Ntok + token];
    __shared__ float wsumq[8], wsumk[8];
    __shared__ float qinv_s, kinv_s;
    float sq = qv*qv, sk = kv*kv;
    #pragma unroll
    for (int o = 16; o > 0; o >>= 1) {
        sq += __shfl_xor_sync(0xffffffffu, sq, o);
        sk += __shfl_xor_sync(0xffffffffu, sk, o);
    }
    if (lane == 0) { wsumq[wid] = sq; wsumk[wid] = sk; }
    __syncthreads();
    if (d < 32) {
        float tq = (lane < 8) ? wsumq[lane] : 0.f;
        float tk = (lane < 8) ? wsumk[lane] : 0.f;
        #pragma unroll
        for (int o = 4; o > 0; o >>= 1) {
            tq += __shfl_xor_sync(0xffffffffu, tq, o);
            tk += __shfl_xor_sync(0xffffffffu, tk, o);
        }
        if (lane == 0) {
            qinv_s = (*temp) / fmaxf(sqrtf(tq), 1e-12f);
            kinv_s = 1.f / fmaxf(sqrtf(tk), 1e-12f);
        }
    }
    __syncthreads();
    g_qtok[((long)b*Ntok + token) * D2 + d] = qv * qinv_s;
    kout  [((long)(b*2 + 1)*Ntok + token) * D2 + d] = kv * kinv_s;
}

// ---------------- build v_new -------------------------------------------------
__global__ void build_vnew(float* __restrict__ vout)
{
    int idx = blockIdx.x * 256 + threadIdx.x;
    if (idx >= BATCH*Ntok*VDdim) return;
    int vd    = idx % VDdim;
    int token = (idx / VDdim) % Ntok;
    int b     = idx / (Ntok*VDdim);
    int c  = vd & 127;
    int p2 = (vd >> 7) & 3;
    int p1 = vd >> 9;
    int hi = token / HGd, wi = token % HGd;
    float val = g_buf2[((long)(b*384 + 256 + c)) * HW2 + (p1*HGd + hi) * HWd + (p2*HGd + wi)];
    vout[((long)(b*2 + 1)*Ntok + token) * VDdim + vd] = val;
}

// =============================================================================
// sparse_select (per row): top-k + local mask + softmax -> normalized lists
// grid (Ntok, NFtot, BATCH), block 256
// =============================================================================
__global__ void __launch_bounds__(256) sparse_select()
{
    int n = blockIdx.x, f = blockIdx.y, b = blockIdx.z;
    int z = b*NFtot + f;
    int rowid = z * Ntok + n;
    const float* arow = g_attn + (long)rowid * Ntok;
    int tid = threadIdx.x;

    __shared__ float rowbuf[Ntok];
    __shared__ float cand[256*5];
    __shared__ float bcast;
    __shared__ int   nnz;
    __shared__ int   sidx[SELCAP];
    __shared__ float sval[SELCAP];

    for (int m = tid*4; m < Ntok; m += 1024)
        *(float4*)&rowbuf[m] = *(const float4*)&arow[m];
    if (tid == 0) nnz = 0;
    __syncthreads();

    // per-thread top-5
    float t5[5] = {-INFINITY,-INFINITY,-INFINITY,-INFINITY,-INFINITY};
    for (int m = tid; m < Ntok; m += 256) {
        float v = rowbuf[m];
        if (v > t5[4]) {
            t5[4] = v;
            #pragma unroll
            for (int i = 4; i > 0; i--)
                if (t5[i] > t5[i-1]) { float tmp = t5[i-1]; t5[i-1] = t5[i]; t5[i] = tmp; }
        }
    }
    #pragma unroll
    for (int i = 0; i < 5; i++) cand[tid*5 + i] = t5[i];
    __syncthreads();

    // warp 0 merges 1280 candidates -> kth largest
    if (tid < 32) {
        float l5[5] = {-INFINITY,-INFINITY,-INFINITY,-INFINITY,-INFINITY};
        const float* cp = cand + tid*40;
        #pragma unroll
        for (int i = 0; i < 40; i++) {
            float v = cp[i];
            if (v > l5[4]) {
                l5[4] = v;
                #pragma unroll
                for (int j = 4; j > 0; j--)
                    if (l5[j] > l5[j-1]) { float tmp = l5[j-1]; l5[j-1] = l5[j]; l5[j] = tmp; }
            }
        }
        float thr = INFINITY;
        #pragma unroll
        for (int r = 0; r < 5; r++) {
            float lm = -INFINITY;
            #pragma unroll
            for (int i = 0; i < 5; i++) {
                float v = l5[i];
                if (v < thr && v > lm) lm = v;
            }
            #pragma unroll
            for (int o = 16; o > 0; o >>= 1)
                lm = fmaxf(lm, __shfl_xor_sync(0xffffffffu, lm, o));
            thr = lm;
        }
        if (tid == 0) bcast = thr;
    }
    __syncthreads();
    float kth = bcast;

    // collect nonzero entries
    int ny = n / HGd, nx = n % HGd;
    for (int m = tid; m < Ntok; m += 256) {
        float a = rowbuf[m];
        float coef = (a >= kth) ? 1.f : 0.f;
        int my = m / HGd, mx = m % HGd;
        if (abs(ny - my) + abs(nx - mx) <= 4) coef += 1.f;
        float v = a * coef;
        if (v != 0.f) {
            int pos = atomicAdd(&nnz, 1);
            if (pos < SELCAP) { sidx[pos] = m; sval[pos] = v; }
        }
    }
    __syncthreads();
    int cnt = min(nnz, SELCAP);

    // softmax via warp 0
    if (tid < 32) {
        float mx = -INFINITY;
        for (int e = tid; e < cnt; e += 32) mx = fmaxf(mx, sval[e]);
        #pragma unroll
        for (int o = 16; o > 0; o >>= 1)
            mx = fmaxf(mx, __shfl_xor_sync(0xffffffffu, mx, o));
        if (tid == 0) bcast = mx;
    }
    __syncthreads();
    float mxv = bcast;
    if (tid < cnt) sval[tid] = expf(sval[tid] - mxv);
    __syncthreads();
    if (tid < 32) {
        float s = 0.f;
        for (int e = tid; e < cnt; e += 32) s += sval[e];
        #pragma unroll
        for (int o = 16; o > 0; o >>= 1)
            s += __shfl_xor_sync(0xffffffffu, s, o);
        if (tid == 0) bcast = s;
    }
    __syncthreads();
    if (tid < cnt) {
        g_selidx[(long)rowid*SELCAP + tid] = sidx[tid];
        g_selw  [(long)rowid*SELCAP + tid] = sval[tid] / bcast;
    }
    if (tid == 0) g_selcnt[rowid] = cnt;
}

// =============================================================================
// sparse_av8: 2x4 query tile (8 queries), union gather with rank-indexed
// weight table. grid (2 dchunks, 288 tiles, 6 z), block 256, 4 dims/thread.
// Union bound: dilated 2x4 rect (<=80) + 8*5 topk = 120 <= MAXU=128 (exact).
// =============================================================================
__global__ void __launch_bounds__(256) sparse_av8(
    const float* __restrict__ v_cached, const float* __restrict__ vout)
{
    int chunk = blockIdx.x;              // 0..1 (1024 dims each)
    int tile  = blockIdx.y;              // 0..287
    int z     = blockIdx.z;              // b*3+f
    int b = z / NFtot, f = z % NFtot;
    int qy0 = (tile / 12) * 2, qx0 = (tile % 12) * 4;
    int tid = threadIdx.x;

    __shared__ int   sidx[8][SELCAP];
    __shared__ float sval[8][SELCAP];
    __shared__ int   scnt[8];
    __shared__ unsigned umask[72];
    __shared__ int   ubase[73];
    __shared__ int   uidx[MAXU];
    __shared__ float Wt[8][MAXU];

    if (tid < 72) umask[tid] = 0;
    int rowbase = z * Ntok;
    if (tid < 8) {
        int q = tid;
        int n = (qy0 + (q >> 2)) * HGd + qx0 + (q & 3);
        scnt[q] = g_selcnt[rowbase + n];
    }
    __syncthreads();
    // load lists
    for (int i = tid; i < 8 * SELCAP; i += 256) {
        int q = i >> 6, e = i & (SELCAP-1);
        if (e < scnt[q]) {
            int n = (qy0 + (q >> 2)) * HGd + qx0 + (q & 3);
            long base = (long)(rowbase + n) * SELCAP + e;
            int m = g_selidx[base];
            sidx[q][e] = m;
            sval[q][e] = g_selw[base];
            atomicOr(&umask[m >> 5], 1u << (m & 31));
        }
    }
    __syncthreads();
    if (tid == 0) {
        int s = 0;
        for (int w = 0; w < 72; w++) { ubase[w] = s; s += __popc(umask[w]); }
        ubase[72] = s;
    }
    __syncthreads();
    int U = min(ubase[72], MAXU);

    for (int i = tid; i < 8*MAXU; i += 256) ((float*)Wt)[i] = 0.f;
    __syncthreads();
    if (tid < 72) {
        unsigned bits = umask[tid];
        int pos = ubase[tid];
        while (bits) {
            int bit = __ffs(bits) - 1; bits &= bits - 1;
            if (pos < MAXU) uidx[pos] = tid*32 + bit;
            pos++;
        }
    }
    __syncthreads();
    for (int i = tid; i < 8*SELCAP; i += 256) {
        int q = i >> 6, e = i & (SELCAP-1);
        if (e < scnt[q]) {
            int m = sidx[q][e];
            int w32 = m >> 5, bit = m & 31;
            int rank = ubase[w32] + __popc(umask[w32] & ((1u << bit) - 1u));
            if (rank < MAXU) Wt[q][rank] = sval[q][e];
        }
    }
    __syncthreads();

    const float* vbase = (f < 2) ? (v_cached + ((long)(b*2 + f)) * Ntok * VDdim)
                                 : (vout     + ((long)(b*2 + 1)) * Ntok * VDdim);
    int d0 = chunk * 1024 + tid * 4;
    u64 acc[8][2] = {};
    for (int e = 0; e < U; e++) {
        int m = uidx[e];
        ulonglong2 vv = *(const ulonglong2*)(vbase + (long)m * VDdim + d0);
        #pragma unroll
        for (int q = 0; q < 8; q++) {
            u64 wq = dup2(Wt[q][e]);
            fma2(acc[q][0], wq, vv.x);
            fma2(acc[q][1], wq, vv.y);
        }
    }
    #pragma unroll
    for (int q = 0; q < 8; q++) {
        int n = (qy0 + (q >> 2)) * HGd + qx0 + (q & 3);
        float2 p0 = unpk(acc[q][0]), p1 = unpk(acc[q][1]);
        float* orow = g_otok + ((long)(rowbase + n)) * VDdim + d0;
        *(float4*)orow = make_float4(p0.x, p0.y, p1.x, p1.y);
    }
}

// ---------------------------------- launch -----------------------------------
extern "C" void kernel_launch(void* const* d_in, const int* in_sizes, int n_in,
                              void* d_out, int out_size)
{
    (void)in_sizes; (void)n_in; (void)out_size;
    const float* x         = (const float*)d_in[0];
    const float* k_cached  = (const float*)d_in[1];
    const float* v_cached  = (const float*)d_in[2];
    const float* temperature = (const float*)d_in[3];
    const float* qk_w  = (const float*)d_in[4],  *qk_b  = (const float*)d_in[5];
    const float* qk_dw_w = (const float*)d_in[6], *qk_dw_b = (const float*)d_in[7];
    const float* v_w   = (const float*)d_in[8],  *v_b   = (const float*)d_in[9];
    const float* v_dw_w = (const float*)d_in[10], *v_dw_b = (const float*)d_in[11];
    const float* k2_w  = (const float*)d_in[12], *k2_b  = (const float*)d_in[13];
    const float* k2_dw_w = (const float*)d_in[14], *k2_dw_b = (const float*)d_in[15];
    const float* q2_w  = (const float*)d_in[16], *q2_b  = (const float*)d_in[17];
    const float* q2_dw_w = (const float*)d_in[18], *q2_dw_b = (const float*)d_in[19];
    const float* proj_w = (const float*)d_in[20], *proj_b = (const float*)d_in[21];

    float* out = (float*)d_out;
    const long OUT_K = (long)BATCH * NFtot * 128 * HW2;
    const long OUT_V = OUT_K + (long)BATCH * 2 * Ntok * D2;
    float* kout = out + OUT_K;
    float* vout = out + OUT_V;

    dim3 blk(256);

    gemm_stageA<<<dim3(288,3,BATCH), blk>>>(x, qk_w, qk_b, v_w, v_b);
    dw3x3v<<<(BATCH*384*HW2/4 + 255)/256, blk>>>(qk_dw_w, qk_dw_b, v_dw_w, v_dw_b);
    gemm_stageC<<<dim3(288,4,BATCH), blk>>>(q2_w, q2_b, k2_w, k2_b);
    dw4x4<<<(BATCH*512*Ntok + 255)/256, blk>>>(q2_dw_w, q2_dw_b, k2_dw_w, k2_dw_b);
    norm_qk<<<dim3(Ntok, BATCH), blk>>>(kout, temperature);
    build_vnew<<<(BATCH*Ntok*VDdim + 255)/256, blk>>>(vout);
    for (int b = 0; b < BATCH; b++) {
        cudaMemcpyAsync(kout + (long)(b*2)*Ntok*D2,
                        k_cached + (long)(b*2+1)*Ntok*D2,
                        (size_t)Ntok*D2*sizeof(float), cudaMemcpyDeviceToDevice, 0);
        cudaMemcpyAsync(vout + (long)(b*2)*Ntok*VDdim,
                        v_cached + (long)(b*2+1)*Ntok*VDdim,
                        (size_t)Ntok*VDdim*sizeof(float), cudaMemcpyDeviceToDevice, 0);
    }
    attn_gemm2<<<dim3(18,18,BATCH*NFtot), blk>>>(k_cached, kout);
    sparse_select<<<dim3(Ntok, NFtot, BATCH), blk>>>();
    sparse_av8<<<dim3(2, 288, BATCH*NFtot), blk>>>(v_cached, vout);
    proj_gemm2<<<dim3(288,1,BATCH*NFtot), blk>>>(proj_w, proj_b, out);
}

// round 14
// speedup vs baseline: 1.5516x; 1.0201x over previous
#include <cuda_runtime.h>
#include <math.h>

#define BATCH 2
#define HWd   192
#define HW2   (HWd*HWd)      // 36864
#define HGd   48
#define Ntok  (HGd*HGd)      // 2304
#define D2    256
#define VDdim 2048
#define NFtot 3
#define SELCAP 64
#define MAXU   128
#define NROWS (BATCH*NFtot*Ntok)

typedef unsigned long long u64;

// ---------------- scratch (device globals; no allocs allowed) ----------------
__device__ float g_buf1[(size_t)BATCH*384*HW2];
__device__ float g_buf2[(size_t)BATCH*384*HW2];
__device__ float g_buf3[(size_t)BATCH*512*HW2];
__device__ float g_buf4[(size_t)BATCH*512*Ntok];
__device__ float g_qtok[(size_t)BATCH*Ntok*D2];
__device__ float g_attn[(size_t)BATCH*NFtot*Ntok*Ntok];
__device__ float g_otok[(size_t)BATCH*NFtot*Ntok*VDdim];
__device__ int   g_selidx[(size_t)NROWS*SELCAP];
__device__ float g_selw  [(size_t)NROWS*SELCAP];
__device__ int   g_selcnt[NROWS];

// ---------------- packed fp32x2 primitives (Blackwell FFMA2) -----------------
__device__ __forceinline__ u64 dup2(float x) {
    u64 r;
    asm("mov.b64 %0, {%1, %1};" : "=l"(r) : "r"(__float_as_uint(x)));
    return r;
}
__device__ __forceinline__ void fma2(u64 &d, u64 a, u64 b) {
    asm("fma.rn.f32x2 %0, %1, %2, %3;" : "=l"(d) : "l"(a), "l"(b), "l"(d));
}
__device__ __forceinline__ float2 unpk(u64 v) {
    float lo, hi;
    asm("mov.b64 {%0, %1}, %2;" : "=f"(lo), "=f"(hi) : "l"(v));
    return make_float2(lo, hi);
}

// one k-step of the 8x8 fragment: 32 fma.f32x2
__device__ __forceinline__ void fma_step(
    const float* __restrict__ As_k, const float* __restrict__ Bs_k,
    int tx, int ty, u64 acc[8][4])
{
    float4 av0 = *(const float4*)(As_k + ty*4);
    float4 av1 = *(const float4*)(As_k + 64 + ty*4);
    ulonglong2 bv0 = *(const ulonglong2*)(Bs_k + tx*4);
    ulonglong2 bv1 = *(const ulonglong2*)(Bs_k + 64 + tx*4);
    u64 aa[8] = {dup2(av0.x), dup2(av0.y), dup2(av0.z), dup2(av0.w),
                 dup2(av1.x), dup2(av1.y), dup2(av1.z), dup2(av1.w)};
    u64 bb[4] = {bv0.x, bv0.y, bv1.x, bv1.y};
    #pragma unroll
    for (int i = 0; i < 8; i++) {
        fma2(acc[i][0], aa[i], bb[0]);
        fma2(acc[i][1], aa[i], bb[1]);
        fma2(acc[i][2], aa[i], bb[2]);
        fma2(acc[i][3], aa[i], bb[3]);
    }
}

// =============================================================================
// double-buffered conv GEMM body
// =============================================================================
__device__ __forceinline__ void gemm_db_conv2(
    const float* __restrict__ A, const float* __restrict__ Bbase, int K,
    float (* __restrict__ As)[16][132], float (* __restrict__ Bs)[16][128],
    int t, u64 acc[8][4])
{
    int arow = t >> 1, akq = (t & 1) * 8;
    int bk = t >> 4, bn = (t & 15) * 4;
    int tx = t & 15, ty = t >> 4;
    const float* Ap = A + (long)arow * K + akq;

    float4 a0 = *(const float4*)(Ap);
    float4 a1 = *(const float4*)(Ap + 4);
    const float* bs0 = Bbase + (long)bk * HW2;
    float4 b0 = *(const float4*)(bs0 + bn);
    float4 b1 = *(const float4*)(bs0 + bn + 64);
    As[0][akq+0][arow]=a0.x; As[0][akq+1][arow]=a0.y; As[0][akq+2][arow]=a0.z; As[0][akq+3][arow]=a0.w;
    As[0][akq+4][arow]=a1.x; As[0][akq+5][arow]=a1.y; As[0][akq+6][arow]=a1.z; As[0][akq+7][arow]=a1.w;
    *(float4*)&Bs[0][bk][bn]    = b0;
    *(float4*)&Bs[0][bk][bn+64] = b1;
    __syncthreads();
    int buf = 0;
    for (int k0 = 16; k0 <= K; k0 += 16) {
        if (k0 < K) {
            a0 = *(const float4*)(Ap + k0);
            a1 = *(const float4*)(Ap + k0 + 4);
            const float* bs2 = Bbase + (long)(k0 + bk) * HW2;
            b0 = *(const float4*)(bs2 + bn);
            b1 = *(const float4*)(bs2 + bn + 64);
        }
        #pragma unroll
        for (int kk = 0; kk < 16; kk++)
            fma_step(&As[buf][kk][0], &Bs[buf][kk][0], tx, ty, acc);
        if (k0 < K) {
            int nb = buf ^ 1;
            As[nb][akq+0][arow]=a0.x; As[nb][akq+1][arow]=a0.y; As[nb][akq+2][arow]=a0.z; As[nb][akq+3][arow]=a0.w;
            As[nb][akq+4][arow]=a1.x; As[nb][akq+5][arow]=a1.y; As[nb][akq+6][arow]=a1.z; As[nb][akq+7][arow]=a1.w;
            *(float4*)&Bs[nb][bk][bn]    = b0;
            *(float4*)&Bs[nb][bk][bn+64] = b1;
            __syncthreads();
            buf = nb;
        }
    }
}

// =============================================================================
// double-buffered TT GEMM body
// =============================================================================
__device__ __forceinline__ void gemm_db_tt2(
    const float* __restrict__ Abase, const float* __restrict__ Bbase, int K,
    float (* __restrict__ As)[16][132], float (* __restrict__ Bs)[16][132],
    int t, u64 acc[8][4])
{
    int row = t >> 1, kq = (t & 1) * 8;
    int tx = t & 15, ty = t >> 4;
    const float* Ap = Abase + (long)row * K + kq;
    const float* Bp = Bbase + (long)row * K + kq;

    float4 a0 = *(const float4*)(Ap);
    float4 a1 = *(const float4*)(Ap + 4);
    float4 b0 = *(const float4*)(Bp);
    float4 b1 = *(const float4*)(Bp + 4);
    As[0][kq+0][row]=a0.x; As[0][kq+1][row]=a0.y; As[0][kq+2][row]=a0.z; As[0][kq+3][row]=a0.w;
    As[0][kq+4][row]=a1.x; As[0][kq+5][row]=a1.y; As[0][kq+6][row]=a1.z; As[0][kq+7][row]=a1.w;
    Bs[0][kq+0][row]=b0.x; Bs[0][kq+1][row]=b0.y; Bs[0][kq+2][row]=b0.z; Bs[0][kq+3][row]=b0.w;
    Bs[0][kq+4][row]=b1.x; Bs[0][kq+5][row]=b1.y; Bs[0][kq+6][row]=b1.z; Bs[0][kq+7][row]=b1.w;
    __syncthreads();
    int buf = 0;
    for (int k0 = 16; k0 <= K; k0 += 16) {
        if (k0 < K) {
            a0 = *(const float4*)(Ap + k0);
            a1 = *(const float4*)(Ap + k0 + 4);
            b0 = *(const float4*)(Bp + k0);
            b1 = *(const float4*)(Bp + k0 + 4);
        }
        #pragma unroll
        for (int kk = 0; kk < 16; kk++)
            fma_step(&As[buf][kk][0], &Bs[buf][kk][0], tx, ty, acc);
        if (k0 < K) {
            int nb = buf ^ 1;
            As[nb][kq+0][row]=a0.x; As[nb][kq+1][row]=a0.y; As[nb][kq+2][row]=a0.z; As[nb][kq+3][row]=a0.w;
            As[nb][kq+4][row]=a1.x; As[nb][kq+5][row]=a1.y; As[nb][kq+6][row]=a1.z; As[nb][kq+7][row]=a1.w;
            Bs[nb][kq+0][row]=b0.x; Bs[nb][kq+1][row]=b0.y; Bs[nb][kq+2][row]=b0.z; Bs[nb][kq+3][row]=b0.w;
            Bs[nb][kq+4][row]=b1.x; Bs[nb][kq+5][row]=b1.y; Bs[nb][kq+6][row]=b1.z; Bs[nb][kq+7][row]=b1.w;
            __syncthreads();
            buf = nb;
        }
    }
}

__device__ __forceinline__ void gemm128_store2(
    float* __restrict__ Crow, const float* __restrict__ bias,
    int t, u64 acc[8][4], long ldc)
{
    int tx = t & 15, ty = t >> 4;
    #pragma unroll
    for (int i = 0; i < 8; i++) {
        int m = (i < 4) ? (ty*4 + i) : (64 + ty*4 + i - 4);
        float bv = bias ? bias[m] : 0.f;
        float2 p0 = unpk(acc[i][0]), p1 = unpk(acc[i][1]);
        float2 p2 = unpk(acc[i][2]), p3 = unpk(acc[i][3]);
        float4 o0 = {p0.x+bv, p0.y+bv, p1.x+bv, p1.y+bv};
        float4 o1 = {p2.x+bv, p2.y+bv, p3.x+bv, p3.y+bv};
        *(float4*)&Crow[(long)m*ldc + tx*4]      = o0;
        *(float4*)&Crow[(long)m*ldc + 64 + tx*4] = o1;
    }
}

// stage A
__global__ void __launch_bounds__(256,2) gemm_stageA(
    const float* __restrict__ x,
    const float* __restrict__ qk_w, const float* __restrict__ qk_b,
    const float* __restrict__ v_w,  const float* __restrict__ v_b)
{
    int n0 = blockIdx.x * 128, y = blockIdx.y, b = blockIdx.z;
    int t = threadIdx.x;
    __shared__ float As[2][16][132];
    __shared__ float Bs[2][16][128];
    u64 acc[8][4] = {};
    const float* A   = (y < 2) ? (qk_w + (long)y*128*128) : v_w;
    const float* bia = (y < 2) ? (qk_b + y*128)           : v_b;
    int cch          = (y < 2) ? (y*128)                  : 256;
    gemm_db_conv2(A, x + (long)b*128*HW2 + n0, 128, As, Bs, t, acc);
    gemm128_store2(g_buf1 + ((long)b*384 + cch) * HW2 + n0, bia, t, acc, HW2);
}

// stage C
__global__ void __launch_bounds__(256,2) gemm_stageC(
    const float* __restrict__ q2_w, const float* __restrict__ q2_b,
    const float* __restrict__ k2_w, const float* __restrict__ k2_b)
{
    int n0 = blockIdx.x * 128, y = blockIdx.y, b = blockIdx.z;
    int t = threadIdx.x;
    __shared__ float As[2][16][132];
    __shared__ float Bs[2][16][128];
    u64 acc[8][4] = {};
    const float* A   = (y < 2) ? (q2_w + (long)y*128*128) : (k2_w + (long)(y-2)*128*128);
    const float* bia = (y < 2) ? (q2_b + y*128)           : (k2_b + (y-2)*128);
    const float* Bbase = g_buf2 + ((long)b*384 + ((y < 2) ? 0 : 128)) * HW2 + n0;
    gemm_db_conv2(A, Bbase, 128, As, Bs, t, acc);
    gemm128_store2(g_buf3 + ((long)b*512 + y*128) * HW2 + n0, bia, t, acc, HW2);
}

// attention GEMM
__global__ void __launch_bounds__(256,2) attn_gemm2(
    const float* __restrict__ kc, const float* __restrict__ knew)
{
    int z = blockIdx.z; int b = z / NFtot, f = z % NFtot;
    const float* Qp = g_qtok + (long)b * Ntok * D2;
    const float* Kp = (f < 2) ? (kc   + ((long)(b*2 + f)) * Ntok * D2)
                              : (knew + ((long)(b*2 + 1)) * Ntok * D2);
    int m0 = blockIdx.y * 128, n0 = blockIdx.x * 128;
    int t = threadIdx.x;
    int tx = t & 15, ty = t >> 4;
    __shared__ float As[2][16][132];
    __shared__ float Bs[2][16][132];
    u64 acc[8][4] = {};
    gemm_db_tt2(Qp + (long)m0 * D2, Kp + (long)n0 * D2, D2, As, Bs, t, acc);
    float* Cp = g_attn + (long)z * Ntok * Ntok;
    #pragma unroll
    for (int i = 0; i < 8; i++) {
        int m = (i < 4) ? (ty*4 + i) : (64 + ty*4 + i - 4);
        float2 p0 = unpk(acc[i][0]), p1 = unpk(acc[i][1]);
        float2 p2 = unpk(acc[i][2]), p3 = unpk(acc[i][3]);
        float4 o0 = {p0.x, p0.y, p1.x, p1.y};
        float4 o1 = {p2.x, p2.y, p3.x, p3.y};
        *(float4*)&Cp[(long)(m0+m)*Ntok + n0 + tx*4]      = o0;
        *(float4*)&Cp[(long)(m0+m)*Ntok + n0 + 64 + tx*4] = o1;
    }
}

// proj 1x1 GEMM with fused window de-permute gather
__global__ void __launch_bounds__(256,2) proj_gemm2(
    const float* __restrict__ W, const float* __restrict__ bias,
    float* __restrict__ Out)
{
    int z  = blockIdx.z;
    int n0 = blockIdx.x * 128;
    int t = threadIdx.x;
    int tx = t & 15, ty = t >> 4;
    __shared__ float As[2][16][132];
    __shared__ float Bs[2][16][132];
    u64 acc[8][4] = {};
    int row = t >> 1;
    int p = n0 + row;
    int h = p / HWd, w = p % HWd;
    int token = (h % HGd) * HGd + (w % HGd);
    int vbase = ((h / HGd) * 4 + (w / HGd)) * 128;
    {
        int kq = (t & 1) * 8;
        const float* Ap = W + (long)row * 128 + kq;
        const float* Bp = g_otok + ((long)z * Ntok + token) * VDdim + vbase + kq;
        float4 a0 = *(const float4*)(Ap);
        float4 a1 = *(const float4*)(Ap + 4);
        float4 b0 = *(const float4*)(Bp);
        float4 b1 = *(const float4*)(Bp + 4);
        As[0][kq+0][row]=a0.x; As[0][kq+1][row]=a0.y; As[0][kq+2][row]=a0.z; As[0][kq+3][row]=a0.w;
        As[0][kq+4][row]=a1.x; As[0][kq+5][row]=a1.y; As[0][kq+6][row]=a1.z; As[0][kq+7][row]=a1.w;
        Bs[0][kq+0][row]=b0.x; Bs[0][kq+1][row]=b0.y; Bs[0][kq+2][row]=b0.z; Bs[0][kq+3][row]=b0.w;
        Bs[0][kq+4][row]=b1.x; Bs[0][kq+5][row]=b1.y; Bs[0][kq+6][row]=b1.z; Bs[0][kq+7][row]=b1.w;
        __syncthreads();
        int buf = 0;
        for (int k0 = 16; k0 <= 128; k0 += 16) {
            if (k0 < 128) {
                a0 = *(const float4*)(Ap + k0);
                a1 = *(const float4*)(Ap + k0 + 4);
                b0 = *(const float4*)(Bp + k0);
                b1 = *(const float4*)(Bp + k0 + 4);
            }
            #pragma unroll
            for (int kk = 0; kk < 16; kk++)
                fma_step(&As[buf][kk][0], &Bs[buf][kk][0], tx, ty, acc);
            if (k0 < 128) {
                int nb = buf ^ 1;
                As[nb][kq+0][row]=a0.x; As[nb][kq+1][row]=a0.y; As[nb][kq+2][row]=a0.z; As[nb][kq+3][row]=a0.w;
                As[nb][kq+4][row]=a1.x; As[nb][kq+5][row]=a1.y; As[nb][kq+6][row]=a1.z; As[nb][kq+7][row]=a1.w;
                Bs[nb][kq+0][row]=b0.x; Bs[nb][kq+1][row]=b0.y; Bs[nb][kq+2][row]=b0.z; Bs[nb][kq+3][row]=b0.w;
                Bs[nb][kq+4][row]=b1.x; Bs[nb][kq+5][row]=b1.y; Bs[nb][kq+6][row]=b1.z; Bs[nb][kq+7][row]=b1.w;
                __syncthreads();
                buf = nb;
            }
        }
    }
    #pragma unroll
    for (int i = 0; i < 8; i++) {
        int m = (i < 4) ? (ty*4 + i) : (64 + ty*4 + i - 4);
        float bv = bias[m];
        float2 p0 = unpk(acc[i][0]), p1 = unpk(acc[i][1]);
        float2 p2 = unpk(acc[i][2]), p3 = unpk(acc[i][3]);
        float4 o0 = {p0.x+bv, p0.y+bv, p1.x+bv, p1.y+bv};
        float4 o1 = {p2.x+bv, p2.y+bv, p3.x+bv, p3.y+bv};
        *(float4*)&Out[((long)z*128 + m)*HW2 + n0 + tx*4]      = o0;
        *(float4*)&Out[((long)z*128 + m)*HW2 + n0 + 64 + tx*4] = o1;
    }
}

// ---------------- depthwise 3x3 pad1, 4 pixels/thread -------------------------
__global__ void __launch_bounds__(256) dw3x3v(
    const float* __restrict__ qk_dw_w, const float* __restrict__ qk_dw_b,
    const float* __restrict__ v_dw_w,  const float* __restrict__ v_dw_b)
{
    int idx = blockIdx.x * 256 + threadIdx.x;
    const int NQ = BATCH*384*HW2/4;
    if (idx >= NQ) return;
    int qw = idx % (HWd/4);
    int h  = (idx / (HWd/4)) % HWd;
    int ch = (idx / (HW2/4)) % 384;
    int b  = idx / (384*HW2/4);
    int w0 = qw * 4;

    const float* wgt; float bv;
    if (ch < 256) { wgt = qk_dw_w + ch*9;        bv = qk_dw_b[ch]; }
    else          { wgt = v_dw_w  + (ch-256)*9;  bv = v_dw_b[ch-256]; }
    float k0=wgt[0],k1=wgt[1],k2=wgt[2],k3=wgt[3],k4=wgt[4],k5=wgt[5],k6=wgt[6],k7=wgt[7],k8=wgt[8];

    const float* in = g_buf1 + ((long)(b*384 + ch)) * HW2;
    float r[3][6];
    #pragma unroll
    for (int ky = 0; ky < 3; ky++) {
        int y = h + ky - 1;
        if ((unsigned)y >= (unsigned)HWd) {
            #pragma unroll
            for (int j = 0; j < 6; j++) r[ky][j] = 0.f;
        } else {
            const float* rp = in + (long)y * HWd + w0;
            float4 c = *(const float4*)rp;
            r[ky][1] = c.x; r[ky][2] = c.y; r[ky][3] = c.z; r[ky][4] = c.w;
            r[ky][0] = (w0 > 0)        ? rp[-1] : 0.f;
            r[ky][5] = (w0 + 4 < HWd)  ? rp[4]  : 0.f;
        }
    }
    float4 o;
    float* op = (float*)&o;
    #pragma unroll
    for (int j = 0; j < 4; j++) {
        op[j] = bv
              + k0*r[0][j] + k1*r[0][j+1] + k2*r[0][j+2]
              + k3*r[1][j] + k4*r[1][j+1] + k5*r[1][j+2]
              + k6*r[2][j] + k7*r[2][j+1] + k8*r[2][j+2];
    }
    *(float4*)&g_buf2[(long)idx*4] = o;
}

// ---------------- depthwise 4x4 stride4 pad1 ----------------------------------
__global__ void dw4x4(const float* __restrict__ q2_dw_w, const float* __restrict__ q2_dw_b,
                      const float* __restrict__ k2_dw_w, const float* __restrict__ k2_dw_b)
{
    int idx = blockIdx.x * 256 + threadIdx.x;
    if (idx >= BATCH*512*Ntok) return;
    int t  = idx % Ntok;
    int ch = (idx / Ntok) % 512;
    int b  = idx / (512*Ntok);
    int oy = t / HGd, ox = t % HGd;
    const float* wgt; float bv;
    if (ch < 256) { wgt = q2_dw_w + ch*16;       bv = q2_dw_b[ch]; }
    else          { wgt = k2_dw_w + (ch-256)*16; bv = k2_dw_b[ch-256]; }
    const float* in = g_buf3 + ((long)(b*512 + ch)) * HW2;
    float s = bv;
    #pragma unroll
    for (int ky = 0; ky < 4; ky++) {
        int y = oy*4 - 1 + ky;
        if ((unsigned)y >= (unsigned)HWd) continue;
        #pragma unroll
        for (int kx = 0; kx < 4; kx++) {
            int x = ox*4 - 1 + kx;
            if ((unsigned)x >= (unsigned)HWd) continue;
            s += wgt[ky*4+kx] * in[y*HWd + x];
        }
    }
    g_buf4[idx] = s;
}

// ---------------- l2 normalize + token-major q/k (shfl reductions) ------------
__global__ void __launch_bounds__(256) norm_qk(float* __restrict__ kout,
                                               const float* __restrict__ temp)
{
    int token = blockIdx.x, b = blockIdx.y, d = threadIdx.x;
    int lane = d & 31, wid = d >> 5;
    float qv = g_buf4[((long)b*512 + d)       * Ntok + token];
    float kv = g_buf4[((long)b*512 + 256 + d) * Ntok + token];
    __shared__ float wsumq[8], wsumk[8];
    __shared__ float qinv_s, kinv_s;
    float sq = qv*qv, sk = kv*kv;
    #pragma unroll
    for (int o = 16; o > 0; o >>= 1) {
        sq += __shfl_xor_sync(0xffffffffu, sq, o);
        sk += __shfl_xor_sync(0xffffffffu, sk, o);
    }
    if (lane == 0) { wsumq[wid] = sq; wsumk[wid] = sk; }
    __syncthreads();
    if (d < 32) {
        float tq = (lane < 8) ? wsumq[lane] : 0.f;
        float tk = (lane < 8) ? wsumk[lane] : 0.f;
        #pragma unroll
        for (int o = 4; o > 0; o >>= 1) {
            tq += __shfl_xor_sync(0xffffffffu, tq, o);
            tk += __shfl_xor_sync(0xffffffffu, tk, o);
        }
        if (lane == 0) {
            qinv_s = (*temp) / fmaxf(sqrtf(tq), 1e-12f);
            kinv_s = 1.f / fmaxf(sqrtf(tk), 1e-12f);
        }
    }
    __syncthreads();
    g_qtok[((long)b*Ntok + token) * D2 + d] = qv * qinv_s;
    kout  [((long)(b*2 + 1)*Ntok + token) * D2 + d] = kv * kinv_s;
}

// ---------------- build v_new: smem-transposed (coalesced both sides) ---------
// block = (b, p1*4+p2, hi): loads [c][wi] along wi, stores [token][c] along c
__global__ void __launch_bounds__(256) build_vnew_t(float* __restrict__ vout)
{
    int hi = blockIdx.x;                 // 0..47
    int pp = blockIdx.y;                 // 0..15 (p1*4+p2)
    int b  = blockIdx.z;
    int p1 = pp >> 2, p2 = pp & 3;
    int tid = threadIdx.x;
    __shared__ float ts[48][129];        // [wi][c]

    const float* src = g_buf2 + ((long)(b*384 + 256)) * HW2
                       + (long)(p1*HGd + hi) * HWd + p2*HGd;
    // load: 128 channels x 48 wi; thread covers (c, wi-range)
    for (int i = tid; i < 128*48; i += 256) {
        int c = i / 48, wi = i - c*48;
        ts[wi][c] = src[(long)c * HW2 + wi];
    }
    __syncthreads();
    // store: token-major, 128 consecutive c per token (float4)
    float* dst = vout + ((long)(b*2 + 1)*Ntok + hi*HGd) * VDdim + p1*512 + p2*128;
    for (int i = tid; i < 48*32; i += 256) {
        int wi = i >> 5, c4 = (i & 31) * 4;
        float4 v = make_float4(ts[wi][c4], ts[wi][c4+1], ts[wi][c4+2], ts[wi][c4+3]);
        *(float4*)&dst[(long)wi * VDdim + c4] = v;
    }
}

// =============================================================================
// sparse_select (per row): top-5 fused into gmem read; pass-2 re-reads via L1
// =============================================================================
__global__ void __launch_bounds__(256) sparse_select()
{
    int n = blockIdx.x, f = blockIdx.y, b = blockIdx.z;
    int z = b*NFtot + f;
    int rowid = z * Ntok + n;
    const float* arow = g_attn + (long)rowid * Ntok;
    int tid = threadIdx.x;

    __shared__ float cand[256*5];
    __shared__ float bcast;
    __shared__ int   nnz;
    __shared__ int   sidx[SELCAP];
    __shared__ float sval[SELCAP];

    if (tid == 0) nnz = 0;

    // pass 1: top-5 directly from gmem (float4), populates L1 for pass 2
    float t5[5] = {-INFINITY,-INFINITY,-INFINITY,-INFINITY,-INFINITY};
    for (int m4 = tid*4; m4 < Ntok; m4 += 1024) {
        float4 v4 = *(const float4*)&arow[m4];
        float vv[4] = {v4.x, v4.y, v4.z, v4.w};
        #pragma unroll
        for (int u = 0; u < 4; u++) {
            float v = vv[u];
            if (v > t5[4]) {
                t5[4] = v;
                #pragma unroll
                for (int i = 4; i > 0; i--)
                    if (t5[i] > t5[i-1]) { float tmp = t5[i-1]; t5[i-1] = t5[i]; t5[i] = tmp; }
            }
        }
    }
    #pragma unroll
    for (int i = 0; i < 5; i++) cand[tid*5 + i] = t5[i];
    __syncthreads();

    // warp 0 merges 1280 candidates -> kth largest
    if (tid < 32) {
        float l5[5] = {-INFINITY,-INFINITY,-INFINITY,-INFINITY,-INFINITY};
        const float* cp = cand + tid*40;
        #pragma unroll
        for (int i = 0; i < 40; i++) {
            float v = cp[i];
            if (v > l5[4]) {
                l5[4] = v;
                #pragma unroll
                for (int j = 4; j > 0; j--)
                    if (l5[j] > l5[j-1]) { float tmp = l5[j-1]; l5[j-1] = l5[j]; l5[j] = tmp; }
            }
        }
        float thr = INFINITY;
        #pragma unroll
        for (int r = 0; r < 5; r++) {
            float lm = -INFINITY;
            #pragma unroll
            for (int i = 0; i < 5; i++) {
                float v = l5[i];
                if (v < thr && v > lm) lm = v;
            }
            #pragma unroll
            for (int o = 16; o > 0; o >>= 1)
                lm = fmaxf(lm, __shfl_xor_sync(0xffffffffu, lm, o));
            thr = lm;
        }
        if (tid == 0) bcast = thr;
    }
    __syncthreads();
    float kth = bcast;

    // pass 2: collect nonzero entries (gmem, L1-hot)
    int ny = n / HGd, nx = n % HGd;
    for (int m = tid; m < Ntok; m += 256) {
        float a = arow[m];
        float coef = (a >= kth) ? 1.f : 0.f;
        int my = m / HGd, mx = m % HGd;
        if (abs(ny - my) + abs(nx - mx) <= 4) coef += 1.f;
        float v = a * coef;
        if (v != 0.f) {
            int pos = atomicAdd(&nnz, 1);
            if (pos < SELCAP) { sidx[pos] = m; sval[pos] = v; }
        }
    }
    __syncthreads();
    int cnt = min(nnz, SELCAP);

    // softmax via warp 0
    if (tid < 32) {
        float mx = -INFINITY;
        for (int e = tid; e < cnt; e += 32) mx = fmaxf(mx, sval[e]);
        #pragma unroll
        for (int o = 16; o > 0; o >>= 1)
            mx = fmaxf(mx, __shfl_xor_sync(0xffffffffu, mx, o));
        if (tid == 0) bcast = mx;
    }
    __syncthreads();
    float mxv = bcast;
    if (tid < cnt) sval[tid] = expf(sval[tid] - mxv);
    __syncthreads();
    if (tid < 32) {
        float s = 0.f;
        for (int e = tid; e < cnt; e += 32) s += sval[e];
        #pragma unroll
        for (int o = 16; o > 0; o >>= 1)
            s += __shfl_xor_sync(0xffffffffu, s, o);
        if (tid == 0) bcast = s;
    }
    __syncthreads();
    if (tid < cnt) {
        g_selidx[(long)rowid*SELCAP + tid] = sidx[tid];
        g_selw  [(long)rowid*SELCAP + tid] = sval[tid] / bcast;
    }
    if (tid == 0) g_selcnt[rowid] = cnt;
}

// =============================================================================
// sparse_av8: 2x4 query tile (8 queries), union gather (round-13 winner)
// =============================================================================
__global__ void __launch_bounds__(256) sparse_av8(
    const float* __restrict__ v_cached, const float* __restrict__ vout)
{
    int chunk = blockIdx.x;
    int tile  = blockIdx.y;
    int z     = blockIdx.z;
    int b = z / NFtot, f = z % NFtot;
    int qy0 = (tile / 12) * 2, qx0 = (tile % 12) * 4;
    int tid = threadIdx.x;

    __shared__ int   sidx[8][SELCAP];
    __shared__ float sval[8][SELCAP];
    __shared__ int   scnt[8];
    __shared__ unsigned umask[72];
    __shared__ int   ubase[73];
    __shared__ int   uidx[MAXU];
    __shared__ float Wt[8][MAXU];

    if (tid < 72) umask[tid] = 0;
    int rowbase = z * Ntok;
    if (tid < 8) {
        int q = tid;
        int n = (qy0 + (q >> 2)) * HGd + qx0 + (q & 3);
        scnt[q] = g_selcnt[rowbase + n];
    }
    __syncthreads();
    for (int i = tid; i < 8 * SELCAP; i += 256) {
        int q = i >> 6, e = i & (SELCAP-1);
        if (e < scnt[q]) {
            int n = (qy0 + (q >> 2)) * HGd + qx0 + (q & 3);
            long base = (long)(rowbase + n) * SELCAP + e;
            int m = g_selidx[base];
            sidx[q][e] = m;
            sval[q][e] = g_selw[base];
            atomicOr(&umask[m >> 5], 1u << (m & 31));
        }
    }
    __syncthreads();
    if (tid == 0) {
        int s = 0;
        for (int w = 0; w < 72; w++) { ubase[w] = s; s += __popc(umask[w]); }
        ubase[72] = s;
    }
    __syncthreads();
    int U = min(ubase[72], MAXU);

    for (int i = tid; i < 8*MAXU; i += 256) ((float*)Wt)[i] = 0.f;
    __syncthreads();
    if (tid < 72) {
        unsigned bits = umask[tid];
        int pos = ubase[tid];
        while (bits) {
            int bit = __ffs(bits) - 1; bits &= bits - 1;
            if (pos < MAXU) uidx[pos] = tid*32 + bit;
            pos++;
        }
    }
    __syncthreads();
    for (int i = tid; i < 8*SELCAP; i += 256) {
        int q = i >> 6, e = i & (SELCAP-1);
        if (e < scnt[q]) {
            int m = sidx[q][e];
            int w32 = m >> 5, bit = m & 31;
            int rank = ubase[w32] + __popc(umask[w32] & ((1u << bit) - 1u));
            if (rank < MAXU) Wt[q][rank] = sval[q][e];
        }
    }
    __syncthreads();

    const float* vbase = (f < 2) ? (v_cached + ((long)(b*2 + f)) * Ntok * VDdim)
                                 : (vout     + ((long)(b*2 + 1)) * Ntok * VDdim);
    int d0 = chunk * 1024 + tid * 4;
    u64 acc[8][2] = {};
    for (int e = 0; e < U; e++) {
        int m = uidx[e];
        ulonglong2 vv = *(const ulonglong2*)(vbase + (long)m * VDdim + d0);
        #pragma unroll
        for (int q = 0; q < 8; q++) {
            u64 wq = dup2(Wt[q][e]);
            fma2(acc[q][0], wq, vv.x);
            fma2(acc[q][1], wq, vv.y);
        }
    }
    #pragma unroll
    for (int q = 0; q < 8; q++) {
        int n = (qy0 + (q >> 2)) * HGd + qx0 + (q & 3);
        float2 p0 = unpk(acc[q][0]), p1 = unpk(acc[q][1]);
        float* orow = g_otok + ((long)(rowbase + n)) * VDdim + d0;
        *(float4*)orow = make_float4(p0.x, p0.y, p1.x, p1.y);
    }
}

// ---------------------------------- launch -----------------------------------
extern "C" void kernel_launch(void* const* d_in, const int* in_sizes, int n_in,
                              void* d_out, int out_size)
{
    (void)in_sizes; (void)n_in; (void)out_size;
    const float* x         = (const float*)d_in[0];
    const float* k_cached  = (const float*)d_in[1];
    const float* v_cached  = (const float*)d_in[2];
    const float* temperature = (const float*)d_in[3];
    const float* qk_w  = (const float*)d_in[4],  *qk_b  = (const float*)d_in[5];
    const float* qk_dw_w = (const float*)d_in[6], *qk_dw_b = (const float*)d_in[7];
    const float* v_w   = (const float*)d_in[8],  *v_b   = (const float*)d_in[9];
    const float* v_dw_w = (const float*)d_in[10], *v_dw_b = (const float*)d_in[11];
    const float* k2_w  = (const float*)d_in[12], *k2_b  = (const float*)d_in[13];
    const float* k2_dw_w = (const float*)d_in[14], *k2_dw_b = (const float*)d_in[15];
    const float* q2_w  = (const float*)d_in[16], *q2_b  = (const float*)d_in[17];
    const float* q2_dw_w = (const float*)d_in[18], *q2_dw_b = (const float*)d_in[19];
    const float* proj_w = (const float*)d_in[20], *proj_b = (const float*)d_in[21];

    float* out = (float*)d_out;
    const long OUT_K = (long)BATCH * NFtot * 128 * HW2;
    const long OUT_V = OUT_K + (long)BATCH * 2 * Ntok * D2;
    float* kout = out + OUT_K;
    float* vout = out + OUT_V;

    dim3 blk(256);

    gemm_stageA<<<dim3(288,3,BATCH), blk>>>(x, qk_w, qk_b, v_w, v_b);
    dw3x3v<<<(BATCH*384*HW2/4 + 255)/256, blk>>>(qk_dw_w, qk_dw_b, v_dw_w, v_dw_b);
    gemm_stageC<<<dim3(288,4,BATCH), blk>>>(q2_w, q2_b, k2_w, k2_b);
    dw4x4<<<(BATCH*512*Ntok + 255)/256, blk>>>(q2_dw_w, q2_dw_b, k2_dw_w, k2_dw_b);
    norm_qk<<<dim3(Ntok, BATCH), blk>>>(kout, temperature);
    build_vnew_t<<<dim3(HGd, 16, BATCH), blk>>>(vout);
    for (int b = 0; b < BATCH; b++) {
        cudaMemcpyAsync(kout + (long)(b*2)*Ntok*D2,
                        k_cached + (long)(b*2+1)*Ntok*D2,
                        (size_t)Ntok*D2*sizeof(float), cudaMemcpyDeviceToDevice, 0);
        cudaMemcpyAsync(vout + (long)(b*2)*Ntok*VDdim,
                        v_cached + (long)(b*2+1)*Ntok*VDdim,
                        (size_t)Ntok*VDdim*sizeof(float), cudaMemcpyDeviceToDevice, 0);
    }
    attn_gemm2<<<dim3(18,18,BATCH*NFtot), blk>>>(k_cached, kout);
    sparse_select<<<dim3(Ntok, NFtot, BATCH), blk>>>();
    sparse_av8<<<dim3(2, 288, BATCH*NFtot), blk>>>(v_cached, vout);
    proj_gemm2<<<dim3(288,1,BATCH*NFtot), blk>>>(proj_w, proj_b, out);
}

// round 15
// speedup vs baseline: 1.5708x; 1.0124x over previous
#include <cuda_runtime.h>
#include <math.h>

#define BATCH 2
#define HWd   192
#define HW2   (HWd*HWd)      // 36864
#define HGd   48
#define Ntok  (HGd*HGd)      // 2304
#define D2    256
#define VDdim 2048
#define NFtot 3
#define SELCAP 64
#define MAXU   128
#define NROWS (BATCH*NFtot*Ntok)

typedef unsigned long long u64;

// ---------------- scratch (device globals; no allocs allowed) ----------------
__device__ float g_buf1[(size_t)BATCH*384*HW2];
__device__ float g_buf2[(size_t)BATCH*384*HW2];
__device__ float g_buf3[(size_t)BATCH*512*HW2];
__device__ float g_buf4[(size_t)BATCH*512*Ntok];
__device__ float g_qtok[(size_t)BATCH*Ntok*D2];
__device__ float g_attn[(size_t)BATCH*NFtot*Ntok*Ntok];
__device__ float g_otok[(size_t)BATCH*NFtot*Ntok*VDdim];
__device__ int   g_selidx[(size_t)NROWS*SELCAP];
__device__ float g_selw  [(size_t)NROWS*SELCAP];
__device__ int   g_selcnt[NROWS];

// ---------------- packed fp32x2 primitives (Blackwell FFMA2) -----------------
__device__ __forceinline__ u64 dup2(float x) {
    u64 r;
    asm("mov.b64 %0, {%1, %1};" : "=l"(r) : "r"(__float_as_uint(x)));
    return r;
}
__device__ __forceinline__ void fma2(u64 &d, u64 a, u64 b) {
    asm("fma.rn.f32x2 %0, %1, %2, %3;" : "=l"(d) : "l"(a), "l"(b), "l"(d));
}
__device__ __forceinline__ float2 unpk(u64 v) {
    float lo, hi;
    asm("mov.b64 {%0, %1}, %2;" : "=f"(lo), "=f"(hi) : "l"(v));
    return make_float2(lo, hi);
}

// one k-step of the 8x8 fragment: 32 fma.f32x2
__device__ __forceinline__ void fma_step(
    const float* __restrict__ As_k, const float* __restrict__ Bs_k,
    int tx, int ty, u64 acc[8][4])
{
    float4 av0 = *(const float4*)(As_k + ty*4);
    float4 av1 = *(const float4*)(As_k + 64 + ty*4);
    ulonglong2 bv0 = *(const ulonglong2*)(Bs_k + tx*4);
    ulonglong2 bv1 = *(const ulonglong2*)(Bs_k + 64 + tx*4);
    u64 aa[8] = {dup2(av0.x), dup2(av0.y), dup2(av0.z), dup2(av0.w),
                 dup2(av1.x), dup2(av1.y), dup2(av1.z), dup2(av1.w)};
    u64 bb[4] = {bv0.x, bv0.y, bv1.x, bv1.y};
    #pragma unroll
    for (int i = 0; i < 8; i++) {
        fma2(acc[i][0], aa[i], bb[0]);
        fma2(acc[i][1], aa[i], bb[1]);
        fma2(acc[i][2], aa[i], bb[2]);
        fma2(acc[i][3], aa[i], bb[3]);
    }
}

// =============================================================================
// double-buffered conv GEMM body
// =============================================================================
__device__ __forceinline__ void gemm_db_conv2(
    const float* __restrict__ A, const float* __restrict__ Bbase, int K,
    float (* __restrict__ As)[16][132], float (* __restrict__ Bs)[16][128],
    int t, u64 acc[8][4])
{
    int arow = t >> 1, akq = (t & 1) * 8;
    int bk = t >> 4, bn = (t & 15) * 4;
    int tx = t & 15, ty = t >> 4;
    const float* Ap = A + (long)arow * K + akq;

    float4 a0 = *(const float4*)(Ap);
    float4 a1 = *(const float4*)(Ap + 4);
    const float* bs0 = Bbase + (long)bk * HW2;
    float4 b0 = *(const float4*)(bs0 + bn);
    float4 b1 = *(const float4*)(bs0 + bn + 64);
    As[0][akq+0][arow]=a0.x; As[0][akq+1][arow]=a0.y; As[0][akq+2][arow]=a0.z; As[0][akq+3][arow]=a0.w;
    As[0][akq+4][arow]=a1.x; As[0][akq+5][arow]=a1.y; As[0][akq+6][arow]=a1.z; As[0][akq+7][arow]=a1.w;
    *(float4*)&Bs[0][bk][bn]    = b0;
    *(float4*)&Bs[0][bk][bn+64] = b1;
    __syncthreads();
    int buf = 0;
    for (int k0 = 16; k0 <= K; k0 += 16) {
        if (k0 < K) {
            a0 = *(const float4*)(Ap + k0);
            a1 = *(const float4*)(Ap + k0 + 4);
            const float* bs2 = Bbase + (long)(k0 + bk) * HW2;
            b0 = *(const float4*)(bs2 + bn);
            b1 = *(const float4*)(bs2 + bn + 64);
        }
        #pragma unroll
        for (int kk = 0; kk < 16; kk++)
            fma_step(&As[buf][kk][0], &Bs[buf][kk][0], tx, ty, acc);
        if (k0 < K) {
            int nb = buf ^ 1;
            As[nb][akq+0][arow]=a0.x; As[nb][akq+1][arow]=a0.y; As[nb][akq+2][arow]=a0.z; As[nb][akq+3][arow]=a0.w;
            As[nb][akq+4][arow]=a1.x; As[nb][akq+5][arow]=a1.y; As[nb][akq+6][arow]=a1.z; As[nb][akq+7][arow]=a1.w;
            *(float4*)&Bs[nb][bk][bn]    = b0;
            *(float4*)&Bs[nb][bk][bn+64] = b1;
            __syncthreads();
            buf = nb;
        }
    }
}

// =============================================================================
// double-buffered TT GEMM body
// =============================================================================
__device__ __forceinline__ void gemm_db_tt2(
    const float* __restrict__ Abase, const float* __restrict__ Bbase, int K,
    float (* __restrict__ As)[16][132], float (* __restrict__ Bs)[16][132],
    int t, u64 acc[8][4])
{
    int row = t >> 1, kq = (t & 1) * 8;
    int tx = t & 15, ty = t >> 4;
    const float* Ap = Abase + (long)row * K + kq;
    const float* Bp = Bbase + (long)row * K + kq;

    float4 a0 = *(const float4*)(Ap);
    float4 a1 = *(const float4*)(Ap + 4);
    float4 b0 = *(const float4*)(Bp);
    float4 b1 = *(const float4*)(Bp + 4);
    As[0][kq+0][row]=a0.x; As[0][kq+1][row]=a0.y; As[0][kq+2][row]=a0.z; As[0][kq+3][row]=a0.w;
    As[0][kq+4][row]=a1.x; As[0][kq+5][row]=a1.y; As[0][kq+6][row]=a1.z; As[0][kq+7][row]=a1.w;
    Bs[0][kq+0][row]=b0.x; Bs[0][kq+1][row]=b0.y; Bs[0][kq+2][row]=b0.z; Bs[0][kq+3][row]=b0.w;
    Bs[0][kq+4][row]=b1.x; Bs[0][kq+5][row]=b1.y; Bs[0][kq+6][row]=b1.z; Bs[0][kq+7][row]=b1.w;
    __syncthreads();
    int buf = 0;
    for (int k0 = 16; k0 <= K; k0 += 16) {
        if (k0 < K) {
            a0 = *(const float4*)(Ap + k0);
            a1 = *(const float4*)(Ap + k0 + 4);
            b0 = *(const float4*)(Bp + k0);
            b1 = *(const float4*)(Bp + k0 + 4);
        }
        #pragma unroll
        for (int kk = 0; kk < 16; kk++)
            fma_step(&As[buf][kk][0], &Bs[buf][kk][0], tx, ty, acc);
        if (k0 < K) {
            int nb = buf ^ 1;
            As[nb][kq+0][row]=a0.x; As[nb][kq+1][row]=a0.y; As[nb][kq+2][row]=a0.z; As[nb][kq+3][row]=a0.w;
            As[nb][kq+4][row]=a1.x; As[nb][kq+5][row]=a1.y; As[nb][kq+6][row]=a1.z; As[nb][kq+7][row]=a1.w;
            Bs[nb][kq+0][row]=b0.x; Bs[nb][kq+1][row]=b0.y; Bs[nb][kq+2][row]=b0.z; Bs[nb][kq+3][row]=b0.w;
            Bs[nb][kq+4][row]=b1.x; Bs[nb][kq+5][row]=b1.y; Bs[nb][kq+6][row]=b1.z; Bs[nb][kq+7][row]=b1.w;
            __syncthreads();
            buf = nb;
        }
    }
}

__device__ __forceinline__ void gemm128_store2(
    float* __restrict__ Crow, const float* __restrict__ bias,
    int t, u64 acc[8][4], long ldc)
{
    int tx = t & 15, ty = t >> 4;
    #pragma unroll
    for (int i = 0; i < 8; i++) {
        int m = (i < 4) ? (ty*4 + i) : (64 + ty*4 + i - 4);
        float bv = bias ? bias[m] : 0.f;
        float2 p0 = unpk(acc[i][0]), p1 = unpk(acc[i][1]);
        float2 p2 = unpk(acc[i][2]), p3 = unpk(acc[i][3]);
        float4 o0 = {p0.x+bv, p0.y+bv, p1.x+bv, p1.y+bv};
        float4 o1 = {p2.x+bv, p2.y+bv, p3.x+bv, p3.y+bv};
        *(float4*)&Crow[(long)m*ldc + tx*4]      = o0;
        *(float4*)&Crow[(long)m*ldc + 64 + tx*4] = o1;
    }
}

// stage A
__global__ void __launch_bounds__(256,2) gemm_stageA(
    const float* __restrict__ x,
    const float* __restrict__ qk_w, const float* __restrict__ qk_b,
    const float* __restrict__ v_w,  const float* __restrict__ v_b)
{
    int n0 = blockIdx.x * 128, y = blockIdx.y, b = blockIdx.z;
    int t = threadIdx.x;
    __shared__ float As[2][16][132];
    __shared__ float Bs[2][16][128];
    u64 acc[8][4] = {};
    const float* A   = (y < 2) ? (qk_w + (long)y*128*128) : v_w;
    const float* bia = (y < 2) ? (qk_b + y*128)           : v_b;
    int cch          = (y < 2) ? (y*128)                  : 256;
    gemm_db_conv2(A, x + (long)b*128*HW2 + n0, 128, As, Bs, t, acc);
    gemm128_store2(g_buf1 + ((long)b*384 + cch) * HW2 + n0, bia, t, acc, HW2);
}

// stage C
__global__ void __launch_bounds__(256,2) gemm_stageC(
    const float* __restrict__ q2_w, const float* __restrict__ q2_b,
    const float* __restrict__ k2_w, const float* __restrict__ k2_b)
{
    int n0 = blockIdx.x * 128, y = blockIdx.y, b = blockIdx.z;
    int t = threadIdx.x;
    __shared__ float As[2][16][132];
    __shared__ float Bs[2][16][128];
    u64 acc[8][4] = {};
    const float* A   = (y < 2) ? (q2_w + (long)y*128*128) : (k2_w + (long)(y-2)*128*128);
    const float* bia = (y < 2) ? (q2_b + y*128)           : (k2_b + (y-2)*128);
    const float* Bbase = g_buf2 + ((long)b*384 + ((y < 2) ? 0 : 128)) * HW2 + n0;
    gemm_db_conv2(A, Bbase, 128, As, Bs, t, acc);
    gemm128_store2(g_buf3 + ((long)b*512 + y*128) * HW2 + n0, bia, t, acc, HW2);
}

// attention GEMM
__global__ void __launch_bounds__(256,2) attn_gemm2(
    const float* __restrict__ kc, const float* __restrict__ knew)
{
    int z = blockIdx.z; int b = z / NFtot, f = z % NFtot;
    const float* Qp = g_qtok + (long)b * Ntok * D2;
    const float* Kp = (f < 2) ? (kc   + ((long)(b*2 + f)) * Ntok * D2)
                              : (knew + ((long)(b*2 + 1)) * Ntok * D2);
    int m0 = blockIdx.y * 128, n0 = blockIdx.x * 128;
    int t = threadIdx.x;
    int tx = t & 15, ty = t >> 4;
    __shared__ float As[2][16][132];
    __shared__ float Bs[2][16][132];
    u64 acc[8][4] = {};
    gemm_db_tt2(Qp + (long)m0 * D2, Kp + (long)n0 * D2, D2, As, Bs, t, acc);
    float* Cp = g_attn + (long)z * Ntok * Ntok;
    #pragma unroll
    for (int i = 0; i < 8; i++) {
        int m = (i < 4) ? (ty*4 + i) : (64 + ty*4 + i - 4);
        float2 p0 = unpk(acc[i][0]), p1 = unpk(acc[i][1]);
        float2 p2 = unpk(acc[i][2]), p3 = unpk(acc[i][3]);
        float4 o0 = {p0.x, p0.y, p1.x, p1.y};
        float4 o1 = {p2.x, p2.y, p3.x, p3.y};
        *(float4*)&Cp[(long)(m0+m)*Ntok + n0 + tx*4]      = o0;
        *(float4*)&Cp[(long)(m0+m)*Ntok + n0 + 64 + tx*4] = o1;
    }
}

// proj 1x1 GEMM with fused window de-permute gather
__global__ void __launch_bounds__(256,2) proj_gemm2(
    const float* __restrict__ W, const float* __restrict__ bias,
    float* __restrict__ Out)
{
    int z  = blockIdx.z;
    int n0 = blockIdx.x * 128;
    int t = threadIdx.x;
    int tx = t & 15, ty = t >> 4;
    __shared__ float As[2][16][132];
    __shared__ float Bs[2][16][132];
    u64 acc[8][4] = {};
    int row = t >> 1;
    int p = n0 + row;
    int h = p / HWd, w = p % HWd;
    int token = (h % HGd) * HGd + (w % HGd);
    int vbase = ((h / HGd) * 4 + (w / HGd)) * 128;
    {
        int kq = (t & 1) * 8;
        const float* Ap = W + (long)row * 128 + kq;
        const float* Bp = g_otok + ((long)z * Ntok + token) * VDdim + vbase + kq;
        float4 a0 = *(const float4*)(Ap);
        float4 a1 = *(const float4*)(Ap + 4);
        float4 b0 = *(const float4*)(Bp);
        float4 b1 = *(const float4*)(Bp + 4);
        As[0][kq+0][row]=a0.x; As[0][kq+1][row]=a0.y; As[0][kq+2][row]=a0.z; As[0][kq+3][row]=a0.w;
        As[0][kq+4][row]=a1.x; As[0][kq+5][row]=a1.y; As[0][kq+6][row]=a1.z; As[0][kq+7][row]=a1.w;
        Bs[0][kq+0][row]=b0.x; Bs[0][kq+1][row]=b0.y; Bs[0][kq+2][row]=b0.z; Bs[0][kq+3][row]=b0.w;
        Bs[0][kq+4][row]=b1.x; Bs[0][kq+5][row]=b1.y; Bs[0][kq+6][row]=b1.z; Bs[0][kq+7][row]=b1.w;
        __syncthreads();
        int buf = 0;
        for (int k0 = 16; k0 <= 128; k0 += 16) {
            if (k0 < 128) {
                a0 = *(const float4*)(Ap + k0);
                a1 = *(const float4*)(Ap + k0 + 4);
                b0 = *(const float4*)(Bp + k0);
                b1 = *(const float4*)(Bp + k0 + 4);
            }
            #pragma unroll
            for (int kk = 0; kk < 16; kk++)
                fma_step(&As[buf][kk][0], &Bs[buf][kk][0], tx, ty, acc);
            if (k0 < 128) {
                int nb = buf ^ 1;
                As[nb][kq+0][row]=a0.x; As[nb][kq+1][row]=a0.y; As[nb][kq+2][row]=a0.z; As[nb][kq+3][row]=a0.w;
                As[nb][kq+4][row]=a1.x; As[nb][kq+5][row]=a1.y; As[nb][kq+6][row]=a1.z; As[nb][kq+7][row]=a1.w;
                Bs[nb][kq+0][row]=b0.x; Bs[nb][kq+1][row]=b0.y; Bs[nb][kq+2][row]=b0.z; Bs[nb][kq+3][row]=b0.w;
                Bs[nb][kq+4][row]=b1.x; Bs[nb][kq+5][row]=b1.y; Bs[nb][kq+6][row]=b1.z; Bs[nb][kq+7][row]=b1.w;
                __syncthreads();
                buf = nb;
            }
        }
    }
    #pragma unroll
    for (int i = 0; i < 8; i++) {
        int m = (i < 4) ? (ty*4 + i) : (64 + ty*4 + i - 4);
        float bv = bias[m];
        float2 p0 = unpk(acc[i][0]), p1 = unpk(acc[i][1]);
        float2 p2 = unpk(acc[i][2]), p3 = unpk(acc[i][3]);
        float4 o0 = {p0.x+bv, p0.y+bv, p1.x+bv, p1.y+bv};
        float4 o1 = {p2.x+bv, p2.y+bv, p3.x+bv, p3.y+bv};
        *(float4*)&Out[((long)z*128 + m)*HW2 + n0 + tx*4]      = o0;
        *(float4*)&Out[((long)z*128 + m)*HW2 + n0 + 64 + tx*4] = o1;
    }
}

// ---------------- depthwise 3x3 pad1, 4 pixels/thread -------------------------
__global__ void __launch_bounds__(256) dw3x3v(
    const float* __restrict__ qk_dw_w, const float* __restrict__ qk_dw_b,
    const float* __restrict__ v_dw_w,  const float* __restrict__ v_dw_b)
{
    int idx = blockIdx.x * 256 + threadIdx.x;
    const int NQ = BATCH*384*HW2/4;
    if (idx >= NQ) return;
    int qw = idx % (HWd/4);
    int h  = (idx / (HWd/4)) % HWd;
    int ch = (idx / (HW2/4)) % 384;
    int b  = idx / (384*HW2/4);
    int w0 = qw * 4;

    const float* wgt; float bv;
    if (ch < 256) { wgt = qk_dw_w + ch*9;        bv = qk_dw_b[ch]; }
    else          { wgt = v_dw_w  + (ch-256)*9;  bv = v_dw_b[ch-256]; }
    float k0=wgt[0],k1=wgt[1],k2=wgt[2],k3=wgt[3],k4=wgt[4],k5=wgt[5],k6=wgt[6],k7=wgt[7],k8=wgt[8];

    const float* in = g_buf1 + ((long)(b*384 + ch)) * HW2;
    float r[3][6];
    #pragma unroll
    for (int ky = 0; ky < 3; ky++) {
        int y = h + ky - 1;
        if ((unsigned)y >= (unsigned)HWd) {
            #pragma unroll
            for (int j = 0; j < 6; j++) r[ky][j] = 0.f;
        } else {
            const float* rp = in + (long)y * HWd + w0;
            float4 c = *(const float4*)rp;
            r[ky][1] = c.x; r[ky][2] = c.y; r[ky][3] = c.z; r[ky][4] = c.w;
            r[ky][0] = (w0 > 0)        ? rp[-1] : 0.f;
            r[ky][5] = (w0 + 4 < HWd)  ? rp[4]  : 0.f;
        }
    }
    float4 o;
    float* op = (float*)&o;
    #pragma unroll
    for (int j = 0; j < 4; j++) {
        op[j] = bv
              + k0*r[0][j] + k1*r[0][j+1] + k2*r[0][j+2]
              + k3*r[1][j] + k4*r[1][j+1] + k5*r[1][j+2]
              + k6*r[2][j] + k7*r[2][j+1] + k8*r[2][j+2];
    }
    *(float4*)&g_buf2[(long)idx*4] = o;
}

// ---------------- depthwise 4x4 stride4 pad1 ----------------------------------
__global__ void dw4x4(const float* __restrict__ q2_dw_w, const float* __restrict__ q2_dw_b,
                      const float* __restrict__ k2_dw_w, const float* __restrict__ k2_dw_b)
{
    int idx = blockIdx.x * 256 + threadIdx.x;
    if (idx >= BATCH*512*Ntok) return;
    int t  = idx % Ntok;
    int ch = (idx / Ntok) % 512;
    int b  = idx / (512*Ntok);
    int oy = t / HGd, ox = t % HGd;
    const float* wgt; float bv;
    if (ch < 256) { wgt = q2_dw_w + ch*16;       bv = q2_dw_b[ch]; }
    else          { wgt = k2_dw_w + (ch-256)*16; bv = k2_dw_b[ch-256]; }
    const float* in = g_buf3 + ((long)(b*512 + ch)) * HW2;
    float s = bv;
    #pragma unroll
    for (int ky = 0; ky < 4; ky++) {
        int y = oy*4 - 1 + ky;
        if ((unsigned)y >= (unsigned)HWd) continue;
        #pragma unroll
        for (int kx = 0; kx < 4; kx++) {
            int x = ox*4 - 1 + kx;
            if ((unsigned)x >= (unsigned)HWd) continue;
            s += wgt[ky*4+kx] * in[y*HWd + x];
        }
    }
    g_buf4[idx] = s;
}

// ---------------- l2 normalize + token-major q/k (shfl reductions) ------------
__global__ void __launch_bounds__(256) norm_qk(float* __restrict__ kout,
                                               const float* __restrict__ temp)
{
    int token = blockIdx.x, b = blockIdx.y, d = threadIdx.x;
    int lane = d & 31, wid = d >> 5;
    float qv = g_buf4[((long)b*512 + d)       * Ntok + token];
    float kv = g_buf4[((long)b*512 + 256 + d) * Ntok + token];
    __shared__ float wsumq[8], wsumk[8];
    __shared__ float qinv_s, kinv_s;
    float sq = qv*qv, sk = kv*kv;
    #pragma unroll
    for (int o = 16; o > 0; o >>= 1) {
        sq += __shfl_xor_sync(0xffffffffu, sq, o);
        sk += __shfl_xor_sync(0xffffffffu, sk, o);
    }
    if (lane == 0) { wsumq[wid] = sq; wsumk[wid] = sk; }
    __syncthreads();
    if (d < 32) {
        float tq = (lane < 8) ? wsumq[lane] : 0.f;
        float tk = (lane < 8) ? wsumk[lane] : 0.f;
        #pragma unroll
        for (int o = 4; o > 0; o >>= 1) {
            tq += __shfl_xor_sync(0xffffffffu, tq, o);
            tk += __shfl_xor_sync(0xffffffffu, tk, o);
        }
        if (lane == 0) {
            qinv_s = (*temp) / fmaxf(sqrtf(tq), 1e-12f);
            kinv_s = 1.f / fmaxf(sqrtf(tk), 1e-12f);
        }
    }
    __syncthreads();
    g_qtok[((long)b*Ntok + token) * D2 + d] = qv * qinv_s;
    kout  [((long)(b*2 + 1)*Ntok + token) * D2 + d] = kv * kinv_s;
}

// ---------------- build v_new: smem-transposed (coalesced both sides) ---------
__global__ void __launch_bounds__(256) build_vnew_t(float* __restrict__ vout)
{
    int hi = blockIdx.x;
    int pp = blockIdx.y;
    int b  = blockIdx.z;
    int p1 = pp >> 2, p2 = pp & 3;
    int tid = threadIdx.x;
    __shared__ float ts[48][129];

    const float* src = g_buf2 + ((long)(b*384 + 256)) * HW2
                       + (long)(p1*HGd + hi) * HWd + p2*HGd;
    for (int i = tid; i < 128*48; i += 256) {
        int c = i / 48, wi = i - c*48;
        ts[wi][c] = src[(long)c * HW2 + wi];
    }
    __syncthreads();
    float* dst = vout + ((long)(b*2 + 1)*Ntok + hi*HGd) * VDdim + p1*512 + p2*128;
    for (int i = tid; i < 48*32; i += 256) {
        int wi = i >> 5, c4 = (i & 31) * 4;
        float4 v = make_float4(ts[wi][c4], ts[wi][c4+1], ts[wi][c4+2], ts[wi][c4+3]);
        *(float4*)&dst[(long)wi * VDdim + c4] = v;
    }
}

// =============================================================================
// sparse_select: single-pass. Pass 1 = pure top-5 (val,idx) scan. Merge -> kth.
// Locals gathered directly via 41 diamond offsets; top-k appended from
// per-thread register candidates (val >= kth, nonlocal). No second row scan.
// =============================================================================
__global__ void __launch_bounds__(256) sparse_select()
{
    int n = blockIdx.x, f = blockIdx.y, b = blockIdx.z;
    int z = b*NFtot + f;
    int rowid = z * Ntok + n;
    const float* arow = g_attn + (long)rowid * Ntok;
    int tid = threadIdx.x;
    int ny = n / HGd, nx = n % HGd;

    __shared__ float cand[256*5];
    __shared__ float bcast;
    __shared__ int   nnz;
    __shared__ int   sidx[SELCAP];
    __shared__ float sval[SELCAP];

    if (tid == 0) nnz = 0;

    // pass 1: top-5 (val, idx) directly from gmem
    float t5v[5] = {-INFINITY,-INFINITY,-INFINITY,-INFINITY,-INFINITY};
    int   t5i[5] = {0,0,0,0,0};
    for (int m4 = tid*4; m4 < Ntok; m4 += 1024) {
        float4 v4 = *(const float4*)&arow[m4];
        float vv[4] = {v4.x, v4.y, v4.z, v4.w};
        #pragma unroll
        for (int u = 0; u < 4; u++) {
            float v = vv[u];
            if (v > t5v[4]) {
                t5v[4] = v; t5i[4] = m4 + u;
                #pragma unroll
                for (int i = 4; i > 0; i--)
                    if (t5v[i] > t5v[i-1]) {
                        float tv = t5v[i-1]; t5v[i-1] = t5v[i]; t5v[i] = tv;
                        int   ti = t5i[i-1]; t5i[i-1] = t5i[i]; t5i[i] = ti;
                    }
            }
        }
    }
    #pragma unroll
    for (int i = 0; i < 5; i++) cand[tid*5 + i] = t5v[i];
    __syncthreads();

    // warp 0 merges 1280 candidate values -> kth largest
    if (tid < 32) {
        float l5[5] = {-INFINITY,-INFINITY,-INFINITY,-INFINITY,-INFINITY};
        const float* cp = cand + tid*40;
        #pragma unroll
        for (int i = 0; i < 40; i++) {
            float v = cp[i];
            if (v > l5[4]) {
                l5[4] = v;
                #pragma unroll
                for (int j = 4; j > 0; j--)
                    if (l5[j] > l5[j-1]) { float tmp = l5[j-1]; l5[j-1] = l5[j]; l5[j] = tmp; }
            }
        }
        float thr = INFINITY;
        #pragma unroll
        for (int r = 0; r < 5; r++) {
            float lm = -INFINITY;
            #pragma unroll
            for (int i = 0; i < 5; i++) {
                float v = l5[i];
                if (v < thr && v > lm) lm = v;
            }
            #pragma unroll
            for (int o = 16; o > 0; o >>= 1)
                lm = fmaxf(lm, __shfl_xor_sync(0xffffffffu, lm, o));
            thr = lm;
        }
        if (tid == 0) bcast = thr;
    }
    __syncthreads();
    float kth = bcast;

    // local diamond gather (41 offsets, direct indexing)
    if (tid < 41) {
        int r = tid, dy = 0;
        for (int d = -4; d <= 4; d++) {
            int sz = 9 - 2*abs(d);
            if (r < sz) { dy = d; break; }
            r -= sz;
        }
        int dx = r - (4 - abs(dy));
        int my = ny + dy, mx = nx + dx;
        if ((unsigned)my < (unsigned)HGd && (unsigned)mx < (unsigned)HGd) {
            int m = my*HGd + mx;
            float a = arow[m];
            float v = a * ((a >= kth) ? 2.f : 1.f);
            if (v != 0.f) {
                int pos = atomicAdd(&nnz, 1);
                sidx[pos] = m; sval[pos] = v;
            }
        }
    }
    // top-k append from register candidates (nonlocal only)
    #pragma unroll
    for (int i = 0; i < 5; i++) {
        float v = t5v[i];
        if (v >= kth && v != 0.f) {
            int m = t5i[i];
            int my = m / HGd, mx = m % HGd;
            if (abs(ny - my) + abs(nx - mx) > 4) {
                int pos = atomicAdd(&nnz, 1);
                sidx[pos] = m; sval[pos] = v;
            }
        }
    }
    __syncthreads();
    int cnt = min(nnz, SELCAP);

    // softmax via warp 0
    if (tid < 32) {
        float mx = -INFINITY;
        for (int e = tid; e < cnt; e += 32) mx = fmaxf(mx, sval[e]);
        #pragma unroll
        for (int o = 16; o > 0; o >>= 1)
            mx = fmaxf(mx, __shfl_xor_sync(0xffffffffu, mx, o));
        if (tid == 0) bcast = mx;
    }
    __syncthreads();
    float mxv = bcast;
    if (tid < cnt) sval[tid] = expf(sval[tid] - mxv);
    __syncthreads();
    if (tid < 32) {
        float s = 0.f;
        for (int e = tid; e < cnt; e += 32) s += sval[e];
        #pragma unroll
        for (int o = 16; o > 0; o >>= 1)
            s += __shfl_xor_sync(0xffffffffu, s, o);
        if (tid == 0) bcast = s;
    }
    __syncthreads();
    if (tid < cnt) {
        g_selidx[(long)rowid*SELCAP + tid] = sidx[tid];
        g_selw  [(long)rowid*SELCAP + tid] = sval[tid] / bcast;
    }
    if (tid == 0) g_selcnt[rowid] = cnt;
}

// =============================================================================
// sparse_av8: 2x4 query tile (8 queries), union gather (round-13 winner)
// =============================================================================
__global__ void __launch_bounds__(256) sparse_av8(
    const float* __restrict__ v_cached, const float* __restrict__ vout)
{
    int chunk = blockIdx.x;
    int tile  = blockIdx.y;
    int z     = blockIdx.z;
    int b = z / NFtot, f = z % NFtot;
    int qy0 = (tile / 12) * 2, qx0 = (tile % 12) * 4;
    int tid = threadIdx.x;

    __shared__ int   sidx[8][SELCAP];
    __shared__ float sval[8][SELCAP];
    __shared__ int   scnt[8];
    __shared__ unsigned umask[72];
    __shared__ int   ubase[73];
    __shared__ int   uidx[MAXU];
    __shared__ float Wt[8][MAXU];

    if (tid < 72) umask[tid] = 0;
    int rowbase = z * Ntok;
    if (tid < 8) {
        int q = tid;
        int n = (qy0 + (q >> 2)) * HGd + qx0 + (q & 3);
        scnt[q] = g_selcnt[rowbase + n];
    }
    __syncthreads();
    for (int i = tid; i < 8 * SELCAP; i += 256) {
        int q = i >> 6, e = i & (SELCAP-1);
        if (e < scnt[q]) {
            int n = (qy0 + (q >> 2)) * HGd + qx0 + (q & 3);
            long base = (long)(rowbase + n) * SELCAP + e;
            int m = g_selidx[base];
            sidx[q][e] = m;
            sval[q][e] = g_selw[base];
            atomicOr(&umask[m >> 5], 1u << (m & 31));
        }
    }
    __syncthreads();
    if (tid == 0) {
        int s = 0;
        for (int w = 0; w < 72; w++) { ubase[w] = s; s += __popc(umask[w]); }
        ubase[72] = s;
    }
    __syncthreads();
    int U = min(ubase[72], MAXU);

    for (int i = tid; i < 8*MAXU; i += 256) ((float*)Wt)[i] = 0.f;
    __syncthreads();
    if (tid < 72) {
        unsigned bits = umask[tid];
        int pos = ubase[tid];
        while (bits) {
            int bit = __ffs(bits) - 1; bits &= bits - 1;
            if (pos < MAXU) uidx[pos] = tid*32 + bit;
            pos++;
        }
    }
    __syncthreads();
    for (int i = tid; i < 8*SELCAP; i += 256) {
        int q = i >> 6, e = i & (SELCAP-1);
        if (e < scnt[q]) {
            int m = sidx[q][e];
            int w32 = m >> 5, bit = m & 31;
            int rank = ubase[w32] + __popc(umask[w32] & ((1u << bit) - 1u));
            if (rank < MAXU) Wt[q][rank] = sval[q][e];
        }
    }
    __syncthreads();

    const float* vbase = (f < 2) ? (v_cached + ((long)(b*2 + f)) * Ntok * VDdim)
                                 : (vout     + ((long)(b*2 + 1)) * Ntok * VDdim);
    int d0 = chunk * 1024 + tid * 4;
    u64 acc[8][2] = {};
    for (int e = 0; e < U; e++) {
        int m = uidx[e];
        ulonglong2 vv = *(const ulonglong2*)(vbase + (long)m * VDdim + d0);
        #pragma unroll
        for (int q = 0; q < 8; q++) {
            u64 wq = dup2(Wt[q][e]);
            fma2(acc[q][0], wq, vv.x);
            fma2(acc[q][1], wq, vv.y);
        }
    }
    #pragma unroll
    for (int q = 0; q < 8; q++) {
        int n = (qy0 + (q >> 2)) * HGd + qx0 + (q & 3);
        float2 p0 = unpk(acc[q][0]), p1 = unpk(acc[q][1]);
        float* orow = g_otok + ((long)(rowbase + n)) * VDdim + d0;
        *(float4*)orow = make_float4(p0.x, p0.y, p1.x, p1.y);
    }
}

// ---------------------------------- launch -----------------------------------
extern "C" void kernel_launch(void* const* d_in, const int* in_sizes, int n_in,
                              void* d_out, int out_size)
{
    (void)in_sizes; (void)n_in; (void)out_size;
    const float* x         = (const float*)d_in[0];
    const float* k_cached  = (const float*)d_in[1];
    const float* v_cached  = (const float*)d_in[2];
    const float* temperature = (const float*)d_in[3];
    const float* qk_w  = (const float*)d_in[4],  *qk_b  = (const float*)d_in[5];
    const float* qk_dw_w = (const float*)d_in[6], *qk_dw_b = (const float*)d_in[7];
    const float* v_w   = (const float*)d_in[8],  *v_b   = (const float*)d_in[9];
    const float* v_dw_w = (const float*)d_in[10], *v_dw_b = (const float*)d_in[11];
    const float* k2_w  = (const float*)d_in[12], *k2_b  = (const float*)d_in[13];
    const float* k2_dw_w = (const float*)d_in[14], *k2_dw_b = (const float*)d_in[15];
    const float* q2_w  = (const float*)d_in[16], *q2_b  = (const float*)d_in[17];
    const float* q2_dw_w = (const float*)d_in[18], *q2_dw_b = (const float*)d_in[19];
    const float* proj_w = (const float*)d_in[20], *proj_b = (const float*)d_in[21];

    float* out = (float*)d_out;
    const long OUT_K = (long)BATCH * NFtot * 128 * HW2;
    const long OUT_V = OUT_K + (long)BATCH * 2 * Ntok * D2;
    float* kout = out + OUT_K;
    float* vout = out + OUT_V;

    dim3 blk(256);

    gemm_stageA<<<dim3(288,3,BATCH), blk>>>(x, qk_w, qk_b, v_w, v_b);
    dw3x3v<<<(BATCH*384*HW2/4 + 255)/256, blk>>>(qk_dw_w, qk_dw_b, v_dw_w, v_dw_b);
    gemm_stageC<<<dim3(288,4,BATCH), blk>>>(q2_w, q2_b, k2_w, k2_b);
    dw4x4<<<(BATCH*512*Ntok + 255)/256, blk>>>(q2_dw_w, q2_dw_b, k2_dw_w, k2_dw_b);
    norm_qk<<<dim3(Ntok, BATCH), blk>>>(kout, temperature);
    build_vnew_t<<<dim3(HGd, 16, BATCH), blk>>>(vout);
    for (int b = 0; b < BATCH; b++) {
        cudaMemcpyAsync(kout + (long)(b*2)*Ntok*D2,
                        k_cached + (long)(b*2+1)*Ntok*D2,
                        (size_t)Ntok*D2*sizeof(float), cudaMemcpyDeviceToDevice, 0);
        cudaMemcpyAsync(vout + (long)(b*2)*Ntok*VDdim,
                        v_cached + (long)(b*2+1)*Ntok*VDdim,
                        (size_t)Ntok*VDdim*sizeof(float), cudaMemcpyDeviceToDevice, 0);
    }
    attn_gemm2<<<dim3(18,18,BATCH*NFtot), blk>>>(k_cached, kout);
    sparse_select<<<dim3(Ntok, NFtot, BATCH), blk>>>();
    sparse_av8<<<dim3(2, 288, BATCH*NFtot), blk>>>(v_cached, vout);
    proj_gemm2<<<dim3(288,1,BATCH*NFtot), blk>>>(proj_w, proj_b, out);
}

// round 16
// speedup vs baseline: 1.5795x; 1.0055x over previous
#include <cuda_runtime.h>
#include <math.h>

#define BATCH 2
#define HWd   192
#define HW2   (HWd*HWd)      // 36864
#define HGd   48
#define Ntok  (HGd*HGd)      // 2304
#define D2    256
#define VDdim 2048
#define NFtot 3
#define SELCAP 64
#define MAXU   128
#define NROWS (BATCH*NFtot*Ntok)

typedef unsigned long long u64;

// ---------------- scratch (device globals; no allocs allowed) ----------------
__device__ float g_buf1[(size_t)BATCH*384*HW2];
__device__ float g_buf2[(size_t)BATCH*384*HW2];
__device__ float g_buf3[(size_t)BATCH*512*HW2];
__device__ float g_buf4[(size_t)BATCH*512*Ntok];
__device__ float g_qtok[(size_t)BATCH*Ntok*D2];
__device__ float g_attn[(size_t)BATCH*NFtot*Ntok*Ntok];
__device__ float g_otok[(size_t)BATCH*NFtot*Ntok*VDdim];
__device__ int   g_selidx[(size_t)NROWS*SELCAP];
__device__ float g_selw  [(size_t)NROWS*SELCAP];
__device__ int   g_selcnt[NROWS];

// ---------------- packed fp32x2 primitives (Blackwell FFMA2) -----------------
__device__ __forceinline__ u64 dup2(float x) {
    u64 r;
    asm("mov.b64 %0, {%1, %1};" : "=l"(r) : "r"(__float_as_uint(x)));
    return r;
}
__device__ __forceinline__ void fma2(u64 &d, u64 a, u64 b) {
    asm("fma.rn.f32x2 %0, %1, %2, %3;" : "=l"(d) : "l"(a), "l"(b), "l"(d));
}
__device__ __forceinline__ float2 unpk(u64 v) {
    float lo, hi;
    asm("mov.b64 {%0, %1}, %2;" : "=f"(lo), "=f"(hi) : "l"(v));
    return make_float2(lo, hi);
}

// one k-step of the 8x8 fragment: 32 fma.f32x2
__device__ __forceinline__ void fma_step(
    const float* __restrict__ As_k, const float* __restrict__ Bs_k,
    int tx, int ty, u64 acc[8][4])
{
    float4 av0 = *(const float4*)(As_k + ty*4);
    float4 av1 = *(const float4*)(As_k + 64 + ty*4);
    ulonglong2 bv0 = *(const ulonglong2*)(Bs_k + tx*4);
    ulonglong2 bv1 = *(const ulonglong2*)(Bs_k + 64 + tx*4);
    u64 aa[8] = {dup2(av0.x), dup2(av0.y), dup2(av0.z), dup2(av0.w),
                 dup2(av1.x), dup2(av1.y), dup2(av1.z), dup2(av1.w)};
    u64 bb[4] = {bv0.x, bv0.y, bv1.x, bv1.y};
    #pragma unroll
    for (int i = 0; i < 8; i++) {
        fma2(acc[i][0], aa[i], bb[0]);
        fma2(acc[i][1], aa[i], bb[1]);
        fma2(acc[i][2], aa[i], bb[2]);
        fma2(acc[i][3], aa[i], bb[3]);
    }
}

// =============================================================================
// double-buffered conv GEMM body
// =============================================================================
__device__ __forceinline__ void gemm_db_conv2(
    const float* __restrict__ A, const float* __restrict__ Bbase, int K,
    float (* __restrict__ As)[16][132], float (* __restrict__ Bs)[16][128],
    int t, u64 acc[8][4])
{
    int arow = t >> 1, akq = (t & 1) * 8;
    int bk = t >> 4, bn = (t & 15) * 4;
    int tx = t & 15, ty = t >> 4;
    const float* Ap = A + (long)arow * K + akq;

    float4 a0 = *(const float4*)(Ap);
    float4 a1 = *(const float4*)(Ap + 4);
    const float* bs0 = Bbase + (long)bk * HW2;
    float4 b0 = *(const float4*)(bs0 + bn);
    float4 b1 = *(const float4*)(bs0 + bn + 64);
    As[0][akq+0][arow]=a0.x; As[0][akq+1][arow]=a0.y; As[0][akq+2][arow]=a0.z; As[0][akq+3][arow]=a0.w;
    As[0][akq+4][arow]=a1.x; As[0][akq+5][arow]=a1.y; As[0][akq+6][arow]=a1.z; As[0][akq+7][arow]=a1.w;
    *(float4*)&Bs[0][bk][bn]    = b0;
    *(float4*)&Bs[0][bk][bn+64] = b1;
    __syncthreads();
    int buf = 0;
    for (int k0 = 16; k0 <= K; k0 += 16) {
        if (k0 < K) {
            a0 = *(const float4*)(Ap + k0);
            a1 = *(const float4*)(Ap + k0 + 4);
            const float* bs2 = Bbase + (long)(k0 + bk) * HW2;
            b0 = *(const float4*)(bs2 + bn);
            b1 = *(const float4*)(bs2 + bn + 64);
        }
        #pragma unroll
        for (int kk = 0; kk < 16; kk++)
            fma_step(&As[buf][kk][0], &Bs[buf][kk][0], tx, ty, acc);
        if (k0 < K) {
            int nb = buf ^ 1;
            As[nb][akq+0][arow]=a0.x; As[nb][akq+1][arow]=a0.y; As[nb][akq+2][arow]=a0.z; As[nb][akq+3][arow]=a0.w;
            As[nb][akq+4][arow]=a1.x; As[nb][akq+5][arow]=a1.y; As[nb][akq+6][arow]=a1.z; As[nb][akq+7][arow]=a1.w;
            *(float4*)&Bs[nb][bk][bn]    = b0;
            *(float4*)&Bs[nb][bk][bn+64] = b1;
            __syncthreads();
            buf = nb;
        }
    }
}

// =============================================================================
// double-buffered TT GEMM body
// =============================================================================
__device__ __forceinline__ void gemm_db_tt2(
    const float* __restrict__ Abase, const float* __restrict__ Bbase, int K,
    float (* __restrict__ As)[16][132], float (* __restrict__ Bs)[16][132],
    int t, u64 acc[8][4])
{
    int row = t >> 1, kq = (t & 1) * 8;
    int tx = t & 15, ty = t >> 4;
    const float* Ap = Abase + (long)row * K + kq;
    const float* Bp = Bbase + (long)row * K + kq;

    float4 a0 = *(const float4*)(Ap);
    float4 a1 = *(const float4*)(Ap + 4);
    float4 b0 = *(const float4*)(Bp);
    float4 b1 = *(const float4*)(Bp + 4);
    As[0][kq+0][row]=a0.x; As[0][kq+1][row]=a0.y; As[0][kq+2][row]=a0.z; As[0][kq+3][row]=a0.w;
    As[0][kq+4][row]=a1.x; As[0][kq+5][row]=a1.y; As[0][kq+6][row]=a1.z; As[0][kq+7][row]=a1.w;
    Bs[0][kq+0][row]=b0.x; Bs[0][kq+1][row]=b0.y; Bs[0][kq+2][row]=b0.z; Bs[0][kq+3][row]=b0.w;
    Bs[0][kq+4][row]=b1.x; Bs[0][kq+5][row]=b1.y; Bs[0][kq+6][row]=b1.z; Bs[0][kq+7][row]=b1.w;
    __syncthreads();
    int buf = 0;
    for (int k0 = 16; k0 <= K; k0 += 16) {
        if (k0 < K) {
            a0 = *(const float4*)(Ap + k0);
            a1 = *(const float4*)(Ap + k0 + 4);
            b0 = *(const float4*)(Bp + k0);
            b1 = *(const float4*)(Bp + k0 + 4);
        }
        #pragma unroll
        for (int kk = 0; kk < 16; kk++)
            fma_step(&As[buf][kk][0], &Bs[buf][kk][0], tx, ty, acc);
        if (k0 < K) {
            int nb = buf ^ 1;
            As[nb][kq+0][row]=a0.x; As[nb][kq+1][row]=a0.y; As[nb][kq+2][row]=a0.z; As[nb][kq+3][row]=a0.w;
            As[nb][kq+4][row]=a1.x; As[nb][kq+5][row]=a1.y; As[nb][kq+6][row]=a1.z; As[nb][kq+7][row]=a1.w;
            Bs[nb][kq+0][row]=b0.x; Bs[nb][kq+1][row]=b0.y; Bs[nb][kq+2][row]=b0.z; Bs[nb][kq+3][row]=b0.w;
            Bs[nb][kq+4][row]=b1.x; Bs[nb][kq+5][row]=b1.y; Bs[nb][kq+6][row]=b1.z; Bs[nb][kq+7][row]=b1.w;
            __syncthreads();
            buf = nb;
        }
    }
}

__device__ __forceinline__ void gemm128_store2(
    float* __restrict__ Crow, const float* __restrict__ bias,
    int t, u64 acc[8][4], long ldc)
{
    int tx = t & 15, ty = t >> 4;
    #pragma unroll
    for (int i = 0; i < 8; i++) {
        int m = (i < 4) ? (ty*4 + i) : (64 + ty*4 + i - 4);
        float bv = bias ? bias[m] : 0.f;
        float2 p0 = unpk(acc[i][0]), p1 = unpk(acc[i][1]);
        float2 p2 = unpk(acc[i][2]), p3 = unpk(acc[i][3]);
        float4 o0 = {p0.x+bv, p0.y+bv, p1.x+bv, p1.y+bv};
        float4 o1 = {p2.x+bv, p2.y+bv, p3.x+bv, p3.y+bv};
        *(float4*)&Crow[(long)m*ldc + tx*4]      = o0;
        *(float4*)&Crow[(long)m*ldc + 64 + tx*4] = o1;
    }
}

// stage A
__global__ void __launch_bounds__(256,2) gemm_stageA(
    const float* __restrict__ x,
    const float* __restrict__ qk_w, const float* __restrict__ qk_b,
    const float* __restrict__ v_w,  const float* __restrict__ v_b)
{
    int n0 = blockIdx.x * 128, y = blockIdx.y, b = blockIdx.z;
    int t = threadIdx.x;
    __shared__ float As[2][16][132];
    __shared__ float Bs[2][16][128];
    u64 acc[8][4] = {};
    const float* A   = (y < 2) ? (qk_w + (long)y*128*128) : v_w;
    const float* bia = (y < 2) ? (qk_b + y*128)           : v_b;
    int cch          = (y < 2) ? (y*128)                  : 256;
    gemm_db_conv2(A, x + (long)b*128*HW2 + n0, 128, As, Bs, t, acc);
    gemm128_store2(g_buf1 + ((long)b*384 + cch) * HW2 + n0, bia, t, acc, HW2);
}

// stage C
__global__ void __launch_bounds__(256,2) gemm_stageC(
    const float* __restrict__ q2_w, const float* __restrict__ q2_b,
    const float* __restrict__ k2_w, const float* __restrict__ k2_b)
{
    int n0 = blockIdx.x * 128, y = blockIdx.y, b = blockIdx.z;
    int t = threadIdx.x;
    __shared__ float As[2][16][132];
    __shared__ float Bs[2][16][128];
    u64 acc[8][4] = {};
    const float* A   = (y < 2) ? (q2_w + (long)y*128*128) : (k2_w + (long)(y-2)*128*128);
    const float* bia = (y < 2) ? (q2_b + y*128)           : (k2_b + (y-2)*128);
    const float* Bbase = g_buf2 + ((long)b*384 + ((y < 2) ? 0 : 128)) * HW2 + n0;
    gemm_db_conv2(A, Bbase, 128, As, Bs, t, acc);
    gemm128_store2(g_buf3 + ((long)b*512 + y*128) * HW2 + n0, bia, t, acc, HW2);
}

// attention GEMM
__global__ void __launch_bounds__(256,2) attn_gemm2(
    const float* __restrict__ kc, const float* __restrict__ knew)
{
    int z = blockIdx.z; int b = z / NFtot, f = z % NFtot;
    const float* Qp = g_qtok + (long)b * Ntok * D2;
    const float* Kp = (f < 2) ? (kc   + ((long)(b*2 + f)) * Ntok * D2)
                              : (knew + ((long)(b*2 + 1)) * Ntok * D2);
    int m0 = blockIdx.y * 128, n0 = blockIdx.x * 128;
    int t = threadIdx.x;
    int tx = t & 15, ty = t >> 4;
    __shared__ float As[2][16][132];
    __shared__ float Bs[2][16][132];
    u64 acc[8][4] = {};
    gemm_db_tt2(Qp + (long)m0 * D2, Kp + (long)n0 * D2, D2, As, Bs, t, acc);
    float* Cp = g_attn + (long)z * Ntok * Ntok;
    #pragma unroll
    for (int i = 0; i < 8; i++) {
        int m = (i < 4) ? (ty*4 + i) : (64 + ty*4 + i - 4);
        float2 p0 = unpk(acc[i][0]), p1 = unpk(acc[i][1]);
        float2 p2 = unpk(acc[i][2]), p3 = unpk(acc[i][3]);
        float4 o0 = {p0.x, p0.y, p1.x, p1.y};
        float4 o1 = {p2.x, p2.y, p3.x, p3.y};
        *(float4*)&Cp[(long)(m0+m)*Ntok + n0 + tx*4]      = o0;
        *(float4*)&Cp[(long)(m0+m)*Ntok + n0 + 64 + tx*4] = o1;
    }
}

// proj 1x1 GEMM with fused window de-permute gather
__global__ void __launch_bounds__(256,2) proj_gemm2(
    const float* __restrict__ W, const float* __restrict__ bias,
    float* __restrict__ Out)
{
    int z  = blockIdx.z;
    int n0 = blockIdx.x * 128;
    int t = threadIdx.x;
    int tx = t & 15, ty = t >> 4;
    __shared__ float As[2][16][132];
    __shared__ float Bs[2][16][132];
    u64 acc[8][4] = {};
    int row = t >> 1;
    int p = n0 + row;
    int h = p / HWd, w = p % HWd;
    int token = (h % HGd) * HGd + (w % HGd);
    int vbase = ((h / HGd) * 4 + (w / HGd)) * 128;
    {
        int kq = (t & 1) * 8;
        const float* Ap = W + (long)row * 128 + kq;
        const float* Bp = g_otok + ((long)z * Ntok + token) * VDdim + vbase + kq;
        float4 a0 = *(const float4*)(Ap);
        float4 a1 = *(const float4*)(Ap + 4);
        float4 b0 = *(const float4*)(Bp);
        float4 b1 = *(const float4*)(Bp + 4);
        As[0][kq+0][row]=a0.x; As[0][kq+1][row]=a0.y; As[0][kq+2][row]=a0.z; As[0][kq+3][row]=a0.w;
        As[0][kq+4][row]=a1.x; As[0][kq+5][row]=a1.y; As[0][kq+6][row]=a1.z; As[0][kq+7][row]=a1.w;
        Bs[0][kq+0][row]=b0.x; Bs[0][kq+1][row]=b0.y; Bs[0][kq+2][row]=b0.z; Bs[0][kq+3][row]=b0.w;
        Bs[0][kq+4][row]=b1.x; Bs[0][kq+5][row]=b1.y; Bs[0][kq+6][row]=b1.z; Bs[0][kq+7][row]=b1.w;
        __syncthreads();
        int buf = 0;
        for (int k0 = 16; k0 <= 128; k0 += 16) {
            if (k0 < 128) {
                a0 = *(const float4*)(Ap + k0);
                a1 = *(const float4*)(Ap + k0 + 4);
                b0 = *(const float4*)(Bp + k0);
                b1 = *(const float4*)(Bp + k0 + 4);
            }
            #pragma unroll
            for (int kk = 0; kk < 16; kk++)
                fma_step(&As[buf][kk][0], &Bs[buf][kk][0], tx, ty, acc);
            if (k0 < 128) {
                int nb = buf ^ 1;
                As[nb][kq+0][row]=a0.x; As[nb][kq+1][row]=a0.y; As[nb][kq+2][row]=a0.z; As[nb][kq+3][row]=a0.w;
                As[nb][kq+4][row]=a1.x; As[nb][kq+5][row]=a1.y; As[nb][kq+6][row]=a1.z; As[nb][kq+7][row]=a1.w;
                Bs[nb][kq+0][row]=b0.x; Bs[nb][kq+1][row]=b0.y; Bs[nb][kq+2][row]=b0.z; Bs[nb][kq+3][row]=b0.w;
                Bs[nb][kq+4][row]=b1.x; Bs[nb][kq+5][row]=b1.y; Bs[nb][kq+6][row]=b1.z; Bs[nb][kq+7][row]=b1.w;
                __syncthreads();
                buf = nb;
            }
        }
    }
    #pragma unroll
    for (int i = 0; i < 8; i++) {
        int m = (i < 4) ? (ty*4 + i) : (64 + ty*4 + i - 4);
        float bv = bias[m];
        float2 p0 = unpk(acc[i][0]), p1 = unpk(acc[i][1]);
        float2 p2 = unpk(acc[i][2]), p3 = unpk(acc[i][3]);
        float4 o0 = {p0.x+bv, p0.y+bv, p1.x+bv, p1.y+bv};
        float4 o1 = {p2.x+bv, p2.y+bv, p3.x+bv, p3.y+bv};
        *(float4*)&Out[((long)z*128 + m)*HW2 + n0 + tx*4]      = o0;
        *(float4*)&Out[((long)z*128 + m)*HW2 + n0 + 64 + tx*4] = o1;
    }
}

// ---------------- depthwise 3x3 pad1, 4 pixels/thread -------------------------
__global__ void __launch_bounds__(256) dw3x3v(
    const float* __restrict__ qk_dw_w, const float* __restrict__ qk_dw_b,
    const float* __restrict__ v_dw_w,  const float* __restrict__ v_dw_b)
{
    int idx = blockIdx.x * 256 + threadIdx.x;
    const int NQ = BATCH*384*HW2/4;
    if (idx >= NQ) return;
    int qw = idx % (HWd/4);
    int h  = (idx / (HWd/4)) % HWd;
    int ch = (idx / (HW2/4)) % 384;
    int b  = idx / (384*HW2/4);
    int w0 = qw * 4;

    const float* wgt; float bv;
    if (ch < 256) { wgt = qk_dw_w + ch*9;        bv = qk_dw_b[ch]; }
    else          { wgt = v_dw_w  + (ch-256)*9;  bv = v_dw_b[ch-256]; }
    float k0=wgt[0],k1=wgt[1],k2=wgt[2],k3=wgt[3],k4=wgt[4],k5=wgt[5],k6=wgt[6],k7=wgt[7],k8=wgt[8];

    const float* in = g_buf1 + ((long)(b*384 + ch)) * HW2;
    float r[3][6];
    #pragma unroll
    for (int ky = 0; ky < 3; ky++) {
        int y = h + ky - 1;
        if ((unsigned)y >= (unsigned)HWd) {
            #pragma unroll
            for (int j = 0; j < 6; j++) r[ky][j] = 0.f;
        } else {
            const float* rp = in + (long)y * HWd + w0;
            float4 c = *(const float4*)rp;
            r[ky][1] = c.x; r[ky][2] = c.y; r[ky][3] = c.z; r[ky][4] = c.w;
            r[ky][0] = (w0 > 0)        ? rp[-1] : 0.f;
            r[ky][5] = (w0 + 4 < HWd)  ? rp[4]  : 0.f;
        }
    }
    float4 o;
    float* op = (float*)&o;
    #pragma unroll
    for (int j = 0; j < 4; j++) {
        op[j] = bv
              + k0*r[0][j] + k1*r[0][j+1] + k2*r[0][j+2]
              + k3*r[1][j] + k4*r[1][j+1] + k5*r[1][j+2]
              + k6*r[2][j] + k7*r[2][j+1] + k8*r[2][j+2];
    }
    *(float4*)&g_buf2[(long)idx*4] = o;
}

// ---------------- depthwise 4x4 stride4 pad1 ----------------------------------
__global__ void dw4x4(const float* __restrict__ q2_dw_w, const float* __restrict__ q2_dw_b,
                      const float* __restrict__ k2_dw_w, const float* __restrict__ k2_dw_b)
{
    int idx = blockIdx.x * 256 + threadIdx.x;
    if (idx >= BATCH*512*Ntok) return;
    int t  = idx % Ntok;
    int ch = (idx / Ntok) % 512;
    int b  = idx / (512*Ntok);
    int oy = t / HGd, ox = t % HGd;
    const float* wgt; float bv;
    if (ch < 256) { wgt = q2_dw_w + ch*16;       bv = q2_dw_b[ch]; }
    else          { wgt = k2_dw_w + (ch-256)*16; bv = k2_dw_b[ch-256]; }
    const float* in = g_buf3 + ((long)(b*512 + ch)) * HW2;
    float s = bv;
    #pragma unroll
    for (int ky = 0; ky < 4; ky++) {
        int y = oy*4 - 1 + ky;
        if ((unsigned)y >= (unsigned)HWd) continue;
        #pragma unroll
        for (int kx = 0; kx < 4; kx++) {
            int x = ox*4 - 1 + kx;
            if ((unsigned)x >= (unsigned)HWd) continue;
            s += wgt[ky*4+kx] * in[y*HWd + x];
        }
    }
    g_buf4[idx] = s;
}

// ---------------- l2 normalize + token-major q/k (shfl reductions) ------------
__global__ void __launch_bounds__(256) norm_qk(float* __restrict__ kout,
                                               const float* __restrict__ temp)
{
    int token = blockIdx.x, b = blockIdx.y, d = threadIdx.x;
    int lane = d & 31, wid = d >> 5;
    float qv = g_buf4[((long)b*512 + d)       * Ntok + token];
    float kv = g_buf4[((long)b*512 + 256 + d) * Ntok + token];
    __shared__ float wsumq[8], wsumk[8];
    __shared__ float qinv_s, kinv_s;
    float sq = qv*qv, sk = kv*kv;
    #pragma unroll
    for (int o = 16; o > 0; o >>= 1) {
        sq += __shfl_xor_sync(0xffffffffu, sq, o);
        sk += __shfl_xor_sync(0xffffffffu, sk, o);
    }
    if (lane == 0) { wsumq[wid] = sq; wsumk[wid] = sk; }
    __syncthreads();
    if (d < 32) {
        float tq = (lane < 8) ? wsumq[lane] : 0.f;
        float tk = (lane < 8) ? wsumk[lane] : 0.f;
        #pragma unroll
        for (int o = 4; o > 0; o >>= 1) {
            tq += __shfl_xor_sync(0xffffffffu, tq, o);
            tk += __shfl_xor_sync(0xffffffffu, tk, o);
        }
        if (lane == 0) {
            qinv_s = (*temp) / fmaxf(sqrtf(tq), 1e-12f);
            kinv_s = 1.f / fmaxf(sqrtf(tk), 1e-12f);
        }
    }
    __syncthreads();
    g_qtok[((long)b*Ntok + token) * D2 + d] = qv * qinv_s;
    kout  [((long)(b*2 + 1)*Ntok + token) * D2 + d] = kv * kinv_s;
}

// ---------------- build v_new: smem-transposed (coalesced both sides) ---------
__global__ void __launch_bounds__(256) build_vnew_t(float* __restrict__ vout)
{
    int hi = blockIdx.x;
    int pp = blockIdx.y;
    int b  = blockIdx.z;
    int p1 = pp >> 2, p2 = pp & 3;
    int tid = threadIdx.x;
    __shared__ float ts[48][129];

    const float* src = g_buf2 + ((long)(b*384 + 256)) * HW2
                       + (long)(p1*HGd + hi) * HWd + p2*HGd;
    for (int i = tid; i < 128*48; i += 256) {
        int c = i / 48, wi = i - c*48;
        ts[wi][c] = src[(long)c * HW2 + wi];
    }
    __syncthreads();
    float* dst = vout + ((long)(b*2 + 1)*Ntok + hi*HGd) * VDdim + p1*512 + p2*128;
    for (int i = tid; i < 48*32; i += 256) {
        int wi = i >> 5, c4 = (i & 31) * 4;
        float4 v = make_float4(ts[wi][c4], ts[wi][c4+1], ts[wi][c4+2], ts[wi][c4+3]);
        *(float4*)&dst[(long)wi * VDdim + c4] = v;
    }
}

// =============================================================================
// sparse_select4: 4 rows per block (64-thread warp-aligned groups).
// Per row: single-pass top-5 scan -> warp merge -> kth; direct diamond gather;
// top-k append from register candidates; warp softmax. grid (576, 3, 2).
// =============================================================================
__global__ void __launch_bounds__(256) sparse_select4()
{
    int f = blockIdx.y, b = blockIdx.z;
    int z = b*NFtot + f;
    int tid = threadIdx.x;
    int g = tid >> 6, lt = tid & 63;
    int n = blockIdx.x * 4 + g;
    int rowid = z * Ntok + n;
    const float* arow = g_attn + (long)rowid * Ntok;
    int ny = n / HGd, nx = n % HGd;

    __shared__ float candv[4][64][5];
    __shared__ float bkth[4], bmax[4], bsum[4];
    __shared__ int   nnz[4];
    __shared__ int   sidx[4][SELCAP];
    __shared__ float sval[4][SELCAP];

    if (lt == 0) nnz[g] = 0;

    // pass 1: top-5 (val, idx); stride 64 threads x float4 = 256, 9 iters
    float t5v[5] = {-INFINITY,-INFINITY,-INFINITY,-INFINITY,-INFINITY};
    int   t5i[5] = {0,0,0,0,0};
    for (int m4 = lt*4; m4 < Ntok; m4 += 256) {
        float4 v4 = *(const float4*)&arow[m4];
        float vv[4] = {v4.x, v4.y, v4.z, v4.w};
        #pragma unroll
        for (int u = 0; u < 4; u++) {
            float v = vv[u];
            if (v > t5v[4]) {
                t5v[4] = v; t5i[4] = m4 + u;
                #pragma unroll
                for (int i = 4; i > 0; i--)
                    if (t5v[i] > t5v[i-1]) {
                        float tv = t5v[i-1]; t5v[i-1] = t5v[i]; t5v[i] = tv;
                        int   ti = t5i[i-1]; t5i[i-1] = t5i[i]; t5i[i] = ti;
                    }
            }
        }
    }
    #pragma unroll
    for (int i = 0; i < 5; i++) candv[g][lt][i] = t5v[i];
    __syncthreads();

    // per-group first warp merges 320 candidate values -> kth largest
    if (lt < 32) {
        float l5[5] = {-INFINITY,-INFINITY,-INFINITY,-INFINITY,-INFINITY};
        const float* cp = &candv[g][lt*2][0];     // 2 slots x 5 = 10 contiguous
        #pragma unroll
        for (int i = 0; i < 10; i++) {
            float v = cp[i];
            if (v > l5[4]) {
                l5[4] = v;
                #pragma unroll
                for (int j = 4; j > 0; j--)
                    if (l5[j] > l5[j-1]) { float tmp = l5[j-1]; l5[j-1] = l5[j]; l5[j] = tmp; }
            }
        }
        float thr = INFINITY;
        #pragma unroll
        for (int r = 0; r < 5; r++) {
            float lm = -INFINITY;
            #pragma unroll
            for (int i = 0; i < 5; i++) {
                float v = l5[i];
                if (v < thr && v > lm) lm = v;
            }
            #pragma unroll
            for (int o = 16; o > 0; o >>= 1)
                lm = fmaxf(lm, __shfl_xor_sync(0xffffffffu, lm, o));
            thr = lm;
        }
        if (lt == 0) bkth[g] = thr;
    }
    __syncthreads();
    float kth = bkth[g];

    // local diamond gather (41 offsets, direct indexing)
    if (lt < 41) {
        int r = lt, dy = 0;
        for (int d = -4; d <= 4; d++) {
            int sz = 9 - 2*abs(d);
            if (r < sz) { dy = d; break; }
            r -= sz;
        }
        int dx = r - (4 - abs(dy));
        int my = ny + dy, mx = nx + dx;
        if ((unsigned)my < (unsigned)HGd && (unsigned)mx < (unsigned)HGd) {
            int m = my*HGd + mx;
            float a = arow[m];
            float v = a * ((a >= kth) ? 2.f : 1.f);
            if (v != 0.f) {
                int pos = atomicAdd(&nnz[g], 1);
                sidx[g][pos] = m; sval[g][pos] = v;
            }
        }
    }
    // top-k append from register candidates (nonlocal only)
    #pragma unroll
    for (int i = 0; i < 5; i++) {
        float v = t5v[i];
        if (v >= kth && v != 0.f) {
            int m = t5i[i];
            int my = m / HGd, mx = m % HGd;
            if (abs(ny - my) + abs(nx - mx) > 4) {
                int pos = atomicAdd(&nnz[g], 1);
                sidx[g][pos] = m; sval[g][pos] = v;
            }
        }
    }
    __syncthreads();
    int cnt = min(nnz[g], SELCAP);

    // softmax via group's first warp
    if (lt < 32) {
        float mx = -INFINITY;
        for (int e = lt; e < cnt; e += 32) mx = fmaxf(mx, sval[g][e]);
        #pragma unroll
        for (int o = 16; o > 0; o >>= 1)
            mx = fmaxf(mx, __shfl_xor_sync(0xffffffffu, mx, o));
        if (lt == 0) bmax[g] = mx;
    }
    __syncthreads();
    float mxv = bmax[g];
    if (lt < cnt) sval[g][lt] = expf(sval[g][lt] - mxv);
    __syncthreads();
    if (lt < 32) {
        float s = 0.f;
        for (int e = lt; e < cnt; e += 32) s += sval[g][e];
        #pragma unroll
        for (int o = 16; o > 0; o >>= 1)
            s += __shfl_xor_sync(0xffffffffu, s, o);
        if (lt == 0) bsum[g] = s;
    }
    __syncthreads();
    if (lt < cnt) {
        g_selidx[(long)rowid*SELCAP + lt] = sidx[g][lt];
        g_selw  [(long)rowid*SELCAP + lt] = sval[g][lt] / bsum[g];
    }
    if (lt == 0) g_selcnt[rowid] = cnt;
}

// =============================================================================
// sparse_av8: 2x4 query tile, union gather; weights pre-duplicated as u64
// =============================================================================
__global__ void __launch_bounds__(256) sparse_av8(
    const float* __restrict__ v_cached, const float* __restrict__ vout)
{
    int chunk = blockIdx.x;
    int tile  = blockIdx.y;
    int z     = blockIdx.z;
    int b = z / NFtot, f = z % NFtot;
    int qy0 = (tile / 12) * 2, qx0 = (tile % 12) * 4;
    int tid = threadIdx.x;

    __shared__ int   sidx[8][SELCAP];
    __shared__ float sval[8][SELCAP];
    __shared__ int   scnt[8];
    __shared__ unsigned umask[72];
    __shared__ int   ubase[73];
    __shared__ int   uidx[MAXU];
    __shared__ u64   Wt2[8][MAXU];

    if (tid < 72) umask[tid] = 0;
    int rowbase = z * Ntok;
    if (tid < 8) {
        int q = tid;
        int n = (qy0 + (q >> 2)) * HGd + qx0 + (q & 3);
        scnt[q] = g_selcnt[rowbase + n];
    }
    __syncthreads();
    for (int i = tid; i < 8 * SELCAP; i += 256) {
        int q = i >> 6, e = i & (SELCAP-1);
        if (e < scnt[q]) {
            int n = (qy0 + (q >> 2)) * HGd + qx0 + (q & 3);
            long base = (long)(rowbase + n) * SELCAP + e;
            int m = g_selidx[base];
            sidx[q][e] = m;
            sval[q][e] = g_selw[base];
            atomicOr(&umask[m >> 5], 1u << (m & 31));
        }
    }
    __syncthreads();
    if (tid == 0) {
        int s = 0;
        for (int w = 0; w < 72; w++) { ubase[w] = s; s += __popc(umask[w]); }
        ubase[72] = s;
    }
    __syncthreads();
    int U = min(ubase[72], MAXU);

    for (int i = tid; i < 8*MAXU; i += 256) ((u64*)Wt2)[i] = 0ull;
    __syncthreads();
    if (tid < 72) {
        unsigned bits = umask[tid];
        int pos = ubase[tid];
        while (bits) {
            int bit = __ffs(bits) - 1; bits &= bits - 1;
            if (pos < MAXU) uidx[pos] = tid*32 + bit;
            pos++;
        }
    }
    __syncthreads();
    for (int i = tid; i < 8*SELCAP; i += 256) {
        int q = i >> 6, e = i & (SELCAP-1);
        if (e < scnt[q]) {
            int m = sidx[q][e];
            int w32 = m >> 5, bit = m & 31;
            int rank = ubase[w32] + __popc(umask[w32] & ((1u << bit) - 1u));
            if (rank < MAXU) Wt2[q][rank] = dup2(sval[q][e]);
        }
    }
    __syncthreads();

    const float* vbase = (f < 2) ? (v_cached + ((long)(b*2 + f)) * Ntok * VDdim)
                                 : (vout     + ((long)(b*2 + 1)) * Ntok * VDdim);
    int d0 = chunk * 1024 + tid * 4;
    u64 acc[8][2] = {};
    for (int e = 0; e < U; e++) {
        int m = uidx[e];
        ulonglong2 vv = *(const ulonglong2*)(vbase + (long)m * VDdim + d0);
        #pragma unroll
        for (int q = 0; q < 8; q++) {
            u64 wq = Wt2[q][e];
            fma2(acc[q][0], wq, vv.x);
            fma2(acc[q][1], wq, vv.y);
        }
    }
    #pragma unroll
    for (int q = 0; q < 8; q++) {
        int n = (qy0 + (q >> 2)) * HGd + qx0 + (q & 3);
        float2 p0 = unpk(acc[q][0]), p1 = unpk(acc[q][1]);
        float* orow = g_otok + ((long)(rowbase + n)) * VDdim + d0;
        *(float4*)orow = make_float4(p0.x, p0.y, p1.x, p1.y);
    }
}

// ---------------------------------- launch -----------------------------------
extern "C" void kernel_launch(void* const* d_in, const int* in_sizes, int n_in,
                              void* d_out, int out_size)
{
    (void)in_sizes; (void)n_in; (void)out_size;
    const float* x         = (const float*)d_in[0];
    const float* k_cached  = (const float*)d_in[1];
    const float* v_cached  = (const float*)d_in[2];
    const float* temperature = (const float*)d_in[3];
    const float* qk_w  = (const float*)d_in[4],  *qk_b  = (const float*)d_in[5];
    const float* qk_dw_w = (const float*)d_in[6], *qk_dw_b = (const float*)d_in[7];
    const float* v_w   = (const float*)d_in[8],  *v_b   = (const float*)d_in[9];
    const float* v_dw_w = (const float*)d_in[10], *v_dw_b = (const float*)d_in[11];
    const float* k2_w  = (const float*)d_in[12], *k2_b  = (const float*)d_in[13];
    const float* k2_dw_w = (const float*)d_in[14], *k2_dw_b = (const float*)d_in[15];
    const float* q2_w  = (const float*)d_in[16], *q2_b  = (const float*)d_in[17];
    const float* q2_dw_w = (const float*)d_in[18], *q2_dw_b = (const float*)d_in[19];
    const float* proj_w = (const float*)d_in[20], *proj_b = (const float*)d_in[21];

    float* out = (float*)d_out;
    const long OUT_K = (long)BATCH * NFtot * 128 * HW2;
    const long OUT_V = OUT_K + (long)BATCH * 2 * Ntok * D2;
    float* kout = out + OUT_K;
    float* vout = out + OUT_V;

    dim3 blk(256);

    gemm_stageA<<<dim3(288,3,BATCH), blk>>>(x, qk_w, qk_b, v_w, v_b);
    dw3x3v<<<(BATCH*384*HW2/4 + 255)/256, blk>>>(qk_dw_w, qk_dw_b, v_dw_w, v_dw_b);
    gemm_stageC<<<dim3(288,4,BATCH), blk>>>(q2_w, q2_b, k2_w, k2_b);
    dw4x4<<<(BATCH*512*Ntok + 255)/256, blk>>>(q2_dw_w, q2_dw_b, k2_dw_w, k2_dw_b);
    norm_qk<<<dim3(Ntok, BATCH), blk>>>(kout, temperature);
    build_vnew_t<<<dim3(HGd, 16, BATCH), blk>>>(vout);
    for (int b = 0; b < BATCH; b++) {
        cudaMemcpyAsync(kout + (long)(b*2)*Ntok*D2,
                        k_cached + (long)(b*2+1)*Ntok*D2,
                        (size_t)Ntok*D2*sizeof(float), cudaMemcpyDeviceToDevice, 0);
        cudaMemcpyAsync(vout + (long)(b*2)*Ntok*VDdim,
                        v_cached + (long)(b*2+1)*Ntok*VDdim,
                        (size_t)Ntok*VDdim*sizeof(float), cudaMemcpyDeviceToDevice, 0);
    }
    attn_gemm2<<<dim3(18,18,BATCH*NFtot), blk>>>(k_cached, kout);
    sparse_select4<<<dim3(Ntok/4, NFtot, BATCH), blk>>>();
    sparse_av8<<<dim3(2, 288, BATCH*NFtot), blk>>>(v_cached, vout);
    proj_gemm2<<<dim3(288,1,BATCH*NFtot), blk>>>(proj_w, proj_b, out);
}